// round 1
// baseline (speedup 1.0000x reference)
#include <cuda_runtime.h>
#include <math.h>

#define BB   2
#define TT   2048
#define DMODEL 1024
#define NH   16
#define DKH  64
#define MTOK (BB*TT)     // 4096

// Scratch (allocation-free): Q/K/V projections + attention context, fp32.
__device__ float g_Q[MTOK*DMODEL];
__device__ float g_K[MTOK*DMODEL];
__device__ float g_V[MTOK*DMODEL];
__device__ float g_C[MTOK*DMODEL];

// ---------------------------------------------------------------------------
// C[M,N] = A[M,K] @ W[K,N] + bias[N]
// 64x64 tile, BK=16, 256 threads, 4x4 micro-tile per thread.
// ---------------------------------------------------------------------------
__global__ __launch_bounds__(256) void gemm_bias(
    const float* __restrict__ A, const float* __restrict__ W,
    const float* __restrict__ bias, float* __restrict__ C,
    int M, int N, int K)
{
    __shared__ float Ast[16][68];   // A tile transposed [k][row], padded
    __shared__ float Ws [16][68];   // W tile [k][col], padded

    const int tid = threadIdx.x;
    const int tx = tid & 15;        // 0..15 -> col group
    const int ty = tid >> 4;        // 0..15 -> row group
    const int rowBase = blockIdx.y * 64;
    const int colBase = blockIdx.x * 64;

    const int aRow = tid >> 2;            // 0..63
    const int aC   = (tid & 3) << 2;      // 0,4,8,12
    const int wRow = tid >> 4;            // 0..15
    const int wC   = (tid & 15) << 2;     // 0..60

    const float* Aptr = A + (size_t)(rowBase + aRow) * K + aC;
    const float* Wptr = W + (size_t)wRow * N + colBase + wC;

    float acc[4][4] = {};

    for (int k0 = 0; k0 < K; k0 += 16) {
        float4 a4 = *(const float4*)(Aptr + k0);
        Ast[aC+0][aRow] = a4.x;
        Ast[aC+1][aRow] = a4.y;
        Ast[aC+2][aRow] = a4.z;
        Ast[aC+3][aRow] = a4.w;
        *(float4*)&Ws[wRow][wC] = *(const float4*)(Wptr + (size_t)k0 * N);
        __syncthreads();

        #pragma unroll
        for (int kk = 0; kk < 16; ++kk) {
            float4 a = *(float4*)&Ast[kk][ty*4];
            float4 w = *(float4*)&Ws [kk][tx*4];
            acc[0][0] += a.x*w.x; acc[0][1] += a.x*w.y; acc[0][2] += a.x*w.z; acc[0][3] += a.x*w.w;
            acc[1][0] += a.y*w.x; acc[1][1] += a.y*w.y; acc[1][2] += a.y*w.z; acc[1][3] += a.y*w.w;
            acc[2][0] += a.z*w.x; acc[2][1] += a.z*w.y; acc[2][2] += a.z*w.z; acc[2][3] += a.z*w.w;
            acc[3][0] += a.w*w.x; acc[3][1] += a.w*w.y; acc[3][2] += a.w*w.z; acc[3][3] += a.w*w.w;
        }
        __syncthreads();
    }

    const int c0 = colBase + tx*4;
    float4 b4 = *(const float4*)(bias + c0);
    #pragma unroll
    for (int i = 0; i < 4; ++i) {
        int r = rowBase + ty*4 + i;
        float4 v;
        v.x = acc[i][0] + b4.x;
        v.y = acc[i][1] + b4.y;
        v.z = acc[i][2] + b4.z;
        v.w = acc[i][3] + b4.w;
        *(float4*)(C + (size_t)r * N + c0) = v;
    }
}

// ---------------------------------------------------------------------------
// Causal flash attention, fp32. Layout: [B*T, H*DKH] (head-interleaved).
// 1 thread = 1 query row. BQ=128 rows per block, KV tiles of 64.
// ---------------------------------------------------------------------------
#define BQ  128
#define BKV 64
#define SS_STRIDE 65
#define ATTN_SMEM ((2*BKV*DKH + BQ*SS_STRIDE) * (int)sizeof(float))

__global__ __launch_bounds__(BQ) void attn(
    const float* __restrict__ Q, const float* __restrict__ K,
    const float* __restrict__ V, float* __restrict__ O)
{
    extern __shared__ float sm[];
    float* Ks = sm;                    // [BKV][DKH]
    float* Vs = sm + BKV*DKH;          // [BKV][DKH]
    float* Ss = sm + 2*BKV*DKH;        // [BQ][SS_STRIDE]

    const int tid = threadIdx.x;
    const int h   = blockIdx.y;
    const int b   = blockIdx.z;
    const int q0  = blockIdx.x * BQ;
    const int qi  = q0 + tid;
    const float scale = 0.125f;        // 1/sqrt(64)

    const float* qptr = Q + ((size_t)(b*TT + qi))*DMODEL + h*DKH;
    float q[DKH], o[DKH];
    #pragma unroll
    for (int d4 = 0; d4 < DKH/4; ++d4) {
        float4 v = *(const float4*)(qptr + d4*4);
        q[d4*4+0]=v.x; q[d4*4+1]=v.y; q[d4*4+2]=v.z; q[d4*4+3]=v.w;
    }
    #pragma unroll
    for (int d = 0; d < DKH; ++d) o[d] = 0.f;

    float m = -1e30f, l = 0.f;
    const int ntiles = q0/BKV + BQ/BKV;   // keys 0 .. q0+BQ-1
    const float* Kbase = K + ((size_t)(b*TT))*DMODEL + h*DKH;
    const float* Vbase = V + ((size_t)(b*TT))*DMODEL + h*DKH;
    float* srow = Ss + tid*SS_STRIDE;

    for (int t = 0; t < ntiles; ++t) {
        const int k0 = t * BKV;
        // cooperative load of K/V tiles (coalesced float4)
        #pragma unroll
        for (int i = 0; i < (BKV*DKH/4)/BQ; ++i) {     // 8 iters
            int idx = tid + i*BQ;                      // 0..1023 float4s
            int row = idx >> 4;
            int c   = (idx & 15) << 2;
            size_t goff = (size_t)(k0 + row)*DMODEL + c;
            *(float4*)&Ks[row*DKH + c] = *(const float4*)(Kbase + goff);
            *(float4*)&Vs[row*DKH + c] = *(const float4*)(Vbase + goff);
        }
        __syncthreads();

        // pass 1: scores + tile max
        float tmax = -1e30f;
        for (int j = 0; j < BKV; ++j) {
            const float* kj = &Ks[j*DKH];
            float s0=0.f, s1=0.f, s2=0.f, s3=0.f;
            #pragma unroll
            for (int d4 = 0; d4 < DKH/4; ++d4) {
                float4 kv = *(const float4*)(kj + d4*4);
                s0 += q[d4*4+0]*kv.x;
                s1 += q[d4*4+1]*kv.y;
                s2 += q[d4*4+2]*kv.z;
                s3 += q[d4*4+3]*kv.w;
            }
            float s = ((s0+s1)+(s2+s3)) * scale;
            if (k0 + j > qi) s = -1e30f;
            srow[j] = s;
            tmax = fmaxf(tmax, s);
        }

        // online-softmax rescale
        float mnew = fmaxf(m, tmax);
        float corr = __expf(m - mnew);
        l *= corr;
        #pragma unroll
        for (int d = 0; d < DKH; ++d) o[d] *= corr;

        // pass 2: P@V accumulate
        for (int j = 0; j < BKV; ++j) {
            float p = __expf(srow[j] - mnew);
            l += p;
            const float* vj = &Vs[j*DKH];
            #pragma unroll
            for (int d4 = 0; d4 < DKH/4; ++d4) {
                float4 vv = *(const float4*)(vj + d4*4);
                o[d4*4+0] += p*vv.x;
                o[d4*4+1] += p*vv.y;
                o[d4*4+2] += p*vv.z;
                o[d4*4+3] += p*vv.w;
            }
        }
        m = mnew;
        __syncthreads();
    }

    const float inv = 1.f / l;
    float* optr = O + ((size_t)(b*TT + qi))*DMODEL + h*DKH;
    #pragma unroll
    for (int d4 = 0; d4 < DKH/4; ++d4) {
        float4 v;
        v.x = o[d4*4+0]*inv;
        v.y = o[d4*4+1]*inv;
        v.z = o[d4*4+2]*inv;
        v.w = o[d4*4+3]*inv;
        *(float4*)(optr + d4*4) = v;
    }
}

// ---------------------------------------------------------------------------
extern "C" void kernel_launch(void* const* d_in, const int* in_sizes, int n_in,
                              void* d_out, int out_size)
{
    const float* q  = (const float*)d_in[0];
    const float* k  = (const float*)d_in[1];
    const float* v  = (const float*)d_in[2];
    // d_in[3] = mask (causal tril) — encoded structurally in the attn kernel
    const float* wq = (const float*)d_in[4];
    const float* bq = (const float*)d_in[5];
    const float* wk = (const float*)d_in[6];
    const float* bk = (const float*)d_in[7];
    const float* wv = (const float*)d_in[8];
    const float* bv = (const float*)d_in[9];
    const float* wo = (const float*)d_in[10];
    const float* bo = (const float*)d_in[11];
    float* out = (float*)d_out;

    float *gq, *gk, *gv, *gc;
    cudaGetSymbolAddress((void**)&gq, g_Q);
    cudaGetSymbolAddress((void**)&gk, g_K);
    cudaGetSymbolAddress((void**)&gv, g_V);
    cudaGetSymbolAddress((void**)&gc, g_C);

    cudaFuncSetAttribute(attn, cudaFuncAttributeMaxDynamicSharedMemorySize, ATTN_SMEM);

    dim3 ggrid(DMODEL/64, MTOK/64);   // (16, 64)
    gemm_bias<<<ggrid, 256>>>(q, wq, bq, gq, MTOK, DMODEL, DMODEL);
    gemm_bias<<<ggrid, 256>>>(k, wk, bk, gk, MTOK, DMODEL, DMODEL);
    gemm_bias<<<ggrid, 256>>>(v, wv, bv, gv, MTOK, DMODEL, DMODEL);

    dim3 agrid(TT/BQ, NH, BB);        // (16, 16, 2)
    attn<<<agrid, BQ, ATTN_SMEM>>>(gq, gk, gv, gc);

    gemm_bias<<<ggrid, 256>>>(gc, wo, bo, out, MTOK, DMODEL, DMODEL);
}

// round 3
// speedup vs baseline: 1.0370x; 1.0370x over previous
#include <cuda_runtime.h>
#include <cstdint>
#include <math.h>

#define BB   2
#define TT   2048
#define DM   1024
#define NH   16
#define DKH  64
#define MTOK (BB*TT)     // 4096

// Scratch (allocation-free)
__device__ float g_Q[MTOK*DM];
__device__ float g_K[MTOK*DM];
__device__ float g_V[MTOK*DM];
__device__ float g_C[MTOK*DM];

__device__ __forceinline__ uint32_t f2tf32(float f) {
    uint32_t r; asm("cvt.rna.tf32.f32 %0, %1;" : "=r"(r) : "f"(f)); return r;
}

__device__ __forceinline__ void mma_tf32(float* c, const uint32_t* a, const uint32_t* b) {
    asm volatile(
        "mma.sync.aligned.m16n8k8.row.col.f32.tf32.tf32.f32 "
        "{%0,%1,%2,%3}, {%4,%5,%6,%7}, {%8,%9}, {%0,%1,%2,%3};"
        : "+f"(c[0]), "+f"(c[1]), "+f"(c[2]), "+f"(c[3])
        : "r"(a[0]), "r"(a[1]), "r"(a[2]), "r"(a[3]), "r"(b[0]), "r"(b[1]));
}

// ===========================================================================
// tf32 mma.sync GEMM: C[M,1024] = A[M,1024] @ W[1024,1024] + bias
// CTA tile 128x128, K chunks of 32. 8 warps (4M x 2N), warp tile 32x64.
// smem staged in per-lane fragment order:
//   sA[mtile(8)][kstep(4)][lane(32)][4]  (a0,a1,a2,a3)
//   sB[ntile(16)][kstep(4)][lane(32)][2] (b0,b1)
// ===========================================================================
#define NCH 32

__global__ __launch_bounds__(256) void gemm_mma(
    const float* __restrict__ A, const float* __restrict__ W,
    const float* __restrict__ bias, float* __restrict__ C)
{
    __shared__ uint32_t sA[8*4*32*4];    // 4096 words = 16KB
    __shared__ uint32_t sB[16*4*32*2];   // 4096 words = 16KB

    const int tid  = threadIdx.x;
    const int wid  = tid >> 5;
    const int lane = tid & 31;
    const int wm   = wid >> 1;      // 0..3
    const int wn   = wid & 1;       // 0..1
    const int g    = lane >> 2;
    const int t    = lane & 3;
    const int rowBase = blockIdx.y * 128;
    const int colBase = blockIdx.x * 128;

    float acc[2][8][4];
    #pragma unroll
    for (int i = 0; i < 2; ++i)
        #pragma unroll
        for (int j = 0; j < 8; ++j)
            #pragma unroll
            for (int e = 0; e < 4; ++e) acc[i][j][e] = 0.f;

    float4 regA[4], regB[4];

    // global chunk load -> registers (coalesced float4)
    auto ldg = [&](int c) {
        const int k0 = c * 32;
        #pragma unroll
        for (int i = 0; i < 4; ++i) {
            int idx = tid + i*256;          // 0..1023
            int row = idx >> 3;             // 0..127
            int c4  = idx & 7;              // 0..7
            regA[i] = *(const float4*)(A + (size_t)(rowBase+row)*DM + k0 + c4*4);
        }
        #pragma unroll
        for (int i = 0; i < 4; ++i) {
            int idx = tid + i*256;
            int kr  = idx >> 5;             // 0..31
            int n4  = idx & 31;             // 0..31
            regB[i] = *(const float4*)(W + (size_t)(k0+kr)*DM + colBase + n4*4);
        }
    };

    // registers -> fragment-permuted smem (tf32 converted)
    auto sts = [&]() {
        #pragma unroll
        for (int i = 0; i < 4; ++i) {
            int idx = tid + i*256;
            int row = idx >> 3;
            int cb  = (idx & 7) * 4;
            int mtile = row >> 4;
            int rr    = row & 15;
            int gg    = rr & 7;
            int hi    = rr >> 3;
            float v[4] = {regA[i].x, regA[i].y, regA[i].z, regA[i].w};
            #pragma unroll
            for (int e = 0; e < 4; ++e) {
                int c     = cb + e;
                int kstep = c >> 3;
                int cc    = c & 7;
                int tt    = cc & 3;
                int chi   = cc >> 2;
                sA[(((mtile*4 + kstep)*32) + gg*4 + tt)*4 + hi + 2*chi] = f2tf32(v[e]);
            }
        }
        #pragma unroll
        for (int i = 0; i < 4; ++i) {
            int idx = tid + i*256;
            int kr  = idx >> 5;
            int nb  = (idx & 31) * 4;
            int kstep = kr >> 3;
            int cc    = kr & 7;
            int tt    = cc & 3;
            int hi    = cc >> 2;
            float v[4] = {regB[i].x, regB[i].y, regB[i].z, regB[i].w};
            #pragma unroll
            for (int e = 0; e < 4; ++e) {
                int n     = nb + e;
                int ntile = n >> 3;
                int gg    = n & 7;
                sB[(((ntile*4 + kstep)*32) + gg*4 + tt)*2 + hi] = f2tf32(v[e]);
            }
        }
    };

    auto compute = [&]() {
        #pragma unroll
        for (int kstep = 0; kstep < 4; ++kstep) {
            uint32_t a[2][4];
            #pragma unroll
            for (int mt = 0; mt < 2; ++mt) {
                const uint32_t* ap = &sA[((( (2*wm+mt)*4 + kstep)*32) + lane)*4];
                uint4 av = *(const uint4*)ap;
                a[mt][0] = av.x; a[mt][1] = av.y; a[mt][2] = av.z; a[mt][3] = av.w;
            }
            #pragma unroll
            for (int nt = 0; nt < 8; ++nt) {
                const uint32_t* bp = &sB[((( (8*wn+nt)*4 + kstep)*32) + lane)*2];
                uint2 bv = *(const uint2*)bp;
                uint32_t b[2] = {bv.x, bv.y};
                mma_tf32(acc[0][nt], a[0], b);
                mma_tf32(acc[1][nt], a[1], b);
            }
        }
    };

    ldg(0);
    sts();
    __syncthreads();
    for (int c = 0; c < NCH; ++c) {
        if (c + 1 < NCH) ldg(c + 1);
        compute();
        __syncthreads();
        if (c + 1 < NCH) {
            sts();
            __syncthreads();
        }
    }

    // epilogue: each warp owns rows [wm*32, wm*32+32), cols [wn*64, wn*64+64)
    #pragma unroll
    for (int mt = 0; mt < 2; ++mt) {
        int r0 = rowBase + wm*32 + mt*16 + g;
        #pragma unroll
        for (int nt = 0; nt < 8; ++nt) {
            int col = colBase + wn*64 + nt*8 + 2*t;
            float b0 = bias[col], b1 = bias[col+1];
            float2 v0 = make_float2(acc[mt][nt][0] + b0, acc[mt][nt][1] + b1);
            float2 v1 = make_float2(acc[mt][nt][2] + b0, acc[mt][nt][3] + b1);
            *(float2*)(C + (size_t)r0*DM + col)     = v0;
            *(float2*)(C + (size_t)(r0+8)*DM + col) = v1;
        }
    }
}

// ===========================================================================
// Causal flash attention, fp32 (unchanged from R1 passing version)
// ===========================================================================
#define BQ  128
#define BKV 64
#define SS_STRIDE 65
#define ATTN_SMEM ((2*BKV*DKH + BQ*SS_STRIDE) * (int)sizeof(float))

__global__ __launch_bounds__(BQ) void attn(
    const float* __restrict__ Q, const float* __restrict__ K,
    const float* __restrict__ V, float* __restrict__ O)
{
    extern __shared__ float sm[];
    float* Ks = sm;
    float* Vs = sm + BKV*DKH;
    float* Ss = sm + 2*BKV*DKH;

    const int tid = threadIdx.x;
    const int h   = blockIdx.y;
    const int b   = blockIdx.z;
    const int q0  = blockIdx.x * BQ;
    const int qi  = q0 + tid;
    const float scale = 0.125f;

    const float* qptr = Q + ((size_t)(b*TT + qi))*DM + h*DKH;
    float q[DKH], o[DKH];
    #pragma unroll
    for (int d4 = 0; d4 < DKH/4; ++d4) {
        float4 v = *(const float4*)(qptr + d4*4);
        q[d4*4+0]=v.x; q[d4*4+1]=v.y; q[d4*4+2]=v.z; q[d4*4+3]=v.w;
    }
    #pragma unroll
    for (int d = 0; d < DKH; ++d) o[d] = 0.f;

    float m = -1e30f, l = 0.f;
    const int ntiles = q0/BKV + BQ/BKV;
    const float* Kbase = K + ((size_t)(b*TT))*DM + h*DKH;
    const float* Vbase = V + ((size_t)(b*TT))*DM + h*DKH;
    float* srow = Ss + tid*SS_STRIDE;

    for (int ti = 0; ti < ntiles; ++ti) {
        const int k0 = ti * BKV;
        #pragma unroll
        for (int i = 0; i < (BKV*DKH/4)/BQ; ++i) {
            int idx = tid + i*BQ;
            int row = idx >> 4;
            int c   = (idx & 15) << 2;
            size_t goff = (size_t)(k0 + row)*DM + c;
            *(float4*)&Ks[row*DKH + c] = *(const float4*)(Kbase + goff);
            *(float4*)&Vs[row*DKH + c] = *(const float4*)(Vbase + goff);
        }
        __syncthreads();

        float tmax = -1e30f;
        for (int j = 0; j < BKV; ++j) {
            const float* kj = &Ks[j*DKH];
            float s0=0.f, s1=0.f, s2=0.f, s3=0.f;
            #pragma unroll
            for (int d4 = 0; d4 < DKH/4; ++d4) {
                float4 kv = *(const float4*)(kj + d4*4);
                s0 += q[d4*4+0]*kv.x;
                s1 += q[d4*4+1]*kv.y;
                s2 += q[d4*4+2]*kv.z;
                s3 += q[d4*4+3]*kv.w;
            }
            float s = ((s0+s1)+(s2+s3)) * scale;
            if (k0 + j > qi) s = -1e30f;
            srow[j] = s;
            tmax = fmaxf(tmax, s);
        }

        float mnew = fmaxf(m, tmax);
        float corr = __expf(m - mnew);
        l *= corr;
        #pragma unroll
        for (int d = 0; d < DKH; ++d) o[d] *= corr;

        for (int j = 0; j < BKV; ++j) {
            float p = __expf(srow[j] - mnew);
            l += p;
            const float* vj = &Vs[j*DKH];
            #pragma unroll
            for (int d4 = 0; d4 < DKH/4; ++d4) {
                float4 vv = *(const float4*)(vj + d4*4);
                o[d4*4+0] += p*vv.x;
                o[d4*4+1] += p*vv.y;
                o[d4*4+2] += p*vv.z;
                o[d4*4+3] += p*vv.w;
            }
        }
        m = mnew;
        __syncthreads();
    }

    const float inv = 1.f / l;
    float* optr = O + ((size_t)(b*TT + qi))*DM + h*DKH;
    #pragma unroll
    for (int d4 = 0; d4 < DKH/4; ++d4) {
        float4 v;
        v.x = o[d4*4+0]*inv;
        v.y = o[d4*4+1]*inv;
        v.z = o[d4*4+2]*inv;
        v.w = o[d4*4+3]*inv;
        *(float4*)(optr + d4*4) = v;
    }
}

// ===========================================================================
extern "C" void kernel_launch(void* const* d_in, const int* in_sizes, int n_in,
                              void* d_out, int out_size)
{
    const float* q  = (const float*)d_in[0];
    const float* k  = (const float*)d_in[1];
    const float* v  = (const float*)d_in[2];
    const float* wq = (const float*)d_in[4];
    const float* bq = (const float*)d_in[5];
    const float* wk = (const float*)d_in[6];
    const float* bk = (const float*)d_in[7];
    const float* wv = (const float*)d_in[8];
    const float* bv = (const float*)d_in[9];
    const float* wo = (const float*)d_in[10];
    const float* bo = (const float*)d_in[11];
    float* out = (float*)d_out;

    float *gq, *gk, *gv, *gc;
    cudaGetSymbolAddress((void**)&gq, g_Q);
    cudaGetSymbolAddress((void**)&gk, g_K);
    cudaGetSymbolAddress((void**)&gv, g_V);
    cudaGetSymbolAddress((void**)&gc, g_C);

    cudaFuncSetAttribute(attn, cudaFuncAttributeMaxDynamicSharedMemorySize, ATTN_SMEM);

    dim3 ggrid(DM/128, MTOK/128);     // (8, 32) = 256 CTAs
    gemm_mma<<<ggrid, 256>>>(q, wq, bq, gq);
    gemm_mma<<<ggrid, 256>>>(k, wk, bk, gk);
    gemm_mma<<<ggrid, 256>>>(v, wv, bv, gv);

    dim3 agrid(TT/BQ, NH, BB);        // (16, 16, 2)
    attn<<<agrid, BQ, ATTN_SMEM>>>(gq, gk, gv, gc);

    gemm_mma<<<ggrid, 256>>>(gc, wo, bo, out);
}

// round 4
// speedup vs baseline: 1.5415x; 1.4865x over previous
#include <cuda_runtime.h>
#include <cstdint>
#include <math.h>

#define BB   2
#define TT   2048
#define DM   1024
#define NH   16
#define DKH  64
#define MTOK (BB*TT)     // 4096

// Scratch (allocation-free)
__device__ float g_Q[MTOK*DM];
__device__ float g_K[MTOK*DM];
__device__ float g_V[MTOK*DM];
__device__ float g_C[MTOK*DM];

__device__ __forceinline__ uint32_t f2tf32(float f) {
    uint32_t r; asm("cvt.rna.tf32.f32 %0, %1;" : "=r"(r) : "f"(f)); return r;
}

__device__ __forceinline__ void mma_tf32(float* c, const uint32_t* a, const uint32_t* b) {
    asm volatile(
        "mma.sync.aligned.m16n8k8.row.col.f32.tf32.tf32.f32 "
        "{%0,%1,%2,%3}, {%4,%5,%6,%7}, {%8,%9}, {%0,%1,%2,%3};"
        : "+f"(c[0]), "+f"(c[1]), "+f"(c[2]), "+f"(c[3])
        : "r"(a[0]), "r"(a[1]), "r"(a[2]), "r"(a[3]), "r"(b[0]), "r"(b[1]));
}

// ===========================================================================
// tf32 mma.sync GEMM (unchanged from R3 passing version)
// ===========================================================================
#define NCH 32

__global__ __launch_bounds__(256) void gemm_mma(
    const float* __restrict__ A, const float* __restrict__ W,
    const float* __restrict__ bias, float* __restrict__ C)
{
    __shared__ uint32_t sA[8*4*32*4];
    __shared__ uint32_t sB[16*4*32*2];

    const int tid  = threadIdx.x;
    const int wid  = tid >> 5;
    const int lane = tid & 31;
    const int wm   = wid >> 1;
    const int wn   = wid & 1;
    const int g    = lane >> 2;
    const int t    = lane & 3;
    const int rowBase = blockIdx.y * 128;
    const int colBase = blockIdx.x * 128;

    float acc[2][8][4];
    #pragma unroll
    for (int i = 0; i < 2; ++i)
        #pragma unroll
        for (int j = 0; j < 8; ++j)
            #pragma unroll
            for (int e = 0; e < 4; ++e) acc[i][j][e] = 0.f;

    float4 regA[4], regB[4];

    auto ldg = [&](int c) {
        const int k0 = c * 32;
        #pragma unroll
        for (int i = 0; i < 4; ++i) {
            int idx = tid + i*256;
            int row = idx >> 3;
            int c4  = idx & 7;
            regA[i] = *(const float4*)(A + (size_t)(rowBase+row)*DM + k0 + c4*4);
        }
        #pragma unroll
        for (int i = 0; i < 4; ++i) {
            int idx = tid + i*256;
            int kr  = idx >> 5;
            int n4  = idx & 31;
            regB[i] = *(const float4*)(W + (size_t)(k0+kr)*DM + colBase + n4*4);
        }
    };

    auto sts = [&]() {
        #pragma unroll
        for (int i = 0; i < 4; ++i) {
            int idx = tid + i*256;
            int row = idx >> 3;
            int cb  = (idx & 7) * 4;
            int mtile = row >> 4;
            int rr    = row & 15;
            int gg    = rr & 7;
            int hi    = rr >> 3;
            float v[4] = {regA[i].x, regA[i].y, regA[i].z, regA[i].w};
            #pragma unroll
            for (int e = 0; e < 4; ++e) {
                int c     = cb + e;
                int kstep = c >> 3;
                int cc    = c & 7;
                int tt    = cc & 3;
                int chi   = cc >> 2;
                sA[(((mtile*4 + kstep)*32) + gg*4 + tt)*4 + hi + 2*chi] = f2tf32(v[e]);
            }
        }
        #pragma unroll
        for (int i = 0; i < 4; ++i) {
            int idx = tid + i*256;
            int kr  = idx >> 5;
            int nb  = (idx & 31) * 4;
            int kstep = kr >> 3;
            int cc    = kr & 7;
            int tt    = cc & 3;
            int hi    = cc >> 2;
            float v[4] = {regB[i].x, regB[i].y, regB[i].z, regB[i].w};
            #pragma unroll
            for (int e = 0; e < 4; ++e) {
                int n     = nb + e;
                int ntile = n >> 3;
                int gg    = n & 7;
                sB[(((ntile*4 + kstep)*32) + gg*4 + tt)*2 + hi] = f2tf32(v[e]);
            }
        }
    };

    auto compute = [&]() {
        #pragma unroll
        for (int kstep = 0; kstep < 4; ++kstep) {
            uint32_t a[2][4];
            #pragma unroll
            for (int mt = 0; mt < 2; ++mt) {
                const uint32_t* ap = &sA[((( (2*wm+mt)*4 + kstep)*32) + lane)*4];
                uint4 av = *(const uint4*)ap;
                a[mt][0] = av.x; a[mt][1] = av.y; a[mt][2] = av.z; a[mt][3] = av.w;
            }
            #pragma unroll
            for (int nt = 0; nt < 8; ++nt) {
                const uint32_t* bp = &sB[((( (8*wn+nt)*4 + kstep)*32) + lane)*2];
                uint2 bv = *(const uint2*)bp;
                uint32_t b[2] = {bv.x, bv.y};
                mma_tf32(acc[0][nt], a[0], b);
                mma_tf32(acc[1][nt], a[1], b);
            }
        }
    };

    ldg(0);
    sts();
    __syncthreads();
    for (int c = 0; c < NCH; ++c) {
        if (c + 1 < NCH) ldg(c + 1);
        compute();
        __syncthreads();
        if (c + 1 < NCH) {
            sts();
            __syncthreads();
        }
    }

    #pragma unroll
    for (int mt = 0; mt < 2; ++mt) {
        int r0 = rowBase + wm*32 + mt*16 + g;
        #pragma unroll
        for (int nt = 0; nt < 8; ++nt) {
            int col = colBase + wn*64 + nt*8 + 2*t;
            float b0 = bias[col], b1 = bias[col+1];
            float2 v0 = make_float2(acc[mt][nt][0] + b0, acc[mt][nt][1] + b1);
            float2 v1 = make_float2(acc[mt][nt][2] + b0, acc[mt][nt][3] + b1);
            *(float2*)(C + (size_t)r0*DM + col)     = v0;
            *(float2*)(C + (size_t)(r0+8)*DM + col) = v1;
        }
    }
}

// ===========================================================================
// Tensor-core causal flash attention (tf32 mma.sync).
// CTA: 128 q-rows x 1 head. 8 warps x 16 rows. KV tiles of 64 keys.
// smem word layout (uint32, dynamic, 64KB):
//   [0,8192)      sQP: Q A-frags [(wm*8+s)*32+lane]*4+reg ; later reused as
//                      P A-frags: wid*1024 + (s*32+lane)*4+reg
//   [8192,12288)  sK : B-frags for S:  (nt*8+s)*64 + lane*2 + hi
//   [12288,16384) sV : B-frags for PV: (nt*8+s)*64 + lane*2 + hi
// ===========================================================================
#define AQ_ROWS 128
#define AKV     64
#define OFF_K   8192
#define OFF_V   12288
#define ATTN_SMEM_TC (16384 * 4)

__global__ __launch_bounds__(256) void attn_tc(
    const float* __restrict__ Q, const float* __restrict__ K,
    const float* __restrict__ V, float* __restrict__ O)
{
    extern __shared__ uint32_t sw[];

    const int tid  = threadIdx.x;
    const int wid  = tid >> 5;
    const int lane = tid & 31;
    const int g    = lane >> 2;
    const int t4   = lane & 3;
    const int h    = blockIdx.y;
    const int b    = blockIdx.z;
    const int q0   = blockIdx.x * AQ_ROWS;

    const float scale = 0.125f;
    const int qi0 = q0 + wid*16 + g;     // absolute query row (low half)
    const int qi1 = qi0 + 8;

    const float* Qb = Q + ((size_t)(b*TT))*DM + h*DKH;
    const float* Kb = K + ((size_t)(b*TT))*DM + h*DKH;
    const float* Vb = V + ((size_t)(b*TT))*DM + h*DKH;

    // ---- stage Q as A-fragments (tf32), then pull into registers ----
    #pragma unroll
    for (int i = 0; i < 8; ++i) {
        int idx = tid + i*256;           // 0..2047
        int row = idx >> 4;              // 0..127
        int d0  = (idx & 15) * 4;
        float4 v = *(const float4*)(Qb + (size_t)(q0+row)*DM + d0);
        float val[4] = {v.x, v.y, v.z, v.w};
        int wm = row >> 4, rr = row & 15, gg = rr & 7, hr = rr >> 3;
        #pragma unroll
        for (int e = 0; e < 4; ++e) {
            int d = d0 + e;
            int s = d >> 3, tt = d & 3, hc = (d >> 2) & 1;
            sw[((wm*8 + s)*32 + gg*4 + tt)*4 + hr + 2*hc] = f2tf32(val[e]);
        }
    }
    __syncthreads();

    uint32_t qa[8][4];
    #pragma unroll
    for (int s = 0; s < 8; ++s) {
        uint4 v = *(const uint4*)&sw[((wid*8 + s)*32 + lane)*4];
        qa[s][0]=v.x; qa[s][1]=v.y; qa[s][2]=v.z; qa[s][3]=v.w;
    }
    __syncthreads();    // Q region now free for P

    float oacc[8][4];
    #pragma unroll
    for (int nt = 0; nt < 8; ++nt)
        #pragma unroll
        for (int e = 0; e < 4; ++e) oacc[nt][e] = 0.f;
    float m0 = -1e30f, m1 = -1e30f, l0 = 0.f, l1 = 0.f;

    const int ntilesKV = q0/AKV + 2;
    uint32_t* sP = sw + wid*1024;

    for (int tk = 0; tk < ntilesKV; ++tk) {
        const int k0 = tk * AKV;

        // ---- stage K and V tiles in B-fragment order ----
        #pragma unroll
        for (int i = 0; i < 4; ++i) {
            int idx = tid + i*256;       // 0..1023
            int j   = idx >> 4;          // 0..63
            int d0  = (idx & 15) * 4;
            float4 kv = *(const float4*)(Kb + (size_t)(k0+j)*DM + d0);
            float4 vv = *(const float4*)(Vb + (size_t)(k0+j)*DM + d0);
            float kvv[4] = {kv.x, kv.y, kv.z, kv.w};
            float vvv[4] = {vv.x, vv.y, vv.z, vv.w};
            #pragma unroll
            for (int e = 0; e < 4; ++e) {
                int d = d0 + e;
                // K frag: n=j, k=d
                {
                    int nt = j >> 3, s = d >> 3;
                    int gl = (j & 7)*4 + (d & 3), hi = (d >> 2) & 1;
                    sw[OFF_K + (nt*8 + s)*64 + gl*2 + hi] = f2tf32(kvv[e]);
                }
                // V frag: n=d, k=j
                {
                    int nt = d >> 3, s = j >> 3;
                    int gl = (d & 7)*4 + (j & 3), hi = (j >> 2) & 1;
                    sw[OFF_V + (nt*8 + s)*64 + gl*2 + hi] = f2tf32(vvv[e]);
                }
            }
        }
        __syncthreads();

        // ---- S = Q @ K^T ----
        float sf[8][4];
        #pragma unroll
        for (int nt = 0; nt < 8; ++nt)
            #pragma unroll
            for (int e = 0; e < 4; ++e) sf[nt][e] = 0.f;
        #pragma unroll
        for (int s = 0; s < 8; ++s) {
            #pragma unroll
            for (int nt = 0; nt < 8; ++nt) {
                uint2 bv = *(const uint2*)&sw[OFF_K + (nt*8 + s)*64 + lane*2];
                uint32_t bb[2] = {bv.x, bv.y};
                mma_tf32(sf[nt], qa[s], bb);
            }
        }

        // ---- scale + causal mask + row max ----
        float rmax0 = -1e30f, rmax1 = -1e30f;
        #pragma unroll
        for (int nt = 0; nt < 8; ++nt) {
            int jb = k0 + nt*8 + 2*t4;
            #pragma unroll
            for (int e = 0; e < 4; ++e) {
                int j = jb + (e & 1);
                float v = sf[nt][e] * scale;
                int qr = (e < 2) ? qi0 : qi1;
                v = (j > qr) ? -1e30f : v;
                sf[nt][e] = v;
                if (e < 2) rmax0 = fmaxf(rmax0, v);
                else       rmax1 = fmaxf(rmax1, v);
            }
        }
        rmax0 = fmaxf(rmax0, __shfl_xor_sync(0xffffffff, rmax0, 1));
        rmax0 = fmaxf(rmax0, __shfl_xor_sync(0xffffffff, rmax0, 2));
        rmax1 = fmaxf(rmax1, __shfl_xor_sync(0xffffffff, rmax1, 1));
        rmax1 = fmaxf(rmax1, __shfl_xor_sync(0xffffffff, rmax1, 2));

        float mn0 = fmaxf(m0, rmax0);
        float mn1 = fmaxf(m1, rmax1);
        float c0 = __expf(m0 - mn0);
        float c1 = __expf(m1 - mn1);

        // ---- exp, write P in A-fragment order, row sums ----
        float s0 = 0.f, s1 = 0.f;
        #pragma unroll
        for (int nt = 0; nt < 8; ++nt) {
            #pragma unroll
            for (int e = 0; e < 4; ++e) {
                float p = __expf(sf[nt][e] - ((e < 2) ? mn0 : mn1));
                if (e < 2) s0 += p; else s1 += p;
                int jj = 2*t4 + (e & 1);           // 0..7 within kstep nt
                int tt = jj & 3, hc = jj >> 2, hr = (e >> 1);
                sP[(nt*32 + g*4 + tt)*4 + hr + 2*hc] = f2tf32(p);
            }
        }
        s0 += __shfl_xor_sync(0xffffffff, s0, 1);
        s0 += __shfl_xor_sync(0xffffffff, s0, 2);
        s1 += __shfl_xor_sync(0xffffffff, s1, 1);
        s1 += __shfl_xor_sync(0xffffffff, s1, 2);
        l0 = l0*c0 + s0;
        l1 = l1*c1 + s1;
        m0 = mn0; m1 = mn1;

        // rescale O
        #pragma unroll
        for (int nt = 0; nt < 8; ++nt) {
            oacc[nt][0] *= c0; oacc[nt][1] *= c0;
            oacc[nt][2] *= c1; oacc[nt][3] *= c1;
        }
        __syncwarp();

        // ---- O += P @ V ----
        #pragma unroll
        for (int s = 0; s < 8; ++s) {
            uint4 av = *(const uint4*)&sP[(s*32 + lane)*4];
            uint32_t aa[4] = {av.x, av.y, av.z, av.w};
            #pragma unroll
            for (int nt = 0; nt < 8; ++nt) {
                uint2 bv = *(const uint2*)&sw[OFF_V + (nt*8 + s)*64 + lane*2];
                uint32_t bb[2] = {bv.x, bv.y};
                mma_tf32(oacc[nt], aa, bb);
            }
        }
        __syncthreads();
    }

    // ---- epilogue ----
    const float i0 = 1.f / l0;
    const float i1 = 1.f / l1;
    float* Ob = O + ((size_t)(b*TT))*DM + h*DKH;
    #pragma unroll
    for (int nt = 0; nt < 8; ++nt) {
        int d = nt*8 + 2*t4;
        *(float2*)(Ob + (size_t)qi0*DM + d) = make_float2(oacc[nt][0]*i0, oacc[nt][1]*i0);
        *(float2*)(Ob + (size_t)qi1*DM + d) = make_float2(oacc[nt][2]*i1, oacc[nt][3]*i1);
    }
}

// ===========================================================================
extern "C" void kernel_launch(void* const* d_in, const int* in_sizes, int n_in,
                              void* d_out, int out_size)
{
    const float* q  = (const float*)d_in[0];
    const float* k  = (const float*)d_in[1];
    const float* v  = (const float*)d_in[2];
    const float* wq = (const float*)d_in[4];
    const float* bq = (const float*)d_in[5];
    const float* wk = (const float*)d_in[6];
    const float* bk = (const float*)d_in[7];
    const float* wv = (const float*)d_in[8];
    const float* bv = (const float*)d_in[9];
    const float* wo = (const float*)d_in[10];
    const float* bo = (const float*)d_in[11];
    float* out = (float*)d_out;

    float *gq, *gk, *gv, *gc;
    cudaGetSymbolAddress((void**)&gq, g_Q);
    cudaGetSymbolAddress((void**)&gk, g_K);
    cudaGetSymbolAddress((void**)&gv, g_V);
    cudaGetSymbolAddress((void**)&gc, g_C);

    cudaFuncSetAttribute(attn_tc, cudaFuncAttributeMaxDynamicSharedMemorySize, ATTN_SMEM_TC);

    dim3 ggrid(DM/128, MTOK/128);     // (8, 32) = 256 CTAs
    gemm_mma<<<ggrid, 256>>>(q, wq, bq, gq);
    gemm_mma<<<ggrid, 256>>>(k, wk, bk, gk);
    gemm_mma<<<ggrid, 256>>>(v, wv, bv, gv);

    dim3 agrid(TT/AQ_ROWS, NH, BB);   // (16, 16, 2)
    attn_tc<<<agrid, 256, ATTN_SMEM_TC>>>(gq, gk, gv, gc);

    gemm_mma<<<ggrid, 256>>>(gc, wo, bo, out);
}

// round 5
// speedup vs baseline: 1.5417x; 1.0002x over previous
#include <cuda_runtime.h>
#include <cstdint>
#include <math.h>

#define BB   2
#define TT   2048
#define DM   1024
#define NH   16
#define DKH  64
#define MTOK (BB*TT)     // 4096

// Scratch (allocation-free)
__device__ float g_Q[MTOK*DM];
__device__ float g_K[MTOK*DM];
__device__ float g_V[MTOK*DM];
__device__ float g_C[MTOK*DM];

__device__ __forceinline__ uint32_t f2tf32(float f) {
    uint32_t r; asm("cvt.rna.tf32.f32 %0, %1;" : "=r"(r) : "f"(f)); return r;
}

__device__ __forceinline__ void mma_tf32(float* c, const uint32_t* a, const uint32_t* b) {
    asm volatile(
        "mma.sync.aligned.m16n8k8.row.col.f32.tf32.tf32.f32 "
        "{%0,%1,%2,%3}, {%4,%5,%6,%7}, {%8,%9}, {%0,%1,%2,%3};"
        : "+f"(c[0]), "+f"(c[1]), "+f"(c[2]), "+f"(c[3])
        : "r"(a[0]), "r"(a[1]), "r"(a[2]), "r"(a[3]), "r"(b[0]), "r"(b[1]));
}

// ===========================================================================
// tf32 mma.sync GEMM v2: double-buffered smem, 1 sync/chunk.
// C[M,1024] = A[M,1024] @ W[1024,1024] + bias. CTA tile 128x128, K chunk 32.
// 8 warps (4M x 2N), warp tile 32x64. Fragment-permuted smem:
//   sA[mtile(8)][kstep(4)][lane(32)][4], sB[ntile(16)][kstep(4)][lane(32)][2]
// ===========================================================================
#define NCH  32
#define BUFW 8192                     // words per buffer (sA 4096 + sB 4096)
#define GM_SMEM (2*BUFW*4)            // 64 KB

__global__ __launch_bounds__(256, 2) void gemm_mma(
    const float* __restrict__ A, const float* __restrict__ W,
    const float* __restrict__ bias, float* __restrict__ C)
{
    extern __shared__ uint32_t dsm[];

    const int tid  = threadIdx.x;
    const int wid  = tid >> 5;
    const int lane = tid & 31;
    const int wm   = wid >> 1;
    const int wn   = wid & 1;
    const int g    = lane >> 2;
    const int t    = lane & 3;
    const int rowBase = blockIdx.y * 128;
    const int colBase = blockIdx.x * 128;

    float acc[2][8][4];
    #pragma unroll
    for (int i = 0; i < 2; ++i)
        #pragma unroll
        for (int j = 0; j < 8; ++j)
            #pragma unroll
            for (int e = 0; e < 4; ++e) acc[i][j][e] = 0.f;

    float4 regA[4], regB[4];

    auto ldg = [&](int c) {
        const int k0 = c * 32;
        #pragma unroll
        for (int i = 0; i < 4; ++i) {
            int idx = tid + i*256;
            int row = idx >> 3;
            int c4  = idx & 7;
            regA[i] = *(const float4*)(A + (size_t)(rowBase+row)*DM + k0 + c4*4);
        }
        #pragma unroll
        for (int i = 0; i < 4; ++i) {
            int idx = tid + i*256;
            int kr  = idx >> 5;
            int n4  = idx & 31;
            regB[i] = *(const float4*)(W + (size_t)(k0+kr)*DM + colBase + n4*4);
        }
    };

    auto sts = [&](int buf) {
        uint32_t* sA = dsm + buf*BUFW;
        uint32_t* sB = sA + 4096;
        #pragma unroll
        for (int i = 0; i < 4; ++i) {
            int idx = tid + i*256;
            int row = idx >> 3;
            int cb  = (idx & 7) * 4;
            int mtile = row >> 4;
            int rr    = row & 15;
            int gg    = rr & 7;
            int hi    = rr >> 3;
            float v[4] = {regA[i].x, regA[i].y, regA[i].z, regA[i].w};
            #pragma unroll
            for (int e = 0; e < 4; ++e) {
                int c     = cb + e;
                int kstep = c >> 3;
                int cc    = c & 7;
                int tt    = cc & 3;
                int chi   = cc >> 2;
                sA[(((mtile*4 + kstep)*32) + gg*4 + tt)*4 + hi + 2*chi] = f2tf32(v[e]);
            }
        }
        #pragma unroll
        for (int i = 0; i < 4; ++i) {
            int idx = tid + i*256;
            int kr  = idx >> 5;
            int nb  = (idx & 31) * 4;
            int kstep = kr >> 3;
            int cc    = kr & 7;
            int tt    = cc & 3;
            int hi    = cc >> 2;
            float v[4] = {regB[i].x, regB[i].y, regB[i].z, regB[i].w};
            #pragma unroll
            for (int e = 0; e < 4; ++e) {
                int n     = nb + e;
                int ntile = n >> 3;
                int gg    = n & 7;
                sB[(((ntile*4 + kstep)*32) + gg*4 + tt)*2 + hi] = f2tf32(v[e]);
            }
        }
    };

    auto compute = [&](int buf) {
        const uint32_t* sA = dsm + buf*BUFW;
        const uint32_t* sB = sA + 4096;
        #pragma unroll
        for (int kstep = 0; kstep < 4; ++kstep) {
            uint32_t a[2][4];
            #pragma unroll
            for (int mt = 0; mt < 2; ++mt) {
                const uint32_t* ap = &sA[((( (2*wm+mt)*4 + kstep)*32) + lane)*4];
                uint4 av = *(const uint4*)ap;
                a[mt][0] = av.x; a[mt][1] = av.y; a[mt][2] = av.z; a[mt][3] = av.w;
            }
            #pragma unroll
            for (int nt = 0; nt < 8; ++nt) {
                const uint32_t* bp = &sB[((( (8*wn+nt)*4 + kstep)*32) + lane)*2];
                uint2 bv = *(const uint2*)bp;
                uint32_t b[2] = {bv.x, bv.y};
                mma_tf32(acc[0][nt], a[0], b);
                mma_tf32(acc[1][nt], a[1], b);
            }
        }
    };

    // prologue
    ldg(0);
    sts(0);
    __syncthreads();
    ldg(1);

    // steady state: branch-free body -> STS/LDG interleave with MMA
    for (int c = 0; c < NCH - 2; ++c) {
        int buf = c & 1;
        sts(buf ^ 1);       // stage chunk c+1 (regs from ldg(c+1))
        ldg(c + 2);         // prefetch chunk c+2
        compute(buf);       // MMA on chunk c
        __syncthreads();
    }
    // c = NCH-2
    sts((NCH - 2) & 1 ^ 1);
    compute((NCH - 2) & 1);
    __syncthreads();
    // c = NCH-1
    compute((NCH - 1) & 1);

    // epilogue
    #pragma unroll
    for (int mt = 0; mt < 2; ++mt) {
        int r0 = rowBase + wm*32 + mt*16 + g;
        #pragma unroll
        for (int nt = 0; nt < 8; ++nt) {
            int col = colBase + wn*64 + nt*8 + 2*t;
            float b0 = bias[col], b1 = bias[col+1];
            float2 v0 = make_float2(acc[mt][nt][0] + b0, acc[mt][nt][1] + b1);
            float2 v1 = make_float2(acc[mt][nt][2] + b0, acc[mt][nt][3] + b1);
            *(float2*)(C + (size_t)r0*DM + col)     = v0;
            *(float2*)(C + (size_t)(r0+8)*DM + col) = v1;
        }
    }
}

// ===========================================================================
// Tensor-core causal flash attention (unchanged from R4 passing version)
// ===========================================================================
#define AQ_ROWS 128
#define AKV     64
#define OFF_K   8192
#define OFF_V   12288
#define ATTN_SMEM_TC (16384 * 4)

__global__ __launch_bounds__(256) void attn_tc(
    const float* __restrict__ Q, const float* __restrict__ K,
    const float* __restrict__ V, float* __restrict__ O)
{
    extern __shared__ uint32_t sw[];

    const int tid  = threadIdx.x;
    const int wid  = tid >> 5;
    const int lane = tid & 31;
    const int g    = lane >> 2;
    const int t4   = lane & 3;
    const int h    = blockIdx.y;
    const int b    = blockIdx.z;
    const int q0   = blockIdx.x * AQ_ROWS;

    const float scale = 0.125f;
    const int qi0 = q0 + wid*16 + g;
    const int qi1 = qi0 + 8;

    const float* Qb = Q + ((size_t)(b*TT))*DM + h*DKH;
    const float* Kb = K + ((size_t)(b*TT))*DM + h*DKH;
    const float* Vb = V + ((size_t)(b*TT))*DM + h*DKH;

    #pragma unroll
    for (int i = 0; i < 8; ++i) {
        int idx = tid + i*256;
        int row = idx >> 4;
        int d0  = (idx & 15) * 4;
        float4 v = *(const float4*)(Qb + (size_t)(q0+row)*DM + d0);
        float val[4] = {v.x, v.y, v.z, v.w};
        int wm = row >> 4, rr = row & 15, gg = rr & 7, hr = rr >> 3;
        #pragma unroll
        for (int e = 0; e < 4; ++e) {
            int d = d0 + e;
            int s = d >> 3, tt = d & 3, hc = (d >> 2) & 1;
            sw[((wm*8 + s)*32 + gg*4 + tt)*4 + hr + 2*hc] = f2tf32(val[e]);
        }
    }
    __syncthreads();

    uint32_t qa[8][4];
    #pragma unroll
    for (int s = 0; s < 8; ++s) {
        uint4 v = *(const uint4*)&sw[((wid*8 + s)*32 + lane)*4];
        qa[s][0]=v.x; qa[s][1]=v.y; qa[s][2]=v.z; qa[s][3]=v.w;
    }
    __syncthreads();

    float oacc[8][4];
    #pragma unroll
    for (int nt = 0; nt < 8; ++nt)
        #pragma unroll
        for (int e = 0; e < 4; ++e) oacc[nt][e] = 0.f;
    float m0 = -1e30f, m1 = -1e30f, l0 = 0.f, l1 = 0.f;

    const int ntilesKV = q0/AKV + 2;
    uint32_t* sP = sw + wid*1024;

    for (int tk = 0; tk < ntilesKV; ++tk) {
        const int k0 = tk * AKV;

        #pragma unroll
        for (int i = 0; i < 4; ++i) {
            int idx = tid + i*256;
            int j   = idx >> 4;
            int d0  = (idx & 15) * 4;
            float4 kv = *(const float4*)(Kb + (size_t)(k0+j)*DM + d0);
            float4 vv = *(const float4*)(Vb + (size_t)(k0+j)*DM + d0);
            float kvv[4] = {kv.x, kv.y, kv.z, kv.w};
            float vvv[4] = {vv.x, vv.y, vv.z, vv.w};
            #pragma unroll
            for (int e = 0; e < 4; ++e) {
                int d = d0 + e;
                {
                    int nt = j >> 3, s = d >> 3;
                    int gl = (j & 7)*4 + (d & 3), hi = (d >> 2) & 1;
                    sw[OFF_K + (nt*8 + s)*64 + gl*2 + hi] = f2tf32(kvv[e]);
                }
                {
                    int nt = d >> 3, s = j >> 3;
                    int gl = (d & 7)*4 + (j & 3), hi = (j >> 2) & 1;
                    sw[OFF_V + (nt*8 + s)*64 + gl*2 + hi] = f2tf32(vvv[e]);
                }
            }
        }
        __syncthreads();

        float sf[8][4];
        #pragma unroll
        for (int nt = 0; nt < 8; ++nt)
            #pragma unroll
            for (int e = 0; e < 4; ++e) sf[nt][e] = 0.f;
        #pragma unroll
        for (int s = 0; s < 8; ++s) {
            #pragma unroll
            for (int nt = 0; nt < 8; ++nt) {
                uint2 bv = *(const uint2*)&sw[OFF_K + (nt*8 + s)*64 + lane*2];
                uint32_t bb[2] = {bv.x, bv.y};
                mma_tf32(sf[nt], qa[s], bb);
            }
        }

        float rmax0 = -1e30f, rmax1 = -1e30f;
        #pragma unroll
        for (int nt = 0; nt < 8; ++nt) {
            int jb = k0 + nt*8 + 2*t4;
            #pragma unroll
            for (int e = 0; e < 4; ++e) {
                int j = jb + (e & 1);
                float v = sf[nt][e] * scale;
                int qr = (e < 2) ? qi0 : qi1;
                v = (j > qr) ? -1e30f : v;
                sf[nt][e] = v;
                if (e < 2) rmax0 = fmaxf(rmax0, v);
                else       rmax1 = fmaxf(rmax1, v);
            }
        }
        rmax0 = fmaxf(rmax0, __shfl_xor_sync(0xffffffff, rmax0, 1));
        rmax0 = fmaxf(rmax0, __shfl_xor_sync(0xffffffff, rmax0, 2));
        rmax1 = fmaxf(rmax1, __shfl_xor_sync(0xffffffff, rmax1, 1));
        rmax1 = fmaxf(rmax1, __shfl_xor_sync(0xffffffff, rmax1, 2));

        float mn0 = fmaxf(m0, rmax0);
        float mn1 = fmaxf(m1, rmax1);
        float c0 = __expf(m0 - mn0);
        float c1 = __expf(m1 - mn1);

        float s0 = 0.f, s1 = 0.f;
        #pragma unroll
        for (int nt = 0; nt < 8; ++nt) {
            #pragma unroll
            for (int e = 0; e < 4; ++e) {
                float p = __expf(sf[nt][e] - ((e < 2) ? mn0 : mn1));
                if (e < 2) s0 += p; else s1 += p;
                int jj = 2*t4 + (e & 1);
                int tt = jj & 3, hc = jj >> 2, hr = (e >> 1);
                sP[(nt*32 + g*4 + tt)*4 + hr + 2*hc] = f2tf32(p);
            }
        }
        s0 += __shfl_xor_sync(0xffffffff, s0, 1);
        s0 += __shfl_xor_sync(0xffffffff, s0, 2);
        s1 += __shfl_xor_sync(0xffffffff, s1, 1);
        s1 += __shfl_xor_sync(0xffffffff, s1, 2);
        l0 = l0*c0 + s0;
        l1 = l1*c1 + s1;
        m0 = mn0; m1 = mn1;

        #pragma unroll
        for (int nt = 0; nt < 8; ++nt) {
            oacc[nt][0] *= c0; oacc[nt][1] *= c0;
            oacc[nt][2] *= c1; oacc[nt][3] *= c1;
        }
        __syncwarp();

        #pragma unroll
        for (int s = 0; s < 8; ++s) {
            uint4 av = *(const uint4*)&sP[(s*32 + lane)*4];
            uint32_t aa[4] = {av.x, av.y, av.z, av.w};
            #pragma unroll
            for (int nt = 0; nt < 8; ++nt) {
                uint2 bv = *(const uint2*)&sw[OFF_V + (nt*8 + s)*64 + lane*2];
                uint32_t bb[2] = {bv.x, bv.y};
                mma_tf32(oacc[nt], aa, bb);
            }
        }
        __syncthreads();
    }

    const float i0 = 1.f / l0;
    const float i1 = 1.f / l1;
    float* Ob = O + ((size_t)(b*TT))*DM + h*DKH;
    #pragma unroll
    for (int nt = 0; nt < 8; ++nt) {
        int d = nt*8 + 2*t4;
        *(float2*)(Ob + (size_t)qi0*DM + d) = make_float2(oacc[nt][0]*i0, oacc[nt][1]*i0);
        *(float2*)(Ob + (size_t)qi1*DM + d) = make_float2(oacc[nt][2]*i1, oacc[nt][3]*i1);
    }
}

// ===========================================================================
extern "C" void kernel_launch(void* const* d_in, const int* in_sizes, int n_in,
                              void* d_out, int out_size)
{
    const float* q  = (const float*)d_in[0];
    const float* k  = (const float*)d_in[1];
    const float* v  = (const float*)d_in[2];
    const float* wq = (const float*)d_in[4];
    const float* bq = (const float*)d_in[5];
    const float* wk = (const float*)d_in[6];
    const float* bk = (const float*)d_in[7];
    const float* wv = (const float*)d_in[8];
    const float* bv = (const float*)d_in[9];
    const float* wo = (const float*)d_in[10];
    const float* bo = (const float*)d_in[11];
    float* out = (float*)d_out;

    float *gq, *gk, *gv, *gc;
    cudaGetSymbolAddress((void**)&gq, g_Q);
    cudaGetSymbolAddress((void**)&gk, g_K);
    cudaGetSymbolAddress((void**)&gv, g_V);
    cudaGetSymbolAddress((void**)&gc, g_C);

    cudaFuncSetAttribute(attn_tc, cudaFuncAttributeMaxDynamicSharedMemorySize, ATTN_SMEM_TC);
    cudaFuncSetAttribute(gemm_mma, cudaFuncAttributeMaxDynamicSharedMemorySize, GM_SMEM);

    dim3 ggrid(DM/128, MTOK/128);     // (8, 32) = 256 CTAs
    gemm_mma<<<ggrid, 256, GM_SMEM>>>(q, wq, bq, gq);
    gemm_mma<<<ggrid, 256, GM_SMEM>>>(k, wk, bk, gk);
    gemm_mma<<<ggrid, 256, GM_SMEM>>>(v, wv, bv, gv);

    dim3 agrid(TT/AQ_ROWS, NH, BB);   // (16, 16, 2)
    attn_tc<<<agrid, 256, ATTN_SMEM_TC>>>(gq, gk, gv, gc);

    gemm_mma<<<ggrid, 256, GM_SMEM>>>(gc, wo, bo, out);
}

// round 6
// speedup vs baseline: 3.3586x; 2.1785x over previous
#include <cuda_runtime.h>
#include <cstdint>
#include <math.h>

#define BB   2
#define TT   2048
#define DM   1024
#define NH   16
#define DKH  64
#define MTOK (BB*TT)     // 4096

// Scratch (allocation-free)
__device__ float g_Q[MTOK*DM];
__device__ float g_K[MTOK*DM];
__device__ float g_V[MTOK*DM];
__device__ float g_C[MTOK*DM];
__device__ float g_WT[4][DM*DM];   // W transposed to [n][k], tf32-prerounded

__device__ __forceinline__ uint32_t f2tf32(float f) {
    uint32_t r; asm("cvt.rna.tf32.f32 %0, %1;" : "=r"(r) : "f"(f)); return r;
}
__device__ __forceinline__ uint32_t smem_u32(const void* p) {
    uint32_t a;
    asm("{ .reg .u64 t; cvta.to.shared.u64 t, %1; cvt.u32.u64 %0, t; }" : "=r"(a) : "l"(p));
    return a;
}
__device__ __forceinline__ void mma_tf32(float* c, const uint32_t* a, const uint32_t* b) {
    asm volatile(
        "mma.sync.aligned.m16n8k8.row.col.f32.tf32.tf32.f32 "
        "{%0,%1,%2,%3}, {%4,%5,%6,%7}, {%8,%9}, {%0,%1,%2,%3};"
        : "+f"(c[0]), "+f"(c[1]), "+f"(c[2]), "+f"(c[3])
        : "r"(a[0]), "r"(a[1]), "r"(a[2]), "r"(a[3]), "r"(b[0]), "r"(b[1]));
}
#define LDSM_X4(r0,r1,r2,r3,addr) \
    asm volatile("ldmatrix.sync.aligned.m8n8.x4.shared.b16 {%0,%1,%2,%3}, [%4];" \
        : "=r"(r0), "=r"(r1), "=r"(r2), "=r"(r3) : "r"(addr))
#define CP_ASYNC16(dst, src) \
    asm volatile("cp.async.cg.shared.global [%0], [%1], 16;" :: "r"(dst), "l"(src))
#define CP_COMMIT()  asm volatile("cp.async.commit_group;" ::: "memory")
#define CP_WAIT2()   asm volatile("cp.async.wait_group 2;" ::: "memory")

// ===========================================================================
// Transpose + tf32-preround: out[n*K+k] = tf32(in[k*N+n])
// ===========================================================================
__global__ __launch_bounds__(256) void transpose_tf32(
    const float* __restrict__ in, float* __restrict__ out)
{
    __shared__ float t[32][33];
    int tx = threadIdx.x & 31;
    int ty = threadIdx.x >> 5;
    int x  = blockIdx.x*32 + tx;
    int y0 = blockIdx.y*32;
    #pragma unroll
    for (int j = ty; j < 32; j += 8) t[j][tx] = in[(size_t)(y0+j)*DM + x];
    __syncthreads();
    int xo  = y0 + tx;
    int yo0 = blockIdx.x*32;
    #pragma unroll
    for (int j = ty; j < 32; j += 8)
        out[(size_t)(yo0+j)*DM + xo] = __uint_as_float(f2tf32(t[tx][j]));
}

// ===========================================================================
// tf32 GEMM v3: cp.async (3-stage) + swizzled natural layout + ldmatrix.
// C[4096,1024] = A[4096,1024] @ WT^T + bias, WT[n][k] pre-transposed.
// CTA 128x128, K chunk 32 (stage = A 16KB + B 16KB = 32KB). 8 warps 4m x 2n.
// Row = 128B; 16B-granule swizzle: gcol' = gcol ^ (row & 7).
// ===========================================================================
#define NCH      32
#define STAGE_B  32768
#define GM_SMEM  (3*STAGE_B)          // 96 KB

__global__ __launch_bounds__(256, 2) void gemm_mma(
    const float* __restrict__ A, const float* __restrict__ WT,
    const float* __restrict__ bias, float* __restrict__ C)
{
    extern __shared__ char dsm[];
    const uint32_t smb = smem_u32(dsm);

    const int tid  = threadIdx.x;
    const int wid  = tid >> 5;
    const int lane = tid & 31;
    const int wm   = wid >> 1;
    const int wn   = wid & 1;
    const int g    = lane >> 2;
    const int t    = lane & 3;
    const int rowBase = blockIdx.y * 128;
    const int colBase = blockIdx.x * 128;

    // cp.async per-thread mapping (row, 16B granule)
    const int cprow = tid >> 3;          // +64 per iter
    const int cpg   = tid & 7;
    const float* aSrc0 = A  + (size_t)(rowBase + cprow)*DM + cpg*4;
    const float* bSrc0 = WT + (size_t)(colBase + cprow)*DM + cpg*4;

    // ldmatrix lane constants
    const int lr = lane & 7;
    const int lh = (lane >> 3) & 1;
    const int lg = lane >> 4;
    const int rowA0 = wm*32 + lr + 8*lh;      // + mt*16
    const int rowB0 = wn*64 + lr + 8*lh;      // + p*16

    float acc[2][8][4];
    #pragma unroll
    for (int i = 0; i < 2; ++i)
        #pragma unroll
        for (int j = 0; j < 8; ++j)
            #pragma unroll
            for (int e = 0; e < 4; ++e) acc[i][j][e] = 0.f;

    auto copy_chunk = [&](int c, int stage) {
        const int k0 = c * 32;
        const uint32_t sb = smb + stage*STAGE_B;
        #pragma unroll
        for (int i = 0; i < 4; ++i) {
            int row = cprow + i*32;
            uint32_t dst = sb + row*128 + 16*(cpg ^ (row & 7));
            CP_ASYNC16(dst, aSrc0 + (size_t)(i*32)*DM + k0);
        }
        #pragma unroll
        for (int i = 0; i < 4; ++i) {
            int row = cprow + i*32;
            uint32_t dst = sb + 16384 + row*128 + 16*(cpg ^ (row & 7));
            CP_ASYNC16(dst, bSrc0 + (size_t)(i*32)*DM + k0);
        }
    };

    auto compute = [&](int stage) {
        const uint32_t sa = smb + stage*STAGE_B;
        const uint32_t sbB = sa + 16384;
        #pragma unroll
        for (int ks = 0; ks < 4; ++ks) {
            const uint32_t swg = 16u * ((2*ks + lg) ^ lr);
            uint32_t a0[4], a1[4];
            LDSM_X4(a0[0],a0[1],a0[2],a0[3], sa + (rowA0      )*128 + swg);
            LDSM_X4(a1[0],a1[1],a1[2],a1[3], sa + (rowA0 + 16 )*128 + swg);
            #pragma unroll
            for (int r = 0; r < 4; ++r) {
                a0[r] = f2tf32(__uint_as_float(a0[r]));
                a1[r] = f2tf32(__uint_as_float(a1[r]));
            }
            #pragma unroll
            for (int p = 0; p < 4; ++p) {
                uint32_t bq[4];
                LDSM_X4(bq[0],bq[1],bq[2],bq[3], sbB + (rowB0 + p*16)*128 + swg);
                uint32_t be[2] = {bq[0], bq[2]};   // nt = 2p
                uint32_t bo[2] = {bq[1], bq[3]};   // nt = 2p+1
                mma_tf32(acc[0][2*p],   a0, be);
                mma_tf32(acc[1][2*p],   a1, be);
                mma_tf32(acc[0][2*p+1], a0, bo);
                mma_tf32(acc[1][2*p+1], a1, bo);
            }
        }
    };

    // 3-stage pipeline
    copy_chunk(0, 0); CP_COMMIT();
    copy_chunk(1, 1); CP_COMMIT();
    copy_chunk(2, 2); CP_COMMIT();

    for (int c = 0; c < NCH; ++c) {
        CP_WAIT2();
        __syncthreads();
        compute(c % 3);
        __syncthreads();
        if (c + 3 < NCH) copy_chunk(c + 3, c % 3);
        CP_COMMIT();               // empty group when no copies -> wait math stays valid
    }

    // epilogue
    #pragma unroll
    for (int mt = 0; mt < 2; ++mt) {
        int r0 = rowBase + wm*32 + mt*16 + g;
        #pragma unroll
        for (int nt = 0; nt < 8; ++nt) {
            int col = colBase + wn*64 + nt*8 + 2*t;
            float b0 = bias[col], b1 = bias[col+1];
            float2 v0 = make_float2(acc[mt][nt][0] + b0, acc[mt][nt][1] + b1);
            float2 v1 = make_float2(acc[mt][nt][2] + b0, acc[mt][nt][3] + b1);
            *(float2*)(C + (size_t)r0*DM + col)     = v0;
            *(float2*)(C + (size_t)(r0+8)*DM + col) = v1;
        }
    }
}

// ===========================================================================
// Tensor-core causal flash attention (unchanged from R4/R5 passing version)
// ===========================================================================
#define AQ_ROWS 128
#define AKV     64
#define OFF_K   8192
#define OFF_V   12288
#define ATTN_SMEM_TC (16384 * 4)

__global__ __launch_bounds__(256) void attn_tc(
    const float* __restrict__ Q, const float* __restrict__ K,
    const float* __restrict__ V, float* __restrict__ O)
{
    extern __shared__ uint32_t sw[];

    const int tid  = threadIdx.x;
    const int wid  = tid >> 5;
    const int lane = tid & 31;
    const int g    = lane >> 2;
    const int t4   = lane & 3;
    const int h    = blockIdx.y;
    const int b    = blockIdx.z;
    const int q0   = blockIdx.x * AQ_ROWS;

    const float scale = 0.125f;
    const int qi0 = q0 + wid*16 + g;
    const int qi1 = qi0 + 8;

    const float* Qb = Q + ((size_t)(b*TT))*DM + h*DKH;
    const float* Kb = K + ((size_t)(b*TT))*DM + h*DKH;
    const float* Vb = V + ((size_t)(b*TT))*DM + h*DKH;

    #pragma unroll
    for (int i = 0; i < 8; ++i) {
        int idx = tid + i*256;
        int row = idx >> 4;
        int d0  = (idx & 15) * 4;
        float4 v = *(const float4*)(Qb + (size_t)(q0+row)*DM + d0);
        float val[4] = {v.x, v.y, v.z, v.w};
        int wm = row >> 4, rr = row & 15, gg = rr & 7, hr = rr >> 3;
        #pragma unroll
        for (int e = 0; e < 4; ++e) {
            int d = d0 + e;
            int s = d >> 3, tt = d & 3, hc = (d >> 2) & 1;
            sw[((wm*8 + s)*32 + gg*4 + tt)*4 + hr + 2*hc] = f2tf32(val[e]);
        }
    }
    __syncthreads();

    uint32_t qa[8][4];
    #pragma unroll
    for (int s = 0; s < 8; ++s) {
        uint4 v = *(const uint4*)&sw[((wid*8 + s)*32 + lane)*4];
        qa[s][0]=v.x; qa[s][1]=v.y; qa[s][2]=v.z; qa[s][3]=v.w;
    }
    __syncthreads();

    float oacc[8][4];
    #pragma unroll
    for (int nt = 0; nt < 8; ++nt)
        #pragma unroll
        for (int e = 0; e < 4; ++e) oacc[nt][e] = 0.f;
    float m0 = -1e30f, m1 = -1e30f, l0 = 0.f, l1 = 0.f;

    const int ntilesKV = q0/AKV + 2;
    uint32_t* sP = sw + wid*1024;

    for (int tk = 0; tk < ntilesKV; ++tk) {
        const int k0 = tk * AKV;

        #pragma unroll
        for (int i = 0; i < 4; ++i) {
            int idx = tid + i*256;
            int j   = idx >> 4;
            int d0  = (idx & 15) * 4;
            float4 kv = *(const float4*)(Kb + (size_t)(k0+j)*DM + d0);
            float4 vv = *(const float4*)(Vb + (size_t)(k0+j)*DM + d0);
            float kvv[4] = {kv.x, kv.y, kv.z, kv.w};
            float vvv[4] = {vv.x, vv.y, vv.z, vv.w};
            #pragma unroll
            for (int e = 0; e < 4; ++e) {
                int d = d0 + e;
                {
                    int nt = j >> 3, s = d >> 3;
                    int gl = (j & 7)*4 + (d & 3), hi = (d >> 2) & 1;
                    sw[OFF_K + (nt*8 + s)*64 + gl*2 + hi] = f2tf32(kvv[e]);
                }
                {
                    int nt = d >> 3, s = j >> 3;
                    int gl = (d & 7)*4 + (j & 3), hi = (j >> 2) & 1;
                    sw[OFF_V + (nt*8 + s)*64 + gl*2 + hi] = f2tf32(vvv[e]);
                }
            }
        }
        __syncthreads();

        float sf[8][4];
        #pragma unroll
        for (int nt = 0; nt < 8; ++nt)
            #pragma unroll
            for (int e = 0; e < 4; ++e) sf[nt][e] = 0.f;
        #pragma unroll
        for (int s = 0; s < 8; ++s) {
            #pragma unroll
            for (int nt = 0; nt < 8; ++nt) {
                uint2 bv = *(const uint2*)&sw[OFF_K + (nt*8 + s)*64 + lane*2];
                uint32_t bb[2] = {bv.x, bv.y};
                mma_tf32(sf[nt], qa[s], bb);
            }
        }

        float rmax0 = -1e30f, rmax1 = -1e30f;
        #pragma unroll
        for (int nt = 0; nt < 8; ++nt) {
            int jb = k0 + nt*8 + 2*t4;
            #pragma unroll
            for (int e = 0; e < 4; ++e) {
                int j = jb + (e & 1);
                float v = sf[nt][e] * scale;
                int qr = (e < 2) ? qi0 : qi1;
                v = (j > qr) ? -1e30f : v;
                sf[nt][e] = v;
                if (e < 2) rmax0 = fmaxf(rmax0, v);
                else       rmax1 = fmaxf(rmax1, v);
            }
        }
        rmax0 = fmaxf(rmax0, __shfl_xor_sync(0xffffffff, rmax0, 1));
        rmax0 = fmaxf(rmax0, __shfl_xor_sync(0xffffffff, rmax0, 2));
        rmax1 = fmaxf(rmax1, __shfl_xor_sync(0xffffffff, rmax1, 1));
        rmax1 = fmaxf(rmax1, __shfl_xor_sync(0xffffffff, rmax1, 2));

        float mn0 = fmaxf(m0, rmax0);
        float mn1 = fmaxf(m1, rmax1);
        float c0 = __expf(m0 - mn0);
        float c1 = __expf(m1 - mn1);

        float s0 = 0.f, s1 = 0.f;
        #pragma unroll
        for (int nt = 0; nt < 8; ++nt) {
            #pragma unroll
            for (int e = 0; e < 4; ++e) {
                float p = __expf(sf[nt][e] - ((e < 2) ? mn0 : mn1));
                if (e < 2) s0 += p; else s1 += p;
                int jj = 2*t4 + (e & 1);
                int tt = jj & 3, hc = jj >> 2, hr = (e >> 1);
                sP[(nt*32 + g*4 + tt)*4 + hr + 2*hc] = f2tf32(p);
            }
        }
        s0 += __shfl_xor_sync(0xffffffff, s0, 1);
        s0 += __shfl_xor_sync(0xffffffff, s0, 2);
        s1 += __shfl_xor_sync(0xffffffff, s1, 1);
        s1 += __shfl_xor_sync(0xffffffff, s1, 2);
        l0 = l0*c0 + s0;
        l1 = l1*c1 + s1;
        m0 = mn0; m1 = mn1;

        #pragma unroll
        for (int nt = 0; nt < 8; ++nt) {
            oacc[nt][0] *= c0; oacc[nt][1] *= c0;
            oacc[nt][2] *= c1; oacc[nt][3] *= c1;
        }
        __syncwarp();

        #pragma unroll
        for (int s = 0; s < 8; ++s) {
            uint4 av = *(const uint4*)&sP[(s*32 + lane)*4];
            uint32_t aa[4] = {av.x, av.y, av.z, av.w};
            #pragma unroll
            for (int nt = 0; nt < 8; ++nt) {
                uint2 bv = *(const uint2*)&sw[OFF_V + (nt*8 + s)*64 + lane*2];
                uint32_t bb[2] = {bv.x, bv.y};
                mma_tf32(oacc[nt], aa, bb);
            }
        }
        __syncthreads();
    }

    const float i0 = 1.f / l0;
    const float i1 = 1.f / l1;
    float* Ob = O + ((size_t)(b*TT))*DM + h*DKH;
    #pragma unroll
    for (int nt = 0; nt < 8; ++nt) {
        int d = nt*8 + 2*t4;
        *(float2*)(Ob + (size_t)qi0*DM + d) = make_float2(oacc[nt][0]*i0, oacc[nt][1]*i0);
        *(float2*)(Ob + (size_t)qi1*DM + d) = make_float2(oacc[nt][2]*i1, oacc[nt][3]*i1);
    }
}

// ===========================================================================
extern "C" void kernel_launch(void* const* d_in, const int* in_sizes, int n_in,
                              void* d_out, int out_size)
{
    const float* q  = (const float*)d_in[0];
    const float* k  = (const float*)d_in[1];
    const float* v  = (const float*)d_in[2];
    const float* wq = (const float*)d_in[4];
    const float* bq = (const float*)d_in[5];
    const float* wk = (const float*)d_in[6];
    const float* bk = (const float*)d_in[7];
    const float* wv = (const float*)d_in[8];
    const float* bv = (const float*)d_in[9];
    const float* wo = (const float*)d_in[10];
    const float* bo = (const float*)d_in[11];
    float* out = (float*)d_out;

    float *gq, *gk, *gv, *gc, *gwt;
    cudaGetSymbolAddress((void**)&gq, g_Q);
    cudaGetSymbolAddress((void**)&gk, g_K);
    cudaGetSymbolAddress((void**)&gv, g_V);
    cudaGetSymbolAddress((void**)&gc, g_C);
    cudaGetSymbolAddress((void**)&gwt, g_WT);
    float* wtq = gwt;
    float* wtk = gwt + (size_t)DM*DM;
    float* wtv = gwt + (size_t)2*DM*DM;
    float* wto = gwt + (size_t)3*DM*DM;

    cudaFuncSetAttribute(attn_tc, cudaFuncAttributeMaxDynamicSharedMemorySize, ATTN_SMEM_TC);
    cudaFuncSetAttribute(gemm_mma, cudaFuncAttributeMaxDynamicSharedMemorySize, GM_SMEM);

    dim3 tgrid(DM/32, DM/32);
    transpose_tf32<<<tgrid, 256>>>(wq, wtq);
    transpose_tf32<<<tgrid, 256>>>(wk, wtk);
    transpose_tf32<<<tgrid, 256>>>(wv, wtv);
    transpose_tf32<<<tgrid, 256>>>(wo, wto);

    dim3 ggrid(DM/128, MTOK/128);     // (8, 32) = 256 CTAs
    gemm_mma<<<ggrid, 256, GM_SMEM>>>(q, wtq, bq, gq);
    gemm_mma<<<ggrid, 256, GM_SMEM>>>(k, wtk, bk, gk);
    gemm_mma<<<ggrid, 256, GM_SMEM>>>(v, wtv, bv, gv);

    dim3 agrid(TT/AQ_ROWS, NH, BB);   // (16, 16, 2)
    attn_tc<<<agrid, 256, ATTN_SMEM_TC>>>(gq, gk, gv, gc);

    gemm_mma<<<ggrid, 256, GM_SMEM>>>(gc, wto, bo, out);
}

// round 7
// speedup vs baseline: 4.3254x; 1.2878x over previous
#include <cuda_runtime.h>
#include <cstdint>
#include <math.h>

#define BB   2
#define TT   2048
#define DM   1024
#define NH   16
#define DKH  64
#define MTOK (BB*TT)     // 4096

// Scratch (allocation-free)
__device__ float g_Q[MTOK*DM];      // tf32-prerounded, prescaled by 0.125
__device__ float g_K[MTOK*DM];      // tf32-prerounded
__device__ float g_VT[DM*MTOK];     // V transposed [channel][token], tf32
__device__ float g_C[MTOK*DM];
__device__ float g_WT[4][DM*DM];    // W transposed [n][k], tf32-prerounded

__device__ __forceinline__ uint32_t f2tf32(float f) {
    uint32_t r; asm("cvt.rna.tf32.f32 %0, %1;" : "=r"(r) : "f"(f)); return r;
}
__device__ __forceinline__ uint32_t smem_u32(const void* p) {
    uint32_t a;
    asm("{ .reg .u64 t; cvta.to.shared.u64 t, %1; cvt.u32.u64 %0, t; }" : "=r"(a) : "l"(p));
    return a;
}
__device__ __forceinline__ void mma_tf32(float* c, const uint32_t* a, const uint32_t* b) {
    asm volatile(
        "mma.sync.aligned.m16n8k8.row.col.f32.tf32.tf32.f32 "
        "{%0,%1,%2,%3}, {%4,%5,%6,%7}, {%8,%9}, {%0,%1,%2,%3};"
        : "+f"(c[0]), "+f"(c[1]), "+f"(c[2]), "+f"(c[3])
        : "r"(a[0]), "r"(a[1]), "r"(a[2]), "r"(a[3]), "r"(b[0]), "r"(b[1]));
}
#define LDSM_X4(r0,r1,r2,r3,addr) \
    asm volatile("ldmatrix.sync.aligned.m8n8.x4.shared.b16 {%0,%1,%2,%3}, [%4];" \
        : "=r"(r0), "=r"(r1), "=r"(r2), "=r"(r3) : "r"(addr))
#define CP_ASYNC16(dst, src) \
    asm volatile("cp.async.cg.shared.global [%0], [%1], 16;" :: "r"(dst), "l"(src))
#define CP_COMMIT()  asm volatile("cp.async.commit_group;" ::: "memory")
#define CP_WAIT2()   asm volatile("cp.async.wait_group 2;" ::: "memory")

// ===========================================================================
// Transpose + tf32-preround: out[n*K+k] = tf32(in[k*N+n])
// ===========================================================================
__global__ __launch_bounds__(256) void transpose_tf32(
    const float* __restrict__ in, float* __restrict__ out)
{
    __shared__ float t[32][33];
    int tx = threadIdx.x & 31;
    int ty = threadIdx.x >> 5;
    int x  = blockIdx.x*32 + tx;
    int y0 = blockIdx.y*32;
    #pragma unroll
    for (int j = ty; j < 32; j += 8) t[j][tx] = in[(size_t)(y0+j)*DM + x];
    __syncthreads();
    int xo  = y0 + tx;
    int yo0 = blockIdx.x*32;
    #pragma unroll
    for (int j = ty; j < 32; j += 8)
        out[(size_t)(yo0+j)*DM + xo] = __uint_as_float(f2tf32(t[tx][j]));
}

// ===========================================================================
// tf32 GEMM: cp.async (3-stage) + swizzled layout + ldmatrix.
// MODE 0: C = A@WT^T + bias              (plain fp32 out)
// MODE 1: C = tf32((A@WT^T + bias)*scl)  (pre-rounded for attention)
// MODE 2: C^T stored: C[col][row], tf32  (V transposed for attention)
// ===========================================================================
#define NCH      32
#define STAGE_B  32768
#define GM_SMEM  (3*STAGE_B)          // 96 KB

template<int MODE>
__global__ __launch_bounds__(256, 2) void gemm_mma(
    const float* __restrict__ A, const float* __restrict__ WT,
    const float* __restrict__ bias, float* __restrict__ C, float scl)
{
    extern __shared__ char dsm[];
    const uint32_t smb = smem_u32(dsm);

    const int tid  = threadIdx.x;
    const int wid  = tid >> 5;
    const int lane = tid & 31;
    const int wm   = wid >> 1;
    const int wn   = wid & 1;
    const int g    = lane >> 2;
    const int t    = lane & 3;
    const int rowBase = blockIdx.y * 128;
    const int colBase = blockIdx.x * 128;

    const int cprow = tid >> 3;
    const int cpg   = tid & 7;
    const float* aSrc0 = A  + (size_t)(rowBase + cprow)*DM + cpg*4;
    const float* bSrc0 = WT + (size_t)(colBase + cprow)*DM + cpg*4;

    const int lr = lane & 7;
    const int lh = (lane >> 3) & 1;
    const int lg = lane >> 4;
    const int rowA0 = wm*32 + lr + 8*lh;
    const int rowB0 = wn*64 + lr + 8*lh;

    float acc[2][8][4];
    #pragma unroll
    for (int i = 0; i < 2; ++i)
        #pragma unroll
        for (int j = 0; j < 8; ++j)
            #pragma unroll
            for (int e = 0; e < 4; ++e) acc[i][j][e] = 0.f;

    auto copy_chunk = [&](int c, int stage) {
        const int k0 = c * 32;
        const uint32_t sb = smb + stage*STAGE_B;
        #pragma unroll
        for (int i = 0; i < 4; ++i) {
            int row = cprow + i*32;
            uint32_t dst = sb + row*128 + 16*(cpg ^ (row & 7));
            CP_ASYNC16(dst, aSrc0 + (size_t)(i*32)*DM + k0);
        }
        #pragma unroll
        for (int i = 0; i < 4; ++i) {
            int row = cprow + i*32;
            uint32_t dst = sb + 16384 + row*128 + 16*(cpg ^ (row & 7));
            CP_ASYNC16(dst, bSrc0 + (size_t)(i*32)*DM + k0);
        }
    };

    auto compute = [&](int stage) {
        const uint32_t sa = smb + stage*STAGE_B;
        const uint32_t sbB = sa + 16384;
        #pragma unroll
        for (int ks = 0; ks < 4; ++ks) {
            const uint32_t swg = 16u * ((2*ks + lg) ^ lr);
            uint32_t a0[4], a1[4];
            LDSM_X4(a0[0],a0[1],a0[2],a0[3], sa + (rowA0      )*128 + swg);
            LDSM_X4(a1[0],a1[1],a1[2],a1[3], sa + (rowA0 + 16 )*128 + swg);
            #pragma unroll
            for (int r = 0; r < 4; ++r) {
                a0[r] = f2tf32(__uint_as_float(a0[r]));
                a1[r] = f2tf32(__uint_as_float(a1[r]));
            }
            #pragma unroll
            for (int p = 0; p < 4; ++p) {
                uint32_t bq[4];
                LDSM_X4(bq[0],bq[1],bq[2],bq[3], sbB + (rowB0 + p*16)*128 + swg);
                uint32_t be[2] = {bq[0], bq[2]};
                uint32_t bo[2] = {bq[1], bq[3]};
                mma_tf32(acc[0][2*p],   a0, be);
                mma_tf32(acc[1][2*p],   a1, be);
                mma_tf32(acc[0][2*p+1], a0, bo);
                mma_tf32(acc[1][2*p+1], a1, bo);
            }
        }
    };

    copy_chunk(0, 0); CP_COMMIT();
    copy_chunk(1, 1); CP_COMMIT();
    copy_chunk(2, 2); CP_COMMIT();

    for (int c = 0; c < NCH; ++c) {
        CP_WAIT2();
        __syncthreads();
        compute(c % 3);
        __syncthreads();
        if (c + 3 < NCH) copy_chunk(c + 3, c % 3);
        CP_COMMIT();
    }

    #pragma unroll
    for (int mt = 0; mt < 2; ++mt) {
        int r0 = rowBase + wm*32 + mt*16 + g;
        #pragma unroll
        for (int nt = 0; nt < 8; ++nt) {
            int col = colBase + wn*64 + nt*8 + 2*t;
            float b0 = bias[col], b1 = bias[col+1];
            float v00 = acc[mt][nt][0] + b0, v01 = acc[mt][nt][1] + b1;
            float v10 = acc[mt][nt][2] + b0, v11 = acc[mt][nt][3] + b1;
            if (MODE == 0) {
                *(float2*)(C + (size_t)r0*DM + col)     = make_float2(v00, v01);
                *(float2*)(C + (size_t)(r0+8)*DM + col) = make_float2(v10, v11);
            } else if (MODE == 1) {
                float2 w0 = make_float2(__uint_as_float(f2tf32(v00*scl)),
                                        __uint_as_float(f2tf32(v01*scl)));
                float2 w1 = make_float2(__uint_as_float(f2tf32(v10*scl)),
                                        __uint_as_float(f2tf32(v11*scl)));
                *(float2*)(C + (size_t)r0*DM + col)     = w0;
                *(float2*)(C + (size_t)(r0+8)*DM + col) = w1;
            } else {
                C[(size_t)col*MTOK + r0]         = __uint_as_float(f2tf32(v00));
                C[(size_t)(col+1)*MTOK + r0]     = __uint_as_float(f2tf32(v01));
                C[(size_t)col*MTOK + r0 + 8]     = __uint_as_float(f2tf32(v10));
                C[(size_t)(col+1)*MTOK + r0 + 8] = __uint_as_float(f2tf32(v11));
            }
        }
    }
}

// ===========================================================================
// Tensor-core causal flash attention v2: cp.async 3-stage KV pipeline,
// ldmatrix fragment loads, pre-rounded/pre-scaled inputs, VT K-major.
// CTA: 128 q-rows x 1 head, 8 warps x 16 rows. KV tile = 64 keys.
// smem: [0,32KB) Q staging (rows 256B, swizzled) -> reused as per-warp P
//       [32KB + st*32KB): K (16KB) + VT (16KB) per stage, st = 0..2
// ===========================================================================
#define AQ_ROWS 128
#define AKV     64
#define ATTN_SMEM_TC (32768 + 3*32768)   // 128 KB

__global__ __launch_bounds__(256) void attn_tc(
    const float* __restrict__ Q, const float* __restrict__ K,
    const float* __restrict__ VT, float* __restrict__ O)
{
    extern __shared__ char smraw[];
    const uint32_t smb = smem_u32(smraw);
    uint32_t* sw = (uint32_t*)smraw;

    const int tid  = threadIdx.x;
    const int wid  = tid >> 5;
    const int lane = tid & 31;
    const int g    = lane >> 2;
    const int t4   = lane & 3;
    const int lr   = lane & 7;
    const int lh   = (lane >> 3) & 1;
    const int lg   = lane >> 4;
    const int h    = blockIdx.y;
    const int b    = blockIdx.z;
    const int q0   = (gridDim.x - 1 - blockIdx.x) * AQ_ROWS;  // longest first

    const int qi0 = q0 + wid*16 + g;
    const int qi1 = qi0 + 8;

    const float* Qb  = Q + ((size_t)(b*TT))*DM + h*DKH;
    const float* Kb  = K + ((size_t)(b*TT))*DM + h*DKH;
    const float* VTb = VT + (size_t)(h*DKH)*MTOK + b*TT;

    const int ntiles = q0/AKV + 2;

    // KV tile copy: rows 256B (16 granules), 16B-granule XOR swizzle
    auto copy_kv = [&](int tile, int st) {
        const int k0 = tile * AKV;
        const uint32_t base = smb + 32768 + st*32768;
        #pragma unroll
        for (int i = 0; i < 4; ++i) {
            int idx = tid + i*256;
            int row = idx >> 4;              // 0..63
            int gg  = idx & 15;
            uint32_t dst = base + row*256 + 16*(gg ^ (row & 7));
            CP_ASYNC16(dst, Kb + (size_t)(k0+row)*DM + gg*4);
        }
        #pragma unroll
        for (int i = 0; i < 4; ++i) {
            int idx = tid + i*256;
            int row = idx >> 4;              // d = 0..63
            int gg  = idx & 15;
            uint32_t dst = base + 16384 + row*256 + 16*(gg ^ (row & 7));
            CP_ASYNC16(dst, VTb + (size_t)row*MTOK + k0 + gg*4);
        }
    };

    // ---- prologue: Q staging + first 3 KV tiles ----
    #pragma unroll
    for (int i = 0; i < 8; ++i) {
        int idx = tid + i*256;
        int row = idx >> 4;                  // 0..127
        int gg  = idx & 15;
        uint32_t dst = smb + row*256 + 16*(gg ^ (row & 7));
        CP_ASYNC16(dst, Qb + (size_t)(q0+row)*DM + gg*4);
    }
    copy_kv(0, 0); CP_COMMIT();
    if (1 < ntiles) copy_kv(1, 1); CP_COMMIT();
    if (2 < ntiles) copy_kv(2, 2); CP_COMMIT();

    CP_WAIT2();
    __syncthreads();

    // Q fragments (pre-rounded, pre-scaled)
    uint32_t qa[8][4];
    const int qrow = wid*16 + lr + 8*lh;
    #pragma unroll
    for (int ks = 0; ks < 8; ++ks)
        LDSM_X4(qa[ks][0], qa[ks][1], qa[ks][2], qa[ks][3],
                smb + qrow*256 + 16u*((2*ks + lg) ^ lr));

    float oacc[8][4];
    #pragma unroll
    for (int nt = 0; nt < 8; ++nt)
        #pragma unroll
        for (int e = 0; e < 4; ++e) oacc[nt][e] = 0.f;
    float m0 = -1e30f, m1 = -1e30f, l0 = 0.f, l1 = 0.f;

    uint32_t* sP = sw + wid*1024;
    const int frow = lr + 8*lh;

    for (int tk = 0; tk < ntiles; ++tk) {
        if (tk > 0) { CP_WAIT2(); __syncthreads(); }
        const uint32_t sK = smb + 32768 + (tk % 3)*32768;
        const uint32_t sV = sK + 16384;

        // ---- S = Q @ K^T (scale pre-folded into Q) ----
        float sf[8][4];
        #pragma unroll
        for (int nt = 0; nt < 8; ++nt)
            #pragma unroll
            for (int e = 0; e < 4; ++e) sf[nt][e] = 0.f;
        #pragma unroll
        for (int ks = 0; ks < 8; ++ks) {
            const uint32_t swg = 16u * ((2*ks + lg) ^ lr);
            #pragma unroll
            for (int p = 0; p < 4; ++p) {
                uint32_t bq[4];
                LDSM_X4(bq[0],bq[1],bq[2],bq[3], sK + (p*16 + frow)*256 + swg);
                uint32_t be[2] = {bq[0], bq[2]};
                uint32_t bo[2] = {bq[1], bq[3]};
                mma_tf32(sf[2*p],   qa[ks], be);
                mma_tf32(sf[2*p+1], qa[ks], bo);
            }
        }

        // ---- causal mask + row max ----
        const int k0 = tk * AKV;
        float rmax0 = -1e30f, rmax1 = -1e30f;
        #pragma unroll
        for (int nt = 0; nt < 8; ++nt) {
            int jb = k0 + nt*8 + 2*t4;
            #pragma unroll
            for (int e = 0; e < 4; ++e) {
                int j = jb + (e & 1);
                float v = sf[nt][e];
                int qr = (e < 2) ? qi0 : qi1;
                v = (j > qr) ? -1e30f : v;
                sf[nt][e] = v;
                if (e < 2) rmax0 = fmaxf(rmax0, v);
                else       rmax1 = fmaxf(rmax1, v);
            }
        }
        rmax0 = fmaxf(rmax0, __shfl_xor_sync(0xffffffff, rmax0, 1));
        rmax0 = fmaxf(rmax0, __shfl_xor_sync(0xffffffff, rmax0, 2));
        rmax1 = fmaxf(rmax1, __shfl_xor_sync(0xffffffff, rmax1, 1));
        rmax1 = fmaxf(rmax1, __shfl_xor_sync(0xffffffff, rmax1, 2));

        float mn0 = fmaxf(m0, rmax0);
        float mn1 = fmaxf(m1, rmax1);
        float c0 = __expf(m0 - mn0);
        float c1 = __expf(m1 - mn1);

        // ---- exp, P -> smem (A-frag order), row sums ----
        float s0 = 0.f, s1 = 0.f;
        #pragma unroll
        for (int nt = 0; nt < 8; ++nt) {
            #pragma unroll
            for (int e = 0; e < 4; ++e) {
                float p = __expf(sf[nt][e] - ((e < 2) ? mn0 : mn1));
                if (e < 2) s0 += p; else s1 += p;
                int jj = 2*t4 + (e & 1);
                int tt = jj & 3, hc = jj >> 2, hr = (e >> 1);
                sP[(nt*32 + g*4 + tt)*4 + hr + 2*hc] = f2tf32(p);
            }
        }
        s0 += __shfl_xor_sync(0xffffffff, s0, 1);
        s0 += __shfl_xor_sync(0xffffffff, s0, 2);
        s1 += __shfl_xor_sync(0xffffffff, s1, 1);
        s1 += __shfl_xor_sync(0xffffffff, s1, 2);
        l0 = l0*c0 + s0;
        l1 = l1*c1 + s1;
        m0 = mn0; m1 = mn1;

        #pragma unroll
        for (int nt = 0; nt < 8; ++nt) {
            oacc[nt][0] *= c0; oacc[nt][1] *= c0;
            oacc[nt][2] *= c1; oacc[nt][3] *= c1;
        }
        __syncwarp();

        // ---- O += P @ V (VT is K-major: n=d, k=j) ----
        #pragma unroll
        for (int s = 0; s < 8; ++s) {
            uint4 av = *(const uint4*)&sP[(s*32 + lane)*4];
            uint32_t aa[4] = {av.x, av.y, av.z, av.w};
            const uint32_t swg = 16u * ((2*s + lg) ^ lr);
            #pragma unroll
            for (int p = 0; p < 4; ++p) {
                uint32_t bq[4];
                LDSM_X4(bq[0],bq[1],bq[2],bq[3], sV + (p*16 + frow)*256 + swg);
                uint32_t be[2] = {bq[0], bq[2]};
                uint32_t bo[2] = {bq[1], bq[3]};
                mma_tf32(oacc[2*p],   aa, be);
                mma_tf32(oacc[2*p+1], aa, bo);
            }
        }

        __syncthreads();
        if (tk + 3 < ntiles) copy_kv(tk + 3, tk % 3);
        CP_COMMIT();
    }

    // ---- epilogue ----
    const float i0 = 1.f / l0;
    const float i1 = 1.f / l1;
    float* Ob = O + ((size_t)(b*TT))*DM + h*DKH;
    #pragma unroll
    for (int nt = 0; nt < 8; ++nt) {
        int d = nt*8 + 2*t4;
        *(float2*)(Ob + (size_t)qi0*DM + d) = make_float2(oacc[nt][0]*i0, oacc[nt][1]*i0);
        *(float2*)(Ob + (size_t)qi1*DM + d) = make_float2(oacc[nt][2]*i1, oacc[nt][3]*i1);
    }
}

// ===========================================================================
extern "C" void kernel_launch(void* const* d_in, const int* in_sizes, int n_in,
                              void* d_out, int out_size)
{
    const float* q  = (const float*)d_in[0];
    const float* k  = (const float*)d_in[1];
    const float* v  = (const float*)d_in[2];
    const float* wq = (const float*)d_in[4];
    const float* bq = (const float*)d_in[5];
    const float* wk = (const float*)d_in[6];
    const float* bk = (const float*)d_in[7];
    const float* wv = (const float*)d_in[8];
    const float* bv = (const float*)d_in[9];
    const float* wo = (const float*)d_in[10];
    const float* bo = (const float*)d_in[11];
    float* out = (float*)d_out;

    float *gq, *gk, *gvt, *gc, *gwt;
    cudaGetSymbolAddress((void**)&gq, g_Q);
    cudaGetSymbolAddress((void**)&gk, g_K);
    cudaGetSymbolAddress((void**)&gvt, g_VT);
    cudaGetSymbolAddress((void**)&gc, g_C);
    cudaGetSymbolAddress((void**)&gwt, g_WT);
    float* wtq = gwt;
    float* wtk = gwt + (size_t)DM*DM;
    float* wtv = gwt + (size_t)2*DM*DM;
    float* wto = gwt + (size_t)3*DM*DM;

    cudaFuncSetAttribute(attn_tc, cudaFuncAttributeMaxDynamicSharedMemorySize, ATTN_SMEM_TC);
    cudaFuncSetAttribute(gemm_mma<0>, cudaFuncAttributeMaxDynamicSharedMemorySize, GM_SMEM);
    cudaFuncSetAttribute(gemm_mma<1>, cudaFuncAttributeMaxDynamicSharedMemorySize, GM_SMEM);
    cudaFuncSetAttribute(gemm_mma<2>, cudaFuncAttributeMaxDynamicSharedMemorySize, GM_SMEM);

    dim3 tgrid(DM/32, DM/32);
    transpose_tf32<<<tgrid, 256>>>(wq, wtq);
    transpose_tf32<<<tgrid, 256>>>(wk, wtk);
    transpose_tf32<<<tgrid, 256>>>(wv, wtv);
    transpose_tf32<<<tgrid, 256>>>(wo, wto);

    dim3 ggrid(DM/128, MTOK/128);     // (8, 32) = 256 CTAs
    gemm_mma<1><<<ggrid, 256, GM_SMEM>>>(q, wtq, bq, gq, 0.125f);  // Q: round+scale
    gemm_mma<1><<<ggrid, 256, GM_SMEM>>>(k, wtk, bk, gk, 1.0f);    // K: round
    gemm_mma<2><<<ggrid, 256, GM_SMEM>>>(v, wtv, bv, gvt, 1.0f);   // V: transpose+round

    dim3 agrid(TT/AQ_ROWS, NH, BB);   // (16, 16, 2)
    attn_tc<<<agrid, 256, ATTN_SMEM_TC>>>(gq, gk, gvt, gc);

    gemm_mma<0><<<ggrid, 256, GM_SMEM>>>(gc, wto, bo, out, 1.0f);
}

// round 8
// speedup vs baseline: 4.4871x; 1.0374x over previous
#include <cuda_runtime.h>
#include <cstdint>
#include <math.h>

#define BB   2
#define TT   2048
#define DM   1024
#define NH   16
#define DKH  64
#define MTOK (BB*TT)     // 4096

// Scratch (allocation-free)
__device__ float g_Q[MTOK*DM];      // tf32-prerounded, prescaled by 0.125*log2(e)
__device__ float g_K[MTOK*DM];      // tf32-prerounded
__device__ float g_VT[DM*MTOK];     // V transposed [channel][token], tf32
__device__ float g_C[MTOK*DM];
__device__ float g_WT[4][DM*DM];    // W transposed [n][k], tf32-prerounded

__device__ __forceinline__ uint32_t f2tf32(float f) {
    uint32_t r; asm("cvt.rna.tf32.f32 %0, %1;" : "=r"(r) : "f"(f)); return r;
}
__device__ __forceinline__ float fexp2(float x) {
    float y; asm("ex2.approx.f32 %0, %1;" : "=f"(y) : "f"(x)); return y;
}
__device__ __forceinline__ uint32_t smem_u32(const void* p) {
    uint32_t a;
    asm("{ .reg .u64 t; cvta.to.shared.u64 t, %1; cvt.u32.u64 %0, t; }" : "=r"(a) : "l"(p));
    return a;
}
__device__ __forceinline__ void mma_tf32(float* c, const uint32_t* a, const uint32_t* b) {
    asm volatile(
        "mma.sync.aligned.m16n8k8.row.col.f32.tf32.tf32.f32 "
        "{%0,%1,%2,%3}, {%4,%5,%6,%7}, {%8,%9}, {%0,%1,%2,%3};"
        : "+f"(c[0]), "+f"(c[1]), "+f"(c[2]), "+f"(c[3])
        : "r"(a[0]), "r"(a[1]), "r"(a[2]), "r"(a[3]), "r"(b[0]), "r"(b[1]));
}
#define LDSM_X4(r0,r1,r2,r3,addr) \
    asm volatile("ldmatrix.sync.aligned.m8n8.x4.shared.b16 {%0,%1,%2,%3}, [%4];" \
        : "=r"(r0), "=r"(r1), "=r"(r2), "=r"(r3) : "r"(addr))
#define CP_ASYNC16(dst, src) \
    asm volatile("cp.async.cg.shared.global [%0], [%1], 16;" :: "r"(dst), "l"(src))
#define CP_COMMIT()  asm volatile("cp.async.commit_group;" ::: "memory")
#define CP_WAIT2()   asm volatile("cp.async.wait_group 2;" ::: "memory")
#define CP_WAIT1()   asm volatile("cp.async.wait_group 1;" ::: "memory")

#define LOG2E 1.4426950408889634f

// ===========================================================================
// Transpose + tf32-preround: out[n*K+k] = tf32(in[k*N+n])
// ===========================================================================
__global__ __launch_bounds__(256) void transpose_tf32(
    const float* __restrict__ in, float* __restrict__ out)
{
    __shared__ float t[32][33];
    int tx = threadIdx.x & 31;
    int ty = threadIdx.x >> 5;
    int x  = blockIdx.x*32 + tx;
    int y0 = blockIdx.y*32;
    #pragma unroll
    for (int j = ty; j < 32; j += 8) t[j][tx] = in[(size_t)(y0+j)*DM + x];
    __syncthreads();
    int xo  = y0 + tx;
    int yo0 = blockIdx.x*32;
    #pragma unroll
    for (int j = ty; j < 32; j += 8)
        out[(size_t)(yo0+j)*DM + xo] = __uint_as_float(f2tf32(t[tx][j]));
}

// ===========================================================================
// tf32 GEMM: cp.async (3-stage) + swizzled layout + ldmatrix.
// MODE 0: plain fp32 out; MODE 1: tf32((x)*scl); MODE 2: transposed tf32 out
// ===========================================================================
#define NCH      32
#define STAGE_B  32768
#define GM_SMEM  (3*STAGE_B)          // 96 KB

template<int MODE>
__global__ __launch_bounds__(256, 2) void gemm_mma(
    const float* __restrict__ A, const float* __restrict__ WT,
    const float* __restrict__ bias, float* __restrict__ C, float scl)
{
    extern __shared__ char dsm[];
    const uint32_t smb = smem_u32(dsm);

    const int tid  = threadIdx.x;
    const int wid  = tid >> 5;
    const int lane = tid & 31;
    const int wm   = wid >> 1;
    const int wn   = wid & 1;
    const int g    = lane >> 2;
    const int t    = lane & 3;
    const int rowBase = blockIdx.y * 128;
    const int colBase = blockIdx.x * 128;

    const int cprow = tid >> 3;
    const int cpg   = tid & 7;
    const float* aSrc0 = A  + (size_t)(rowBase + cprow)*DM + cpg*4;
    const float* bSrc0 = WT + (size_t)(colBase + cprow)*DM + cpg*4;

    const int lr = lane & 7;
    const int lh = (lane >> 3) & 1;
    const int lg = lane >> 4;
    const int rowA0 = wm*32 + lr + 8*lh;
    const int rowB0 = wn*64 + lr + 8*lh;

    float acc[2][8][4];
    #pragma unroll
    for (int i = 0; i < 2; ++i)
        #pragma unroll
        for (int j = 0; j < 8; ++j)
            #pragma unroll
            for (int e = 0; e < 4; ++e) acc[i][j][e] = 0.f;

    auto copy_chunk = [&](int c, int stage) {
        const int k0 = c * 32;
        const uint32_t sb = smb + stage*STAGE_B;
        #pragma unroll
        for (int i = 0; i < 4; ++i) {
            int row = cprow + i*32;
            uint32_t dst = sb + row*128 + 16*(cpg ^ (row & 7));
            CP_ASYNC16(dst, aSrc0 + (size_t)(i*32)*DM + k0);
        }
        #pragma unroll
        for (int i = 0; i < 4; ++i) {
            int row = cprow + i*32;
            uint32_t dst = sb + 16384 + row*128 + 16*(cpg ^ (row & 7));
            CP_ASYNC16(dst, bSrc0 + (size_t)(i*32)*DM + k0);
        }
    };

    auto compute = [&](int stage) {
        const uint32_t sa = smb + stage*STAGE_B;
        const uint32_t sbB = sa + 16384;
        #pragma unroll
        for (int ks = 0; ks < 4; ++ks) {
            const uint32_t swg = 16u * ((2*ks + lg) ^ lr);
            uint32_t a0[4], a1[4];
            LDSM_X4(a0[0],a0[1],a0[2],a0[3], sa + (rowA0      )*128 + swg);
            LDSM_X4(a1[0],a1[1],a1[2],a1[3], sa + (rowA0 + 16 )*128 + swg);
            #pragma unroll
            for (int r = 0; r < 4; ++r) {
                a0[r] = f2tf32(__uint_as_float(a0[r]));
                a1[r] = f2tf32(__uint_as_float(a1[r]));
            }
            #pragma unroll
            for (int p = 0; p < 4; ++p) {
                uint32_t bq[4];
                LDSM_X4(bq[0],bq[1],bq[2],bq[3], sbB + (rowB0 + p*16)*128 + swg);
                uint32_t be[2] = {bq[0], bq[2]};
                uint32_t bo[2] = {bq[1], bq[3]};
                mma_tf32(acc[0][2*p],   a0, be);
                mma_tf32(acc[1][2*p],   a1, be);
                mma_tf32(acc[0][2*p+1], a0, bo);
                mma_tf32(acc[1][2*p+1], a1, bo);
            }
        }
    };

    copy_chunk(0, 0); CP_COMMIT();
    copy_chunk(1, 1); CP_COMMIT();
    copy_chunk(2, 2); CP_COMMIT();

    for (int c = 0; c < NCH; ++c) {
        CP_WAIT2();
        __syncthreads();
        compute(c % 3);
        __syncthreads();
        if (c + 3 < NCH) copy_chunk(c + 3, c % 3);
        CP_COMMIT();
    }

    #pragma unroll
    for (int mt = 0; mt < 2; ++mt) {
        int r0 = rowBase + wm*32 + mt*16 + g;
        #pragma unroll
        for (int nt = 0; nt < 8; ++nt) {
            int col = colBase + wn*64 + nt*8 + 2*t;
            float b0 = bias[col], b1 = bias[col+1];
            float v00 = acc[mt][nt][0] + b0, v01 = acc[mt][nt][1] + b1;
            float v10 = acc[mt][nt][2] + b0, v11 = acc[mt][nt][3] + b1;
            if (MODE == 0) {
                *(float2*)(C + (size_t)r0*DM + col)     = make_float2(v00, v01);
                *(float2*)(C + (size_t)(r0+8)*DM + col) = make_float2(v10, v11);
            } else if (MODE == 1) {
                float2 w0 = make_float2(__uint_as_float(f2tf32(v00*scl)),
                                        __uint_as_float(f2tf32(v01*scl)));
                float2 w1 = make_float2(__uint_as_float(f2tf32(v10*scl)),
                                        __uint_as_float(f2tf32(v11*scl)));
                *(float2*)(C + (size_t)r0*DM + col)     = w0;
                *(float2*)(C + (size_t)(r0+8)*DM + col) = w1;
            } else {
                C[(size_t)col*MTOK + r0]         = __uint_as_float(f2tf32(v00));
                C[(size_t)(col+1)*MTOK + r0]     = __uint_as_float(f2tf32(v01));
                C[(size_t)col*MTOK + r0 + 8]     = __uint_as_float(f2tf32(v10));
                C[(size_t)(col+1)*MTOK + r0 + 8] = __uint_as_float(f2tf32(v11));
            }
        }
    }
}

// ===========================================================================
// Tensor-core causal flash attention v3: 2 CTAs/SM.
// smem (112 KB): [0,32K) Q persistent; [32K,48K) P (2KB/warp, 32-key half);
//                [48K + st*32K) st=0,1: K 16KB + VT 16KB
// Q fragments reloaded from smem per tile (no persistent qa regs).
// P->smem->PV done in two 32-key halves (P region halved).
// exp via ex2.approx; log2(e) folded into Q prescale.
// ===========================================================================
#define AQ_ROWS 128
#define AKV     64
#define AOFF_P  32768
#define AOFF_KV 49152
#define ATTN_SMEM_TC (AOFF_KV + 2*32768)   // 112 KB

__global__ __launch_bounds__(256, 2) void attn_tc(
    const float* __restrict__ Q, const float* __restrict__ K,
    const float* __restrict__ VT, float* __restrict__ O)
{
    extern __shared__ char smraw[];
    const uint32_t smb = smem_u32(smraw);

    const int tid  = threadIdx.x;
    const int wid  = tid >> 5;
    const int lane = tid & 31;
    const int g    = lane >> 2;
    const int t4   = lane & 3;
    const int lr   = lane & 7;
    const int lh   = (lane >> 3) & 1;
    const int lg   = lane >> 4;
    const int h    = blockIdx.y;
    const int b    = blockIdx.z;
    const int q0   = (gridDim.x - 1 - blockIdx.x) * AQ_ROWS;  // longest first

    const int qi0 = q0 + wid*16 + g;
    const int qi1 = qi0 + 8;

    const float* Qb  = Q + ((size_t)(b*TT))*DM + h*DKH;
    const float* Kb  = K + ((size_t)(b*TT))*DM + h*DKH;
    const float* VTb = VT + (size_t)(h*DKH)*MTOK + b*TT;

    const int ntiles = q0/AKV + 2;

    auto copy_kv = [&](int tile, int st) {
        const int k0 = tile * AKV;
        const uint32_t base = smb + AOFF_KV + st*32768;
        #pragma unroll
        for (int i = 0; i < 4; ++i) {
            int idx = tid + i*256;
            int row = idx >> 4;
            int gg  = idx & 15;
            uint32_t dst = base + row*256 + 16*(gg ^ (row & 7));
            CP_ASYNC16(dst, Kb + (size_t)(k0+row)*DM + gg*4);
        }
        #pragma unroll
        for (int i = 0; i < 4; ++i) {
            int idx = tid + i*256;
            int row = idx >> 4;
            int gg  = idx & 15;
            uint32_t dst = base + 16384 + row*256 + 16*(gg ^ (row & 7));
            CP_ASYNC16(dst, VTb + (size_t)row*MTOK + k0 + gg*4);
        }
    };

    // ---- prologue: Q + first 2 KV tiles ----
    #pragma unroll
    for (int i = 0; i < 8; ++i) {
        int idx = tid + i*256;
        int row = idx >> 4;
        int gg  = idx & 15;
        uint32_t dst = smb + row*256 + 16*(gg ^ (row & 7));
        CP_ASYNC16(dst, Qb + (size_t)(q0+row)*DM + gg*4);
    }
    copy_kv(0, 0); CP_COMMIT();
    copy_kv(1, 1); CP_COMMIT();

    float oacc[8][4];
    #pragma unroll
    for (int nt = 0; nt < 8; ++nt)
        #pragma unroll
        for (int e = 0; e < 4; ++e) oacc[nt][e] = 0.f;
    float m0 = -1e30f, m1 = -1e30f, l0 = 0.f, l1 = 0.f;

    uint32_t* sPw = (uint32_t*)(smraw + AOFF_P + wid*2048);
    const int frow = lr + 8*lh;
    const int qrow = wid*16 + frow;

    for (int tk = 0; tk < ntiles; ++tk) {
        CP_WAIT1();
        __syncthreads();
        const uint32_t sK = smb + AOFF_KV + (tk & 1)*32768;
        const uint32_t sV = sK + 16384;

        // ---- S = Q @ K^T (scale+log2e pre-folded into Q) ----
        float sf[8][4];
        #pragma unroll
        for (int nt = 0; nt < 8; ++nt)
            #pragma unroll
            for (int e = 0; e < 4; ++e) sf[nt][e] = 0.f;
        #pragma unroll
        for (int ks = 0; ks < 8; ++ks) {
            const uint32_t swg = 16u * ((2*ks + lg) ^ lr);
            uint32_t qa[4];
            LDSM_X4(qa[0], qa[1], qa[2], qa[3], smb + qrow*256 + swg);
            #pragma unroll
            for (int p = 0; p < 4; ++p) {
                uint32_t bq[4];
                LDSM_X4(bq[0],bq[1],bq[2],bq[3], sK + (p*16 + frow)*256 + swg);
                uint32_t be[2] = {bq[0], bq[2]};
                uint32_t bo[2] = {bq[1], bq[3]};
                mma_tf32(sf[2*p],   qa, be);
                mma_tf32(sf[2*p+1], qa, bo);
            }
        }

        // ---- causal mask + row max ----
        const int k0 = tk * AKV;
        float rmax0 = -1e30f, rmax1 = -1e30f;
        #pragma unroll
        for (int nt = 0; nt < 8; ++nt) {
            int jb = k0 + nt*8 + 2*t4;
            #pragma unroll
            for (int e = 0; e < 4; ++e) {
                int j = jb + (e & 1);
                float v = sf[nt][e];
                int qr = (e < 2) ? qi0 : qi1;
                v = (j > qr) ? -1e30f : v;
                sf[nt][e] = v;
                if (e < 2) rmax0 = fmaxf(rmax0, v);
                else       rmax1 = fmaxf(rmax1, v);
            }
        }
        rmax0 = fmaxf(rmax0, __shfl_xor_sync(0xffffffff, rmax0, 1));
        rmax0 = fmaxf(rmax0, __shfl_xor_sync(0xffffffff, rmax0, 2));
        rmax1 = fmaxf(rmax1, __shfl_xor_sync(0xffffffff, rmax1, 1));
        rmax1 = fmaxf(rmax1, __shfl_xor_sync(0xffffffff, rmax1, 2));

        float mn0 = fmaxf(m0, rmax0);
        float mn1 = fmaxf(m1, rmax1);
        float c0 = fexp2(m0 - mn0);
        float c1 = fexp2(m1 - mn1);

        // rescale O before PV accumulation
        #pragma unroll
        for (int nt = 0; nt < 8; ++nt) {
            oacc[nt][0] *= c0; oacc[nt][1] *= c0;
            oacc[nt][2] *= c1; oacc[nt][3] *= c1;
        }

        float s0 = 0.f, s1 = 0.f;

        // ---- two 32-key halves: exp+write P, then PV ----
        #pragma unroll
        for (int half = 0; half < 2; ++half) {
            #pragma unroll
            for (int q4 = 0; q4 < 4; ++q4) {
                int nt = half*4 + q4;
                #pragma unroll
                for (int e = 0; e < 4; ++e) {
                    float p = fexp2(sf[nt][e] - ((e < 2) ? mn0 : mn1));
                    if (e < 2) s0 += p; else s1 += p;
                    int jj = 2*t4 + (e & 1);
                    int tt = jj & 3, hc = jj >> 2, hr = (e >> 1);
                    sPw[(q4*32 + g*4 + tt)*4 + hr + 2*hc] = f2tf32(p);
                }
            }
            __syncwarp();
            #pragma unroll
            for (int s4 = 0; s4 < 4; ++s4) {
                int s = half*4 + s4;
                uint4 av = *(const uint4*)&sPw[(s4*32 + lane)*4];
                uint32_t aa[4] = {av.x, av.y, av.z, av.w};
                const uint32_t swg = 16u * ((2*s + lg) ^ lr);
                #pragma unroll
                for (int p = 0; p < 4; ++p) {
                    uint32_t bq[4];
                    LDSM_X4(bq[0],bq[1],bq[2],bq[3], sV + (p*16 + frow)*256 + swg);
                    uint32_t be[2] = {bq[0], bq[2]};
                    uint32_t bo[2] = {bq[1], bq[3]};
                    mma_tf32(oacc[2*p],   aa, be);
                    mma_tf32(oacc[2*p+1], aa, bo);
                }
            }
            __syncwarp();
        }

        s0 += __shfl_xor_sync(0xffffffff, s0, 1);
        s0 += __shfl_xor_sync(0xffffffff, s0, 2);
        s1 += __shfl_xor_sync(0xffffffff, s1, 1);
        s1 += __shfl_xor_sync(0xffffffff, s1, 2);
        l0 = l0*c0 + s0;
        l1 = l1*c1 + s1;
        m0 = mn0; m1 = mn1;

        __syncthreads();
        if (tk + 2 < ntiles) copy_kv(tk + 2, tk & 1);
        CP_COMMIT();
    }

    // ---- epilogue ----
    const float i0 = 1.f / l0;
    const float i1 = 1.f / l1;
    float* Ob = O + ((size_t)(b*TT))*DM + h*DKH;
    #pragma unroll
    for (int nt = 0; nt < 8; ++nt) {
        int d = nt*8 + 2*t4;
        *(float2*)(Ob + (size_t)qi0*DM + d) = make_float2(oacc[nt][0]*i0, oacc[nt][1]*i0);
        *(float2*)(Ob + (size_t)qi1*DM + d) = make_float2(oacc[nt][2]*i1, oacc[nt][3]*i1);
    }
}

// ===========================================================================
extern "C" void kernel_launch(void* const* d_in, const int* in_sizes, int n_in,
                              void* d_out, int out_size)
{
    const float* q  = (const float*)d_in[0];
    const float* k  = (const float*)d_in[1];
    const float* v  = (const float*)d_in[2];
    const float* wq = (const float*)d_in[4];
    const float* bq = (const float*)d_in[5];
    const float* wk = (const float*)d_in[6];
    const float* bk = (const float*)d_in[7];
    const float* wv = (const float*)d_in[8];
    const float* bv = (const float*)d_in[9];
    const float* wo = (const float*)d_in[10];
    const float* bo = (const float*)d_in[11];
    float* out = (float*)d_out;

    float *gq, *gk, *gvt, *gc, *gwt;
    cudaGetSymbolAddress((void**)&gq, g_Q);
    cudaGetSymbolAddress((void**)&gk, g_K);
    cudaGetSymbolAddress((void**)&gvt, g_VT);
    cudaGetSymbolAddress((void**)&gc, g_C);
    cudaGetSymbolAddress((void**)&gwt, g_WT);
    float* wtq = gwt;
    float* wtk = gwt + (size_t)DM*DM;
    float* wtv = gwt + (size_t)2*DM*DM;
    float* wto = gwt + (size_t)3*DM*DM;

    cudaFuncSetAttribute(attn_tc, cudaFuncAttributeMaxDynamicSharedMemorySize, ATTN_SMEM_TC);
    cudaFuncSetAttribute(gemm_mma<0>, cudaFuncAttributeMaxDynamicSharedMemorySize, GM_SMEM);
    cudaFuncSetAttribute(gemm_mma<1>, cudaFuncAttributeMaxDynamicSharedMemorySize, GM_SMEM);
    cudaFuncSetAttribute(gemm_mma<2>, cudaFuncAttributeMaxDynamicSharedMemorySize, GM_SMEM);

    dim3 tgrid(DM/32, DM/32);
    transpose_tf32<<<tgrid, 256>>>(wq, wtq);
    transpose_tf32<<<tgrid, 256>>>(wk, wtk);
    transpose_tf32<<<tgrid, 256>>>(wv, wtv);
    transpose_tf32<<<tgrid, 256>>>(wo, wto);

    dim3 ggrid(DM/128, MTOK/128);     // (8, 32) = 256 CTAs
    gemm_mma<1><<<ggrid, 256, GM_SMEM>>>(q, wtq, bq, gq, 0.125f * LOG2E); // Q: round+scale+log2e
    gemm_mma<1><<<ggrid, 256, GM_SMEM>>>(k, wtk, bk, gk, 1.0f);           // K: round
    gemm_mma<2><<<ggrid, 256, GM_SMEM>>>(v, wtv, bv, gvt, 1.0f);          // V: transpose+round

    dim3 agrid(TT/AQ_ROWS, NH, BB);   // (16, 16, 2)
    attn_tc<<<agrid, 256, ATTN_SMEM_TC>>>(gq, gk, gvt, gc);

    gemm_mma<0><<<ggrid, 256, GM_SMEM>>>(gc, wto, bo, out, 1.0f);
}

// round 9
// speedup vs baseline: 4.5530x; 1.0147x over previous
#include <cuda_runtime.h>
#include <cstdint>
#include <math.h>

#define BB   2
#define TT   2048
#define DM   1024
#define NH   16
#define DKH  64
#define MTOK (BB*TT)     // 4096

// Scratch (allocation-free)
__device__ float g_Q[MTOK*DM];      // tf32-prerounded, prescaled by 0.125*log2(e)
__device__ float g_K[MTOK*DM];      // tf32-prerounded
__device__ float g_VT[DM*MTOK];     // V transposed [channel][token], tf32
__device__ float g_C[MTOK*DM];
__device__ float g_WT[4][DM*DM];    // W transposed [n][k], tf32-prerounded

__device__ __forceinline__ uint32_t f2tf32(float f) {
    uint32_t r; asm("cvt.rna.tf32.f32 %0, %1;" : "=r"(r) : "f"(f)); return r;
}
__device__ __forceinline__ float fexp2(float x) {
    float y; asm("ex2.approx.f32 %0, %1;" : "=f"(y) : "f"(x)); return y;
}
__device__ __forceinline__ uint32_t smem_u32(const void* p) {
    uint32_t a;
    asm("{ .reg .u64 t; cvta.to.shared.u64 t, %1; cvt.u32.u64 %0, t; }" : "=r"(a) : "l"(p));
    return a;
}
__device__ __forceinline__ void mma_tf32(float* c, const uint32_t* a, const uint32_t* b) {
    asm volatile(
        "mma.sync.aligned.m16n8k8.row.col.f32.tf32.tf32.f32 "
        "{%0,%1,%2,%3}, {%4,%5,%6,%7}, {%8,%9}, {%0,%1,%2,%3};"
        : "+f"(c[0]), "+f"(c[1]), "+f"(c[2]), "+f"(c[3])
        : "r"(a[0]), "r"(a[1]), "r"(a[2]), "r"(a[3]), "r"(b[0]), "r"(b[1]));
}
#define LDSM_X4(r0,r1,r2,r3,addr) \
    asm volatile("ldmatrix.sync.aligned.m8n8.x4.shared.b16 {%0,%1,%2,%3}, [%4];" \
        : "=r"(r0), "=r"(r1), "=r"(r2), "=r"(r3) : "r"(addr))
#define CP_ASYNC16(dst, src) \
    asm volatile("cp.async.cg.shared.global [%0], [%1], 16;" :: "r"(dst), "l"(src))
#define CP_COMMIT()  asm volatile("cp.async.commit_group;" ::: "memory")
#define CP_WAIT2()   asm volatile("cp.async.wait_group 2;" ::: "memory")
#define CP_WAIT1()   asm volatile("cp.async.wait_group 1;" ::: "memory")

#define LOG2E 1.4426950408889634f

// ===========================================================================
// Fused transpose + tf32-preround for all 4 weights (z selects)
// ===========================================================================
__global__ __launch_bounds__(256) void transpose_tf32_x4(
    const float* __restrict__ w0, const float* __restrict__ w1,
    const float* __restrict__ w2, const float* __restrict__ w3,
    float* __restrict__ o0, float* __restrict__ o1,
    float* __restrict__ o2, float* __restrict__ o3)
{
    const float* in  = (blockIdx.z == 0) ? w0 : (blockIdx.z == 1) ? w1 :
                       (blockIdx.z == 2) ? w2 : w3;
    float*       out = (blockIdx.z == 0) ? o0 : (blockIdx.z == 1) ? o1 :
                       (blockIdx.z == 2) ? o2 : o3;
    __shared__ float t[32][33];
    int tx = threadIdx.x & 31;
    int ty = threadIdx.x >> 5;
    int x  = blockIdx.x*32 + tx;
    int y0 = blockIdx.y*32;
    #pragma unroll
    for (int j = ty; j < 32; j += 8) t[j][tx] = in[(size_t)(y0+j)*DM + x];
    __syncthreads();
    int xo  = y0 + tx;
    int yo0 = blockIdx.x*32;
    #pragma unroll
    for (int j = ty; j < 32; j += 8)
        out[(size_t)(yo0+j)*DM + xo] = __uint_as_float(f2tf32(t[tx][j]));
}

// ===========================================================================
// tf32 GEMM core v4: 256(M) x 128(N) CTA tile, 512 threads (16 warps, 8m x 2n),
// 4-stage cp.async pipeline, ONE syncthreads per chunk.
// Stage = A 32KB + B 16KB = 48KB; 4 stages = 192KB smem.
// mode 0: fp32 out; mode 1: tf32(x*scl); mode 2: transposed tf32 out
// ===========================================================================
#define NCH      32
#define STG_B    49152
#define GM_SMEM  (4*STG_B)            // 192 KB

__device__ __forceinline__ void gemm_core(
    const float* __restrict__ A, const float* __restrict__ WT,
    const float* __restrict__ bias, float* __restrict__ C,
    float scl, int mode, char* dsm)
{
    const uint32_t smb = smem_u32(dsm);

    const int tid  = threadIdx.x;
    const int wid  = tid >> 5;
    const int lane = tid & 31;
    const int wm   = wid >> 1;           // 0..7
    const int wn   = wid & 1;            // 0..1
    const int g    = lane >> 2;
    const int t    = lane & 3;
    const int rowBase = blockIdx.y * 256;
    const int colBase = blockIdx.x * 128;

    const int cprow = tid >> 3;          // 0..63
    const int cpg   = tid & 7;
    const float* aSrc0 = A  + (size_t)(rowBase + cprow)*DM + cpg*4;
    const float* bSrc0 = WT + (size_t)(colBase + cprow)*DM + cpg*4;

    const int lr = lane & 7;
    const int lh = (lane >> 3) & 1;
    const int lg = lane >> 4;
    const int rowA0 = wm*32 + lr + 8*lh;
    const int rowB0 = wn*64 + lr + 8*lh;

    float acc[2][8][4];
    #pragma unroll
    for (int i = 0; i < 2; ++i)
        #pragma unroll
        for (int j = 0; j < 8; ++j)
            #pragma unroll
            for (int e = 0; e < 4; ++e) acc[i][j][e] = 0.f;

    auto copy_chunk = [&](int c, int stage) {
        const int k0 = c * 32;
        const uint32_t sb = smb + stage*STG_B;
        #pragma unroll
        for (int i = 0; i < 4; ++i) {         // A: 256 rows
            int row = cprow + i*64;
            uint32_t dst = sb + row*128 + 16*(cpg ^ (row & 7));
            CP_ASYNC16(dst, aSrc0 + (size_t)(i*64)*DM + k0);
        }
        #pragma unroll
        for (int i = 0; i < 2; ++i) {         // B: 128 rows
            int row = cprow + i*64;
            uint32_t dst = sb + 32768 + row*128 + 16*(cpg ^ (row & 7));
            CP_ASYNC16(dst, bSrc0 + (size_t)(i*64)*DM + k0);
        }
    };

    auto compute = [&](int stage) {
        const uint32_t sa  = smb + stage*STG_B;
        const uint32_t sbB = sa + 32768;
        #pragma unroll
        for (int ks = 0; ks < 4; ++ks) {
            const uint32_t swg = 16u * ((2*ks + lg) ^ lr);
            uint32_t a0[4], a1[4];
            LDSM_X4(a0[0],a0[1],a0[2],a0[3], sa + (rowA0      )*128 + swg);
            LDSM_X4(a1[0],a1[1],a1[2],a1[3], sa + (rowA0 + 16 )*128 + swg);
            #pragma unroll
            for (int r = 0; r < 4; ++r) {
                a0[r] = f2tf32(__uint_as_float(a0[r]));
                a1[r] = f2tf32(__uint_as_float(a1[r]));
            }
            #pragma unroll
            for (int p = 0; p < 4; ++p) {
                uint32_t bq[4];
                LDSM_X4(bq[0],bq[1],bq[2],bq[3], sbB + (rowB0 + p*16)*128 + swg);
                uint32_t be[2] = {bq[0], bq[2]};
                uint32_t bo[2] = {bq[1], bq[3]};
                mma_tf32(acc[0][2*p],   a0, be);
                mma_tf32(acc[1][2*p],   a1, be);
                mma_tf32(acc[0][2*p+1], a0, bo);
                mma_tf32(acc[1][2*p+1], a1, bo);
            }
        }
    };

    copy_chunk(0, 0); CP_COMMIT();
    copy_chunk(1, 1); CP_COMMIT();
    copy_chunk(2, 2); CP_COMMIT();

    for (int c = 0; c < NCH; ++c) {
        CP_WAIT2();
        __syncthreads();                 // chunk c visible; stage (c+3)&3 free
        if (c + 3 < NCH) copy_chunk(c + 3, (c + 3) & 3);
        CP_COMMIT();
        compute(c & 3);
    }

    #pragma unroll
    for (int mt = 0; mt < 2; ++mt) {
        int r0 = rowBase + wm*32 + mt*16 + g;
        #pragma unroll
        for (int nt = 0; nt < 8; ++nt) {
            int col = colBase + wn*64 + nt*8 + 2*t;
            float b0 = bias[col], b1 = bias[col+1];
            float v00 = acc[mt][nt][0] + b0, v01 = acc[mt][nt][1] + b1;
            float v10 = acc[mt][nt][2] + b0, v11 = acc[mt][nt][3] + b1;
            if (mode == 0) {
                *(float2*)(C + (size_t)r0*DM + col)     = make_float2(v00, v01);
                *(float2*)(C + (size_t)(r0+8)*DM + col) = make_float2(v10, v11);
            } else if (mode == 1) {
                float2 w0 = make_float2(__uint_as_float(f2tf32(v00*scl)),
                                        __uint_as_float(f2tf32(v01*scl)));
                float2 w1 = make_float2(__uint_as_float(f2tf32(v10*scl)),
                                        __uint_as_float(f2tf32(v11*scl)));
                *(float2*)(C + (size_t)r0*DM + col)     = w0;
                *(float2*)(C + (size_t)(r0+8)*DM + col) = w1;
            } else {
                C[(size_t)col*MTOK + r0]         = __uint_as_float(f2tf32(v00));
                C[(size_t)(col+1)*MTOK + r0]     = __uint_as_float(f2tf32(v01));
                C[(size_t)col*MTOK + r0 + 8]     = __uint_as_float(f2tf32(v10));
                C[(size_t)(col+1)*MTOK + r0 + 8] = __uint_as_float(f2tf32(v11));
            }
        }
    }
}

// Fused Q/K/V projection: blockIdx.z selects input/weight/output + mode.
__global__ __launch_bounds__(512, 1) void gemm_qkv(
    const float* __restrict__ q, const float* __restrict__ k, const float* __restrict__ v,
    const float* __restrict__ wtq, const float* __restrict__ wtk, const float* __restrict__ wtv,
    const float* __restrict__ bq, const float* __restrict__ bk, const float* __restrict__ bv,
    float* __restrict__ oq, float* __restrict__ ok, float* __restrict__ ovt)
{
    extern __shared__ char dsm[];
    const int z = blockIdx.z;
    const float* A  = (z == 0) ? q   : (z == 1) ? k   : v;
    const float* WT = (z == 0) ? wtq : (z == 1) ? wtk : wtv;
    const float* bb = (z == 0) ? bq  : (z == 1) ? bk  : bv;
    float*       C  = (z == 0) ? oq  : (z == 1) ? ok  : ovt;
    float scl = (z == 0) ? 0.125f * LOG2E : 1.0f;
    int mode  = (z == 2) ? 2 : 1;
    gemm_core(A, WT, bb, C, scl, mode, dsm);
}

__global__ __launch_bounds__(512, 1) void gemm_out(
    const float* __restrict__ A, const float* __restrict__ WT,
    const float* __restrict__ bias, float* __restrict__ C)
{
    extern __shared__ char dsm[];
    gemm_core(A, WT, bias, C, 1.0f, 0, dsm);
}

// ===========================================================================
// Tensor-core causal flash attention (unchanged from R8 passing version)
// ===========================================================================
#define AQ_ROWS 128
#define AKV     64
#define AOFF_P  32768
#define AOFF_KV 49152
#define ATTN_SMEM_TC (AOFF_KV + 2*32768)   // 112 KB

__global__ __launch_bounds__(256, 2) void attn_tc(
    const float* __restrict__ Q, const float* __restrict__ K,
    const float* __restrict__ VT, float* __restrict__ O)
{
    extern __shared__ char smraw[];
    const uint32_t smb = smem_u32(smraw);

    const int tid  = threadIdx.x;
    const int wid  = tid >> 5;
    const int lane = tid & 31;
    const int g    = lane >> 2;
    const int t4   = lane & 3;
    const int lr   = lane & 7;
    const int lh   = (lane >> 3) & 1;
    const int lg   = lane >> 4;
    const int h    = blockIdx.y;
    const int b    = blockIdx.z;
    const int q0   = (gridDim.x - 1 - blockIdx.x) * AQ_ROWS;

    const int qi0 = q0 + wid*16 + g;
    const int qi1 = qi0 + 8;

    const float* Qb  = Q + ((size_t)(b*TT))*DM + h*DKH;
    const float* Kb  = K + ((size_t)(b*TT))*DM + h*DKH;
    const float* VTb = VT + (size_t)(h*DKH)*MTOK + b*TT;

    const int ntiles = q0/AKV + 2;

    auto copy_kv = [&](int tile, int st) {
        const int k0 = tile * AKV;
        const uint32_t base = smb + AOFF_KV + st*32768;
        #pragma unroll
        for (int i = 0; i < 4; ++i) {
            int idx = tid + i*256;
            int row = idx >> 4;
            int gg  = idx & 15;
            uint32_t dst = base + row*256 + 16*(gg ^ (row & 7));
            CP_ASYNC16(dst, Kb + (size_t)(k0+row)*DM + gg*4);
        }
        #pragma unroll
        for (int i = 0; i < 4; ++i) {
            int idx = tid + i*256;
            int row = idx >> 4;
            int gg  = idx & 15;
            uint32_t dst = base + 16384 + row*256 + 16*(gg ^ (row & 7));
            CP_ASYNC16(dst, VTb + (size_t)row*MTOK + k0 + gg*4);
        }
    };

    #pragma unroll
    for (int i = 0; i < 8; ++i) {
        int idx = tid + i*256;
        int row = idx >> 4;
        int gg  = idx & 15;
        uint32_t dst = smb + row*256 + 16*(gg ^ (row & 7));
        CP_ASYNC16(dst, Qb + (size_t)(q0+row)*DM + gg*4);
    }
    copy_kv(0, 0); CP_COMMIT();
    copy_kv(1, 1); CP_COMMIT();

    float oacc[8][4];
    #pragma unroll
    for (int nt = 0; nt < 8; ++nt)
        #pragma unroll
        for (int e = 0; e < 4; ++e) oacc[nt][e] = 0.f;
    float m0 = -1e30f, m1 = -1e30f, l0 = 0.f, l1 = 0.f;

    uint32_t* sPw = (uint32_t*)(smraw + AOFF_P + wid*2048);
    const int frow = lr + 8*lh;
    const int qrow = wid*16 + frow;

    for (int tk = 0; tk < ntiles; ++tk) {
        CP_WAIT1();
        __syncthreads();
        const uint32_t sK = smb + AOFF_KV + (tk & 1)*32768;
        const uint32_t sV = sK + 16384;

        float sf[8][4];
        #pragma unroll
        for (int nt = 0; nt < 8; ++nt)
            #pragma unroll
            for (int e = 0; e < 4; ++e) sf[nt][e] = 0.f;
        #pragma unroll
        for (int ks = 0; ks < 8; ++ks) {
            const uint32_t swg = 16u * ((2*ks + lg) ^ lr);
            uint32_t qa[4];
            LDSM_X4(qa[0], qa[1], qa[2], qa[3], smb + qrow*256 + swg);
            #pragma unroll
            for (int p = 0; p < 4; ++p) {
                uint32_t bq[4];
                LDSM_X4(bq[0],bq[1],bq[2],bq[3], sK + (p*16 + frow)*256 + swg);
                uint32_t be[2] = {bq[0], bq[2]};
                uint32_t bo[2] = {bq[1], bq[3]};
                mma_tf32(sf[2*p],   qa, be);
                mma_tf32(sf[2*p+1], qa, bo);
            }
        }

        const int k0 = tk * AKV;
        float rmax0 = -1e30f, rmax1 = -1e30f;
        #pragma unroll
        for (int nt = 0; nt < 8; ++nt) {
            int jb = k0 + nt*8 + 2*t4;
            #pragma unroll
            for (int e = 0; e < 4; ++e) {
                int j = jb + (e & 1);
                float v = sf[nt][e];
                int qr = (e < 2) ? qi0 : qi1;
                v = (j > qr) ? -1e30f : v;
                sf[nt][e] = v;
                if (e < 2) rmax0 = fmaxf(rmax0, v);
                else       rmax1 = fmaxf(rmax1, v);
            }
        }
        rmax0 = fmaxf(rmax0, __shfl_xor_sync(0xffffffff, rmax0, 1));
        rmax0 = fmaxf(rmax0, __shfl_xor_sync(0xffffffff, rmax0, 2));
        rmax1 = fmaxf(rmax1, __shfl_xor_sync(0xffffffff, rmax1, 1));
        rmax1 = fmaxf(rmax1, __shfl_xor_sync(0xffffffff, rmax1, 2));

        float mn0 = fmaxf(m0, rmax0);
        float mn1 = fmaxf(m1, rmax1);
        float c0 = fexp2(m0 - mn0);
        float c1 = fexp2(m1 - mn1);

        #pragma unroll
        for (int nt = 0; nt < 8; ++nt) {
            oacc[nt][0] *= c0; oacc[nt][1] *= c0;
            oacc[nt][2] *= c1; oacc[nt][3] *= c1;
        }

        float s0 = 0.f, s1 = 0.f;
        #pragma unroll
        for (int half = 0; half < 2; ++half) {
            #pragma unroll
            for (int q4 = 0; q4 < 4; ++q4) {
                int nt = half*4 + q4;
                #pragma unroll
                for (int e = 0; e < 4; ++e) {
                    float p = fexp2(sf[nt][e] - ((e < 2) ? mn0 : mn1));
                    if (e < 2) s0 += p; else s1 += p;
                    int jj = 2*t4 + (e & 1);
                    int tt = jj & 3, hc = jj >> 2, hr = (e >> 1);
                    sPw[(q4*32 + g*4 + tt)*4 + hr + 2*hc] = f2tf32(p);
                }
            }
            __syncwarp();
            #pragma unroll
            for (int s4 = 0; s4 < 4; ++s4) {
                int s = half*4 + s4;
                uint4 av = *(const uint4*)&sPw[(s4*32 + lane)*4];
                uint32_t aa[4] = {av.x, av.y, av.z, av.w};
                const uint32_t swg = 16u * ((2*s + lg) ^ lr);
                #pragma unroll
                for (int p = 0; p < 4; ++p) {
                    uint32_t bq[4];
                    LDSM_X4(bq[0],bq[1],bq[2],bq[3], sV + (p*16 + frow)*256 + swg);
                    uint32_t be[2] = {bq[0], bq[2]};
                    uint32_t bo[2] = {bq[1], bq[3]};
                    mma_tf32(oacc[2*p],   aa, be);
                    mma_tf32(oacc[2*p+1], aa, bo);
                }
            }
            __syncwarp();
        }

        s0 += __shfl_xor_sync(0xffffffff, s0, 1);
        s0 += __shfl_xor_sync(0xffffffff, s0, 2);
        s1 += __shfl_xor_sync(0xffffffff, s1, 1);
        s1 += __shfl_xor_sync(0xffffffff, s1, 2);
        l0 = l0*c0 + s0;
        l1 = l1*c1 + s1;
        m0 = mn0; m1 = mn1;

        __syncthreads();
        if (tk + 2 < ntiles) copy_kv(tk + 2, tk & 1);
        CP_COMMIT();
    }

    const float i0 = 1.f / l0;
    const float i1 = 1.f / l1;
    float* Ob = O + ((size_t)(b*TT))*DM + h*DKH;
    #pragma unroll
    for (int nt = 0; nt < 8; ++nt) {
        int d = nt*8 + 2*t4;
        *(float2*)(Ob + (size_t)qi0*DM + d) = make_float2(oacc[nt][0]*i0, oacc[nt][1]*i0);
        *(float2*)(Ob + (size_t)qi1*DM + d) = make_float2(oacc[nt][2]*i1, oacc[nt][3]*i1);
    }
}

// ===========================================================================
extern "C" void kernel_launch(void* const* d_in, const int* in_sizes, int n_in,
                              void* d_out, int out_size)
{
    const float* q  = (const float*)d_in[0];
    const float* k  = (const float*)d_in[1];
    const float* v  = (const float*)d_in[2];
    const float* wq = (const float*)d_in[4];
    const float* bq = (const float*)d_in[5];
    const float* wk = (const float*)d_in[6];
    const float* bk = (const float*)d_in[7];
    const float* wv = (const float*)d_in[8];
    const float* bv = (const float*)d_in[9];
    const float* wo = (const float*)d_in[10];
    const float* bo = (const float*)d_in[11];
    float* out = (float*)d_out;

    float *gq, *gk, *gvt, *gc, *gwt;
    cudaGetSymbolAddress((void**)&gq, g_Q);
    cudaGetSymbolAddress((void**)&gk, g_K);
    cudaGetSymbolAddress((void**)&gvt, g_VT);
    cudaGetSymbolAddress((void**)&gc, g_C);
    cudaGetSymbolAddress((void**)&gwt, g_WT);
    float* wtq = gwt;
    float* wtk = gwt + (size_t)DM*DM;
    float* wtv = gwt + (size_t)2*DM*DM;
    float* wto = gwt + (size_t)3*DM*DM;

    cudaFuncSetAttribute(attn_tc, cudaFuncAttributeMaxDynamicSharedMemorySize, ATTN_SMEM_TC);
    cudaFuncSetAttribute(gemm_qkv, cudaFuncAttributeMaxDynamicSharedMemorySize, GM_SMEM);
    cudaFuncSetAttribute(gemm_out, cudaFuncAttributeMaxDynamicSharedMemorySize, GM_SMEM);

    dim3 tgrid(DM/32, DM/32, 4);
    transpose_tf32_x4<<<tgrid, 256>>>(wq, wk, wv, wo, wtq, wtk, wtv, wto);

    dim3 qkvgrid(DM/128, MTOK/256, 3);   // (8, 16, 3) = 384 CTAs
    gemm_qkv<<<qkvgrid, 512, GM_SMEM>>>(q, k, v, wtq, wtk, wtv, bq, bk, bv,
                                        gq, gk, gvt);

    dim3 agrid(TT/AQ_ROWS, NH, BB);      // (16, 16, 2)
    attn_tc<<<agrid, 256, ATTN_SMEM_TC>>>(gq, gk, gvt, gc);

    dim3 ogrid(DM/128, MTOK/256);        // (8, 16) = 128 CTAs
    gemm_out<<<ogrid, 512, GM_SMEM>>>(gc, wto, bo, out);
}

// round 10
// speedup vs baseline: 4.6165x; 1.0139x over previous
#include <cuda_runtime.h>
#include <cstdint>
#include <math.h>

#define BB   2
#define TT   2048
#define DM   1024
#define NH   16
#define DKH  64
#define MTOK (BB*TT)     // 4096

// Scratch (allocation-free)
__device__ float g_Q[MTOK*DM];      // tf32-prerounded, prescaled by 0.125*log2(e)
__device__ float g_K[MTOK*DM];      // tf32-prerounded
__device__ float g_VT[DM*MTOK];     // V transposed [channel][token], tf32
__device__ float g_C[MTOK*DM];
__device__ float g_WT[4][DM*DM];    // W transposed [n][k], tf32-prerounded

__device__ __forceinline__ uint32_t f2tf32(float f) {
    uint32_t r; asm("cvt.rna.tf32.f32 %0, %1;" : "=r"(r) : "f"(f)); return r;
}
__device__ __forceinline__ float fexp2(float x) {
    float y; asm("ex2.approx.f32 %0, %1;" : "=f"(y) : "f"(x)); return y;
}
__device__ __forceinline__ uint32_t smem_u32(const void* p) {
    uint32_t a;
    asm("{ .reg .u64 t; cvta.to.shared.u64 t, %1; cvt.u32.u64 %0, t; }" : "=r"(a) : "l"(p));
    return a;
}
__device__ __forceinline__ void mma_tf32(float* c, const uint32_t* a, const uint32_t* b) {
    asm volatile(
        "mma.sync.aligned.m16n8k8.row.col.f32.tf32.tf32.f32 "
        "{%0,%1,%2,%3}, {%4,%5,%6,%7}, {%8,%9}, {%0,%1,%2,%3};"
        : "+f"(c[0]), "+f"(c[1]), "+f"(c[2]), "+f"(c[3])
        : "r"(a[0]), "r"(a[1]), "r"(a[2]), "r"(a[3]), "r"(b[0]), "r"(b[1]));
}
#define LDSM_X4(r0,r1,r2,r3,addr) \
    asm volatile("ldmatrix.sync.aligned.m8n8.x4.shared.b16 {%0,%1,%2,%3}, [%4];" \
        : "=r"(r0), "=r"(r1), "=r"(r2), "=r"(r3) : "r"(addr))
#define CP_ASYNC16(dst, src) \
    asm volatile("cp.async.cg.shared.global [%0], [%1], 16;" :: "r"(dst), "l"(src))
#define CP_COMMIT()  asm volatile("cp.async.commit_group;" ::: "memory")
#define CP_WAIT2()   asm volatile("cp.async.wait_group 2;" ::: "memory")
#define CP_WAIT1()   asm volatile("cp.async.wait_group 1;" ::: "memory")
#define CP_WAIT0()   asm volatile("cp.async.wait_group 0;" ::: "memory")

#define LOG2E 1.4426950408889634f

// ===========================================================================
// Fused transpose + tf32-preround for all 4 weights (z selects)
// ===========================================================================
__global__ __launch_bounds__(256) void transpose_tf32_x4(
    const float* __restrict__ w0, const float* __restrict__ w1,
    const float* __restrict__ w2, const float* __restrict__ w3,
    float* __restrict__ o0, float* __restrict__ o1,
    float* __restrict__ o2, float* __restrict__ o3)
{
    const float* in  = (blockIdx.z == 0) ? w0 : (blockIdx.z == 1) ? w1 :
                       (blockIdx.z == 2) ? w2 : w3;
    float*       out = (blockIdx.z == 0) ? o0 : (blockIdx.z == 1) ? o1 :
                       (blockIdx.z == 2) ? o2 : o3;
    __shared__ float t[32][33];
    int tx = threadIdx.x & 31;
    int ty = threadIdx.x >> 5;
    int x  = blockIdx.x*32 + tx;
    int y0 = blockIdx.y*32;
    #pragma unroll
    for (int j = ty; j < 32; j += 8) t[j][tx] = in[(size_t)(y0+j)*DM + x];
    __syncthreads();
    int xo  = y0 + tx;
    int yo0 = blockIdx.x*32;
    #pragma unroll
    for (int j = ty; j < 32; j += 8)
        out[(size_t)(yo0+j)*DM + xo] = __uint_as_float(f2tf32(t[tx][j]));
}

// ===========================================================================
// tf32 GEMM core: 256(M) x 128(N) CTA tile, 512 threads (16 warps, 8m x 2n),
// 4-stage cp.async pipeline, one syncthreads per chunk.
// mode 0: fp32 out; mode 1: tf32(x*scl); mode 2: transposed tf32 out
// ===========================================================================
#define NCH      32
#define STG_B    49152
#define GM_SMEM  (4*STG_B)            // 192 KB

__device__ __forceinline__ void gemm_core(
    const float* __restrict__ A, const float* __restrict__ WT,
    const float* __restrict__ bias, float* __restrict__ C,
    float scl, int mode, char* dsm)
{
    const uint32_t smb = smem_u32(dsm);

    const int tid  = threadIdx.x;
    const int wid  = tid >> 5;
    const int lane = tid & 31;
    const int wm   = wid >> 1;
    const int wn   = wid & 1;
    const int g    = lane >> 2;
    const int t    = lane & 3;
    const int rowBase = blockIdx.y * 256;
    const int colBase = blockIdx.x * 128;

    const int cprow = tid >> 3;
    const int cpg   = tid & 7;
    const float* aSrc0 = A  + (size_t)(rowBase + cprow)*DM + cpg*4;
    const float* bSrc0 = WT + (size_t)(colBase + cprow)*DM + cpg*4;

    const int lr = lane & 7;
    const int lh = (lane >> 3) & 1;
    const int lg = lane >> 4;
    const int rowA0 = wm*32 + lr + 8*lh;
    const int rowB0 = wn*64 + lr + 8*lh;

    float acc[2][8][4];
    #pragma unroll
    for (int i = 0; i < 2; ++i)
        #pragma unroll
        for (int j = 0; j < 8; ++j)
            #pragma unroll
            for (int e = 0; e < 4; ++e) acc[i][j][e] = 0.f;

    auto copy_chunk = [&](int c, int stage) {
        const int k0 = c * 32;
        const uint32_t sb = smb + stage*STG_B;
        #pragma unroll
        for (int i = 0; i < 4; ++i) {
            int row = cprow + i*64;
            uint32_t dst = sb + row*128 + 16*(cpg ^ (row & 7));
            CP_ASYNC16(dst, aSrc0 + (size_t)(i*64)*DM + k0);
        }
        #pragma unroll
        for (int i = 0; i < 2; ++i) {
            int row = cprow + i*64;
            uint32_t dst = sb + 32768 + row*128 + 16*(cpg ^ (row & 7));
            CP_ASYNC16(dst, bSrc0 + (size_t)(i*64)*DM + k0);
        }
    };

    auto compute = [&](int stage) {
        const uint32_t sa  = smb + stage*STG_B;
        const uint32_t sbB = sa + 32768;
        #pragma unroll
        for (int ks = 0; ks < 4; ++ks) {
            const uint32_t swg = 16u * ((2*ks + lg) ^ lr);
            uint32_t a0[4], a1[4];
            LDSM_X4(a0[0],a0[1],a0[2],a0[3], sa + (rowA0      )*128 + swg);
            LDSM_X4(a1[0],a1[1],a1[2],a1[3], sa + (rowA0 + 16 )*128 + swg);
            #pragma unroll
            for (int r = 0; r < 4; ++r) {
                a0[r] = f2tf32(__uint_as_float(a0[r]));
                a1[r] = f2tf32(__uint_as_float(a1[r]));
            }
            #pragma unroll
            for (int p = 0; p < 4; ++p) {
                uint32_t bq[4];
                LDSM_X4(bq[0],bq[1],bq[2],bq[3], sbB + (rowB0 + p*16)*128 + swg);
                uint32_t be[2] = {bq[0], bq[2]};
                uint32_t bo[2] = {bq[1], bq[3]};
                mma_tf32(acc[0][2*p],   a0, be);
                mma_tf32(acc[1][2*p],   a1, be);
                mma_tf32(acc[0][2*p+1], a0, bo);
                mma_tf32(acc[1][2*p+1], a1, bo);
            }
        }
    };

    copy_chunk(0, 0); CP_COMMIT();
    copy_chunk(1, 1); CP_COMMIT();
    copy_chunk(2, 2); CP_COMMIT();

    for (int c = 0; c < NCH; ++c) {
        CP_WAIT2();
        __syncthreads();
        if (c + 3 < NCH) copy_chunk(c + 3, (c + 3) & 3);
        CP_COMMIT();
        compute(c & 3);
    }

    #pragma unroll
    for (int mt = 0; mt < 2; ++mt) {
        int r0 = rowBase + wm*32 + mt*16 + g;
        #pragma unroll
        for (int nt = 0; nt < 8; ++nt) {
            int col = colBase + wn*64 + nt*8 + 2*t;
            float b0 = bias[col], b1 = bias[col+1];
            float v00 = acc[mt][nt][0] + b0, v01 = acc[mt][nt][1] + b1;
            float v10 = acc[mt][nt][2] + b0, v11 = acc[mt][nt][3] + b1;
            if (mode == 0) {
                *(float2*)(C + (size_t)r0*DM + col)     = make_float2(v00, v01);
                *(float2*)(C + (size_t)(r0+8)*DM + col) = make_float2(v10, v11);
            } else if (mode == 1) {
                float2 w0 = make_float2(__uint_as_float(f2tf32(v00*scl)),
                                        __uint_as_float(f2tf32(v01*scl)));
                float2 w1 = make_float2(__uint_as_float(f2tf32(v10*scl)),
                                        __uint_as_float(f2tf32(v11*scl)));
                *(float2*)(C + (size_t)r0*DM + col)     = w0;
                *(float2*)(C + (size_t)(r0+8)*DM + col) = w1;
            } else {
                C[(size_t)col*MTOK + r0]         = __uint_as_float(f2tf32(v00));
                C[(size_t)(col+1)*MTOK + r0]     = __uint_as_float(f2tf32(v01));
                C[(size_t)col*MTOK + r0 + 8]     = __uint_as_float(f2tf32(v10));
                C[(size_t)(col+1)*MTOK + r0 + 8] = __uint_as_float(f2tf32(v11));
            }
        }
    }
}

__global__ __launch_bounds__(512, 1) void gemm_qkv(
    const float* __restrict__ q, const float* __restrict__ k, const float* __restrict__ v,
    const float* __restrict__ wtq, const float* __restrict__ wtk, const float* __restrict__ wtv,
    const float* __restrict__ bq, const float* __restrict__ bk, const float* __restrict__ bv,
    float* __restrict__ oq, float* __restrict__ ok, float* __restrict__ ovt)
{
    extern __shared__ char dsm[];
    const int z = blockIdx.z;
    const float* A  = (z == 0) ? q   : (z == 1) ? k   : v;
    const float* WT = (z == 0) ? wtq : (z == 1) ? wtk : wtv;
    const float* bb = (z == 0) ? bq  : (z == 1) ? bk  : bv;
    float*       C  = (z == 0) ? oq  : (z == 1) ? ok  : ovt;
    float scl = (z == 0) ? 0.125f * LOG2E : 1.0f;
    int mode  = (z == 2) ? 2 : 1;
    gemm_core(A, WT, bb, C, scl, mode, dsm);
}

__global__ __launch_bounds__(512, 1) void gemm_out(
    const float* __restrict__ A, const float* __restrict__ WT,
    const float* __restrict__ bias, float* __restrict__ C)
{
    extern __shared__ char dsm[];
    gemm_core(A, WT, bias, C, 1.0f, 0, dsm);
}

// ===========================================================================
// Tensor-core causal flash attention v4: software-pipelined S(t+1).
// smem (112 KB): [0,32K) Q persistent; [32K,48K) P (2KB/warp, 32-key half);
//                [48K + st*32K) st=0,1: K 16KB + VT 16KB
// Inner loop: softmax(t), exp+PV half0, exp half1, S(t+1), PV half1.
// Interior tiles skip causal-mask compares.
// ===========================================================================
#define AQ_ROWS 128
#define AKV     64
#define AOFF_P  32768
#define AOFF_KV 49152
#define ATTN_SMEM_TC (AOFF_KV + 2*32768)   // 112 KB

__global__ __launch_bounds__(256, 2) void attn_tc(
    const float* __restrict__ Q, const float* __restrict__ K,
    const float* __restrict__ VT, float* __restrict__ O)
{
    extern __shared__ char smraw[];
    const uint32_t smb = smem_u32(smraw);

    const int tid  = threadIdx.x;
    const int wid  = tid >> 5;
    const int lane = tid & 31;
    const int g    = lane >> 2;
    const int t4   = lane & 3;
    const int lr   = lane & 7;
    const int lh   = (lane >> 3) & 1;
    const int lg   = lane >> 4;
    const int h    = blockIdx.y;
    const int b    = blockIdx.z;
    const int q0   = (gridDim.x - 1 - blockIdx.x) * AQ_ROWS;

    const int qi0 = q0 + wid*16 + g;
    const int qi1 = qi0 + 8;

    const float* Qb  = Q + ((size_t)(b*TT))*DM + h*DKH;
    const float* Kb  = K + ((size_t)(b*TT))*DM + h*DKH;
    const float* VTb = VT + (size_t)(h*DKH)*MTOK + b*TT;

    const int ntiles = q0/AKV + 2;

    auto copy_kv = [&](int tile, int st) {
        const int k0 = tile * AKV;
        const uint32_t base = smb + AOFF_KV + st*32768;
        #pragma unroll
        for (int i = 0; i < 4; ++i) {
            int idx = tid + i*256;
            int row = idx >> 4;
            int gg  = idx & 15;
            uint32_t dst = base + row*256 + 16*(gg ^ (row & 7));
            CP_ASYNC16(dst, Kb + (size_t)(k0+row)*DM + gg*4);
        }
        #pragma unroll
        for (int i = 0; i < 4; ++i) {
            int idx = tid + i*256;
            int row = idx >> 4;
            int gg  = idx & 15;
            uint32_t dst = base + 16384 + row*256 + 16*(gg ^ (row & 7));
            CP_ASYNC16(dst, VTb + (size_t)row*MTOK + k0 + gg*4);
        }
    };

    const int frow = lr + 8*lh;
    const int qrow = wid*16 + frow;

    float sf[8][4];

    // S = Q@K^T from KV stage st into sf
    auto do_S = [&](int st) {
        const uint32_t sK = smb + AOFF_KV + st*32768;
        #pragma unroll
        for (int nt = 0; nt < 8; ++nt)
            #pragma unroll
            for (int e = 0; e < 4; ++e) sf[nt][e] = 0.f;
        #pragma unroll
        for (int ks = 0; ks < 8; ++ks) {
            const uint32_t swg = 16u * ((2*ks + lg) ^ lr);
            uint32_t qa[4];
            LDSM_X4(qa[0], qa[1], qa[2], qa[3], smb + qrow*256 + swg);
            #pragma unroll
            for (int p = 0; p < 4; ++p) {
                uint32_t bq[4];
                LDSM_X4(bq[0],bq[1],bq[2],bq[3], sK + (p*16 + frow)*256 + swg);
                uint32_t be[2] = {bq[0], bq[2]};
                uint32_t bo[2] = {bq[1], bq[3]};
                mma_tf32(sf[2*p],   qa, be);
                mma_tf32(sf[2*p+1], qa, bo);
            }
        }
    };

    // ---- prologue: Q staging + first 2 KV tiles ----
    #pragma unroll
    for (int i = 0; i < 8; ++i) {
        int idx = tid + i*256;
        int row = idx >> 4;
        int gg  = idx & 15;
        uint32_t dst = smb + row*256 + 16*(gg ^ (row & 7));
        CP_ASYNC16(dst, Qb + (size_t)(q0+row)*DM + gg*4);
    }
    copy_kv(0, 0); CP_COMMIT();
    copy_kv(1, 1); CP_COMMIT();

    float oacc[8][4];
    #pragma unroll
    for (int nt = 0; nt < 8; ++nt)
        #pragma unroll
        for (int e = 0; e < 4; ++e) oacc[nt][e] = 0.f;
    float m0 = -1e30f, m1 = -1e30f, l0 = 0.f, l1 = 0.f;

    uint32_t* sPw = (uint32_t*)(smraw + AOFF_P + wid*2048);

    CP_WAIT1();
    __syncthreads();
    do_S(0);                              // S(0)

    for (int tk = 0; tk < ntiles; ++tk) {
        const uint32_t sV = smb + AOFF_KV + (tk & 1)*32768 + 16384;

        // ---- mask (diagonal tiles only) + row max ----
        float rmax0 = -1e30f, rmax1 = -1e30f;
        if (tk >= ntiles - 2) {
            const int k0 = tk * AKV;
            #pragma unroll
            for (int nt = 0; nt < 8; ++nt) {
                int jb = k0 + nt*8 + 2*t4;
                #pragma unroll
                for (int e = 0; e < 4; ++e) {
                    int j = jb + (e & 1);
                    float v = sf[nt][e];
                    int qr = (e < 2) ? qi0 : qi1;
                    v = (j > qr) ? -1e30f : v;
                    sf[nt][e] = v;
                    if (e < 2) rmax0 = fmaxf(rmax0, v);
                    else       rmax1 = fmaxf(rmax1, v);
                }
            }
        } else {
            #pragma unroll
            for (int nt = 0; nt < 8; ++nt) {
                rmax0 = fmaxf(rmax0, fmaxf(sf[nt][0], sf[nt][1]));
                rmax1 = fmaxf(rmax1, fmaxf(sf[nt][2], sf[nt][3]));
            }
        }
        rmax0 = fmaxf(rmax0, __shfl_xor_sync(0xffffffff, rmax0, 1));
        rmax0 = fmaxf(rmax0, __shfl_xor_sync(0xffffffff, rmax0, 2));
        rmax1 = fmaxf(rmax1, __shfl_xor_sync(0xffffffff, rmax1, 1));
        rmax1 = fmaxf(rmax1, __shfl_xor_sync(0xffffffff, rmax1, 2));

        float mn0 = fmaxf(m0, rmax0);
        float mn1 = fmaxf(m1, rmax1);
        float c0 = fexp2(m0 - mn0);
        float c1 = fexp2(m1 - mn1);
        m0 = mn0; m1 = mn1;

        #pragma unroll
        for (int nt = 0; nt < 8; ++nt) {
            oacc[nt][0] *= c0; oacc[nt][1] *= c0;
            oacc[nt][2] *= c1; oacc[nt][3] *= c1;
        }

        float s0 = 0.f, s1 = 0.f;

        // ---- half 0: exp + P write, PV ----
        #pragma unroll
        for (int q4 = 0; q4 < 4; ++q4) {
            #pragma unroll
            for (int e = 0; e < 4; ++e) {
                float p = fexp2(sf[q4][e] - ((e < 2) ? mn0 : mn1));
                if (e < 2) s0 += p; else s1 += p;
                int jj = 2*t4 + (e & 1);
                int tt = jj & 3, hc = jj >> 2, hr = (e >> 1);
                sPw[(q4*32 + g*4 + tt)*4 + hr + 2*hc] = f2tf32(p);
            }
        }
        __syncwarp();
        #pragma unroll
        for (int s4 = 0; s4 < 4; ++s4) {
            uint4 av = *(const uint4*)&sPw[(s4*32 + lane)*4];
            uint32_t aa[4] = {av.x, av.y, av.z, av.w};
            const uint32_t swg = 16u * ((2*s4 + lg) ^ lr);
            #pragma unroll
            for (int p = 0; p < 4; ++p) {
                uint32_t bq[4];
                LDSM_X4(bq[0],bq[1],bq[2],bq[3], sV + (p*16 + frow)*256 + swg);
                uint32_t be[2] = {bq[0], bq[2]};
                uint32_t bo[2] = {bq[1], bq[3]};
                mma_tf32(oacc[2*p],   aa, be);
                mma_tf32(oacc[2*p+1], aa, bo);
            }
        }
        __syncwarp();

        // ---- half 1: exp + P write ----
        #pragma unroll
        for (int q4 = 0; q4 < 4; ++q4) {
            #pragma unroll
            for (int e = 0; e < 4; ++e) {
                float p = fexp2(sf[4 + q4][e] - ((e < 2) ? mn0 : mn1));
                if (e < 2) s0 += p; else s1 += p;
                int jj = 2*t4 + (e & 1);
                int tt = jj & 3, hc = jj >> 2, hr = (e >> 1);
                sPw[(q4*32 + g*4 + tt)*4 + hr + 2*hc] = f2tf32(p);
            }
        }
        __syncwarp();

        // ---- prefetched S(t+1): sf regs are dead, overwrite them ----
        if (tk + 1 < ntiles) {
            CP_WAIT0();
            __syncthreads();
            do_S((tk + 1) & 1);
        }

        // ---- half 1 PV ----
        #pragma unroll
        for (int s4 = 0; s4 < 4; ++s4) {
            uint4 av = *(const uint4*)&sPw[(s4*32 + lane)*4];
            uint32_t aa[4] = {av.x, av.y, av.z, av.w};
            const int s = 4 + s4;
            const uint32_t swg = 16u * ((2*s + lg) ^ lr);
            #pragma unroll
            for (int p = 0; p < 4; ++p) {
                uint32_t bq[4];
                LDSM_X4(bq[0],bq[1],bq[2],bq[3], sV + (p*16 + frow)*256 + swg);
                uint32_t be[2] = {bq[0], bq[2]};
                uint32_t bo[2] = {bq[1], bq[3]};
                mma_tf32(oacc[2*p],   aa, be);
                mma_tf32(oacc[2*p+1], aa, bo);
            }
        }

        s0 += __shfl_xor_sync(0xffffffff, s0, 1);
        s0 += __shfl_xor_sync(0xffffffff, s0, 2);
        s1 += __shfl_xor_sync(0xffffffff, s1, 1);
        s1 += __shfl_xor_sync(0xffffffff, s1, 2);
        l0 = l0*c0 + s0;
        l1 = l1*c1 + s1;

        __syncthreads();
        if (tk + 2 < ntiles) copy_kv(tk + 2, tk & 1);
        CP_COMMIT();
    }

    const float i0 = 1.f / l0;
    const float i1 = 1.f / l1;
    float* Ob = O + ((size_t)(b*TT))*DM + h*DKH;
    #pragma unroll
    for (int nt = 0; nt < 8; ++nt) {
        int d = nt*8 + 2*t4;
        *(float2*)(Ob + (size_t)qi0*DM + d) = make_float2(oacc[nt][0]*i0, oacc[nt][1]*i0);
        *(float2*)(Ob + (size_t)qi1*DM + d) = make_float2(oacc[nt][2]*i1, oacc[nt][3]*i1);
    }
}

// ===========================================================================
extern "C" void kernel_launch(void* const* d_in, const int* in_sizes, int n_in,
                              void* d_out, int out_size)
{
    const float* q  = (const float*)d_in[0];
    const float* k  = (const float*)d_in[1];
    const float* v  = (const float*)d_in[2];
    const float* wq = (const float*)d_in[4];
    const float* bq = (const float*)d_in[5];
    const float* wk = (const float*)d_in[6];
    const float* bk = (const float*)d_in[7];
    const float* wv = (const float*)d_in[8];
    const float* bv = (const float*)d_in[9];
    const float* wo = (const float*)d_in[10];
    const float* bo = (const float*)d_in[11];
    float* out = (float*)d_out;

    float *gq, *gk, *gvt, *gc, *gwt;
    cudaGetSymbolAddress((void**)&gq, g_Q);
    cudaGetSymbolAddress((void**)&gk, g_K);
    cudaGetSymbolAddress((void**)&gvt, g_VT);
    cudaGetSymbolAddress((void**)&gc, g_C);
    cudaGetSymbolAddress((void**)&gwt, g_WT);
    float* wtq = gwt;
    float* wtk = gwt + (size_t)DM*DM;
    float* wtv = gwt + (size_t)2*DM*DM;
    float* wto = gwt + (size_t)3*DM*DM;

    cudaFuncSetAttribute(attn_tc, cudaFuncAttributeMaxDynamicSharedMemorySize, ATTN_SMEM_TC);
    cudaFuncSetAttribute(gemm_qkv, cudaFuncAttributeMaxDynamicSharedMemorySize, GM_SMEM);
    cudaFuncSetAttribute(gemm_out, cudaFuncAttributeMaxDynamicSharedMemorySize, GM_SMEM);

    dim3 tgrid(DM/32, DM/32, 4);
    transpose_tf32_x4<<<tgrid, 256>>>(wq, wk, wv, wo, wtq, wtk, wtv, wto);

    dim3 qkvgrid(DM/128, MTOK/256, 3);   // (8, 16, 3) = 384 CTAs
    gemm_qkv<<<qkvgrid, 512, GM_SMEM>>>(q, k, v, wtq, wtk, wtv, bq, bk, bv,
                                        gq, gk, gvt);

    dim3 agrid(TT/AQ_ROWS, NH, BB);      // (16, 16, 2)
    attn_tc<<<agrid, 256, ATTN_SMEM_TC>>>(gq, gk, gvt, gc);

    dim3 ogrid(DM/128, MTOK/256);        // (8, 16) = 128 CTAs
    gemm_out<<<ogrid, 512, GM_SMEM>>>(gc, wto, bo, out);
}

// round 11
// speedup vs baseline: 8.1161x; 1.7581x over previous
#include <cuda_runtime.h>
#include <cuda_fp16.h>
#include <cstdint>
#include <math.h>

#define BB   2
#define TT   2048
#define DM   1024
#define NH   16
#define DKH  64
#define MTOK (BB*TT)     // 4096

// Scratch (allocation-free), all fp16 operands
__device__ __half g_QI[MTOK*DM];    // preround of input q
__device__ __half g_KI[MTOK*DM];    // preround of input k
__device__ __half g_VI[MTOK*DM];    // preround of input v
__device__ __half g_Q[MTOK*DM];     // Q proj, prescaled 0.125*log2e
__device__ __half g_K[MTOK*DM];     // K proj
__device__ __half g_VT[DM*MTOK];    // V proj transposed [channel][token]
__device__ __half g_C[MTOK*DM];     // attention output (half)
__device__ __half g_WT[4][DM*DM];   // weights transposed [n][k]

#define LOG2E 1.4426950408889634f

__device__ __forceinline__ uint32_t smem_u32(const void* p) {
    uint32_t a;
    asm("{ .reg .u64 t; cvta.to.shared.u64 t, %1; cvt.u32.u64 %0, t; }" : "=r"(a) : "l"(p));
    return a;
}
__device__ __forceinline__ float fexp2(float x) {
    float y; asm("ex2.approx.f32 %0, %1;" : "=f"(y) : "f"(x)); return y;
}
// pack two floats -> half2 (lo, hi)
__device__ __forceinline__ uint32_t pack_h2(float lo, float hi) {
    uint32_t r;
    asm("cvt.rn.f16x2.f32 %0, %1, %2;" : "=r"(r) : "f"(hi), "f"(lo));
    return r;
}
__device__ __forceinline__ void mma_f16(float* c, const uint32_t* a, const uint32_t* b) {
    asm volatile(
        "mma.sync.aligned.m16n8k16.row.col.f32.f16.f16.f32 "
        "{%0,%1,%2,%3}, {%4,%5,%6,%7}, {%8,%9}, {%0,%1,%2,%3};"
        : "+f"(c[0]), "+f"(c[1]), "+f"(c[2]), "+f"(c[3])
        : "r"(a[0]), "r"(a[1]), "r"(a[2]), "r"(a[3]), "r"(b[0]), "r"(b[1]));
}
#define LDSM_X4(r0,r1,r2,r3,addr) \
    asm volatile("ldmatrix.sync.aligned.m8n8.x4.shared.b16 {%0,%1,%2,%3}, [%4];" \
        : "=r"(r0), "=r"(r1), "=r"(r2), "=r"(r3) : "r"(addr))
#define CP_ASYNC16(dst, src) \
    asm volatile("cp.async.cg.shared.global [%0], [%1], 16;" :: "r"(dst), "l"(src))
#define CP_COMMIT()  asm volatile("cp.async.commit_group;" ::: "memory")
#define CP_WAIT2()   asm volatile("cp.async.wait_group 2;" ::: "memory")
#define CP_WAIT1()   asm volatile("cp.async.wait_group 1;" ::: "memory")

// ===========================================================================
// Weight transpose + fp16 convert: out[n*K+k] = half(in[k*N+n])
// ===========================================================================
__global__ __launch_bounds__(256) void transpose_h_x4(
    const float* __restrict__ w0, const float* __restrict__ w1,
    const float* __restrict__ w2, const float* __restrict__ w3,
    __half* __restrict__ o0, __half* __restrict__ o1,
    __half* __restrict__ o2, __half* __restrict__ o3)
{
    const float* in  = (blockIdx.z == 0) ? w0 : (blockIdx.z == 1) ? w1 :
                       (blockIdx.z == 2) ? w2 : w3;
    __half*      out = (blockIdx.z == 0) ? o0 : (blockIdx.z == 1) ? o1 :
                       (blockIdx.z == 2) ? o2 : o3;
    __shared__ float t[32][33];
    int tx = threadIdx.x & 31;
    int ty = threadIdx.x >> 5;
    int x  = blockIdx.x*32 + tx;
    int y0 = blockIdx.y*32;
    #pragma unroll
    for (int j = ty; j < 32; j += 8) t[j][tx] = in[(size_t)(y0+j)*DM + x];
    __syncthreads();
    int xo  = y0 + tx;
    int yo0 = blockIdx.x*32;
    #pragma unroll
    for (int j = ty; j < 32; j += 8)
        out[(size_t)(yo0+j)*DM + xo] = __float2half_rn(t[tx][j]);
}

// ===========================================================================
// Elementwise fp32 -> fp16 preround for q,k,v inputs (z selects)
// ===========================================================================
__global__ __launch_bounds__(256) void preround_h(
    const float* __restrict__ q, const float* __restrict__ k,
    const float* __restrict__ v,
    __half* __restrict__ oq, __half* __restrict__ ok, __half* __restrict__ ov)
{
    const float* in = (blockIdx.z == 0) ? q : (blockIdx.z == 1) ? k : v;
    __half*     out = (blockIdx.z == 0) ? oq : (blockIdx.z == 1) ? ok : ov;
    int idx = blockIdx.x*256 + threadIdx.x;       // one float4 per thread
    float4 f = ((const float4*)in)[idx];
    uint2 u;
    u.x = pack_h2(f.x, f.y);
    u.y = pack_h2(f.z, f.w);
    ((uint2*)out)[idx] = u;
}

// ===========================================================================
// fp16 GEMM core: 256(M) x 128(N) CTA tile, 512 threads (16 warps, 8m x 2n),
// K-chunk 64 halves (128B rows), 4-stage cp.async, NCH = 16.
// mode 0: fp32 out; mode 1: half(x*scl); mode 2: transposed half out
// ===========================================================================
#define NCH      16
#define STG_B    49152                // A 32KB + B 16KB
#define GM_SMEM  (4*STG_B)            // 192 KB

__device__ __forceinline__ void gemm_core(
    const __half* __restrict__ A, const __half* __restrict__ WT,
    const float* __restrict__ bias, void* __restrict__ Cv,
    float scl, int mode, char* dsm)
{
    const uint32_t smb = smem_u32(dsm);

    const int tid  = threadIdx.x;
    const int wid  = tid >> 5;
    const int lane = tid & 31;
    const int wm   = wid >> 1;
    const int wn   = wid & 1;
    const int g    = lane >> 2;
    const int t    = lane & 3;
    const int rowBase = blockIdx.y * 256;
    const int colBase = blockIdx.x * 128;

    const int lr = lane & 7;
    const int lh = (lane >> 3) & 1;
    const int lg = lane >> 4;
    const int rowA0 = wm*32 + lr + 8*lh;
    const int rowB0 = wn*64 + lr + 8*lh;

    float acc[2][8][4];
    #pragma unroll
    for (int i = 0; i < 2; ++i)
        #pragma unroll
        for (int j = 0; j < 8; ++j)
            #pragma unroll
            for (int e = 0; e < 4; ++e) acc[i][j][e] = 0.f;

    auto copy_chunk = [&](int c, int stage) {
        const int k0 = c * 64;                  // halves
        const uint32_t sb = smb + stage*STG_B;
        // A: 256 rows x 8 granules = 2048, 4 per thread
        #pragma unroll
        for (int i = 0; i < 4; ++i) {
            int idx = tid + i*512;
            int row = idx >> 3;
            int gg  = idx & 7;
            uint32_t dst = sb + row*128 + 16*(gg ^ (row & 7));
            CP_ASYNC16(dst, A + (size_t)(rowBase+row)*DM + k0 + gg*8);
        }
        // B: 128 rows x 8 granules = 1024, 2 per thread
        #pragma unroll
        for (int i = 0; i < 2; ++i) {
            int idx = tid + i*512;
            int row = idx >> 3;
            int gg  = idx & 7;
            uint32_t dst = sb + 32768 + row*128 + 16*(gg ^ (row & 7));
            CP_ASYNC16(dst, WT + (size_t)(colBase+row)*DM + k0 + gg*8);
        }
    };

    auto compute = [&](int stage) {
        const uint32_t sa  = smb + stage*STG_B;
        const uint32_t sbB = sa + 32768;
        #pragma unroll
        for (int ks = 0; ks < 4; ++ks) {        // k16 steps
            const uint32_t swg = 16u * ((2*ks + lg) ^ lr);
            uint32_t a0[4], a1[4];
            LDSM_X4(a0[0],a0[1],a0[2],a0[3], sa + (rowA0     )*128 + swg);
            LDSM_X4(a1[0],a1[1],a1[2],a1[3], sa + (rowA0 + 16)*128 + swg);
            #pragma unroll
            for (int p = 0; p < 4; ++p) {
                uint32_t bq[4];
                LDSM_X4(bq[0],bq[1],bq[2],bq[3], sbB + (rowB0 + p*16)*128 + swg);
                uint32_t be[2] = {bq[0], bq[2]};
                uint32_t bo[2] = {bq[1], bq[3]};
                mma_f16(acc[0][2*p],   a0, be);
                mma_f16(acc[1][2*p],   a1, be);
                mma_f16(acc[0][2*p+1], a0, bo);
                mma_f16(acc[1][2*p+1], a1, bo);
            }
        }
    };

    copy_chunk(0, 0); CP_COMMIT();
    copy_chunk(1, 1); CP_COMMIT();
    copy_chunk(2, 2); CP_COMMIT();

    for (int c = 0; c < NCH; ++c) {
        CP_WAIT2();
        __syncthreads();
        if (c + 3 < NCH) copy_chunk(c + 3, (c + 3) & 3);
        CP_COMMIT();
        compute(c & 3);
    }

    #pragma unroll
    for (int mt = 0; mt < 2; ++mt) {
        int r0 = rowBase + wm*32 + mt*16 + g;
        #pragma unroll
        for (int nt = 0; nt < 8; ++nt) {
            int col = colBase + wn*64 + nt*8 + 2*t;
            float b0 = bias[col], b1 = bias[col+1];
            float v00 = acc[mt][nt][0] + b0, v01 = acc[mt][nt][1] + b1;
            float v10 = acc[mt][nt][2] + b0, v11 = acc[mt][nt][3] + b1;
            if (mode == 0) {
                float* C = (float*)Cv;
                *(float2*)(C + (size_t)r0*DM + col)     = make_float2(v00, v01);
                *(float2*)(C + (size_t)(r0+8)*DM + col) = make_float2(v10, v11);
            } else if (mode == 1) {
                __half* C = (__half*)Cv;
                *(uint32_t*)(C + (size_t)r0*DM + col)     = pack_h2(v00*scl, v01*scl);
                *(uint32_t*)(C + (size_t)(r0+8)*DM + col) = pack_h2(v10*scl, v11*scl);
            } else {
                __half* C = (__half*)Cv;
                C[(size_t)col*MTOK + r0]         = __float2half_rn(v00);
                C[(size_t)(col+1)*MTOK + r0]     = __float2half_rn(v01);
                C[(size_t)col*MTOK + r0 + 8]     = __float2half_rn(v10);
                C[(size_t)(col+1)*MTOK + r0 + 8] = __float2half_rn(v11);
            }
        }
    }
}

__global__ __launch_bounds__(512, 1) void gemm_qkv(
    const __half* __restrict__ qi, const __half* __restrict__ ki, const __half* __restrict__ vi,
    const __half* __restrict__ wtq, const __half* __restrict__ wtk, const __half* __restrict__ wtv,
    const float* __restrict__ bq, const float* __restrict__ bk, const float* __restrict__ bv,
    __half* __restrict__ oq, __half* __restrict__ ok, __half* __restrict__ ovt)
{
    extern __shared__ char dsm[];
    const int z = blockIdx.z;
    const __half* A  = (z == 0) ? qi  : (z == 1) ? ki  : vi;
    const __half* WT = (z == 0) ? wtq : (z == 1) ? wtk : wtv;
    const float*  bb = (z == 0) ? bq  : (z == 1) ? bk  : bv;
    __half*       C  = (z == 0) ? oq  : (z == 1) ? ok  : ovt;
    float scl = (z == 0) ? 0.125f * LOG2E : 1.0f;
    int mode  = (z == 2) ? 2 : 1;
    gemm_core(A, WT, bb, C, scl, mode, dsm);
}

__global__ __launch_bounds__(512, 1) void gemm_out(
    const __half* __restrict__ A, const __half* __restrict__ WT,
    const float* __restrict__ bias, float* __restrict__ C)
{
    extern __shared__ char dsm[];
    gemm_core(A, WT, bias, C, 1.0f, 0, dsm);
}

// ===========================================================================
// fp16 tensor-core causal flash attention: P stays in registers (FA2 layout
// identity: S C-frag == PV A-frag for m16n8k16). No P smem, no cvt chains.
// CTA: 128 q-rows x 1 head, 8 warps x 16 rows. KV tile 64 keys.
// smem (48KB): [0,16K) Q; [16K + st*16K) st=0,1: K 8KB + VT 8KB
// ===========================================================================
#define AQ_ROWS 128
#define AKV     64
#define AOFF_KV 16384
#define ATTN_SMEM_TC (AOFF_KV + 2*16384)   // 48 KB

__global__ __launch_bounds__(256, 2) void attn_tc(
    const __half* __restrict__ Q, const __half* __restrict__ K,
    const __half* __restrict__ VT, __half* __restrict__ O)
{
    extern __shared__ char smraw[];
    const uint32_t smb = smem_u32(smraw);

    const int tid  = threadIdx.x;
    const int wid  = tid >> 5;
    const int lane = tid & 31;
    const int g    = lane >> 2;
    const int t4   = lane & 3;
    const int lr   = lane & 7;
    const int lh   = (lane >> 3) & 1;
    const int lg   = lane >> 4;
    const int h    = blockIdx.y;
    const int b    = blockIdx.z;
    const int q0   = (gridDim.x - 1 - blockIdx.x) * AQ_ROWS;  // longest first

    const int qi0 = q0 + wid*16 + g;
    const int qi1 = qi0 + 8;

    const __half* Qb  = Q + ((size_t)(b*TT))*DM + h*DKH;
    const __half* Kb  = K + ((size_t)(b*TT))*DM + h*DKH;
    const __half* VTb = VT + (size_t)(h*DKH)*MTOK + b*TT;

    const int ntiles = q0/AKV + 2;

    auto copy_kv = [&](int tile, int st) {
        const int k0 = tile * AKV;
        const uint32_t base = smb + AOFF_KV + st*16384;
        #pragma unroll
        for (int i = 0; i < 2; ++i) {           // K: 64 rows x 8 granules
            int idx = tid + i*256;
            int row = idx >> 3;
            int gg  = idx & 7;
            uint32_t dst = base + row*128 + 16*(gg ^ (row & 7));
            CP_ASYNC16(dst, Kb + (size_t)(k0+row)*DM + gg*8);
        }
        #pragma unroll
        for (int i = 0; i < 2; ++i) {           // VT: 64 d-rows x 8 granules
            int idx = tid + i*256;
            int row = idx >> 3;
            int gg  = idx & 7;
            uint32_t dst = base + 8192 + row*128 + 16*(gg ^ (row & 7));
            CP_ASYNC16(dst, VTb + (size_t)row*MTOK + k0 + gg*8);
        }
    };

    // ---- prologue: Q staging + first 2 KV tiles ----
    #pragma unroll
    for (int i = 0; i < 4; ++i) {               // Q: 128 rows x 8 granules
        int idx = tid + i*256;
        int row = idx >> 3;
        int gg  = idx & 7;
        uint32_t dst = smb + row*128 + 16*(gg ^ (row & 7));
        CP_ASYNC16(dst, Qb + (size_t)(q0+row)*DM + gg*8);
    }
    copy_kv(0, 0); CP_COMMIT();
    copy_kv(1, 1); CP_COMMIT();

    float oacc[8][4];
    #pragma unroll
    for (int nt = 0; nt < 8; ++nt)
        #pragma unroll
        for (int e = 0; e < 4; ++e) oacc[nt][e] = 0.f;
    float m0 = -1e30f, m1 = -1e30f, l0 = 0.f, l1 = 0.f;

    const int frow = lr + 8*lh;
    const int qrow = wid*16 + frow;

    for (int tk = 0; tk < ntiles; ++tk) {
        CP_WAIT1();
        __syncthreads();
        const uint32_t sK = smb + AOFF_KV + (tk & 1)*16384;
        const uint32_t sV = sK + 8192;

        // ---- S = Q @ K^T (scale+log2e folded into Q) ----
        float sf[8][4];
        #pragma unroll
        for (int nt = 0; nt < 8; ++nt)
            #pragma unroll
            for (int e = 0; e < 4; ++e) sf[nt][e] = 0.f;
        #pragma unroll
        for (int ks = 0; ks < 4; ++ks) {
            const uint32_t swg = 16u * ((2*ks + lg) ^ lr);
            uint32_t qa[4];
            LDSM_X4(qa[0], qa[1], qa[2], qa[3], smb + qrow*128 + swg);
            #pragma unroll
            for (int p = 0; p < 4; ++p) {
                uint32_t bq[4];
                LDSM_X4(bq[0],bq[1],bq[2],bq[3], sK + (p*16 + frow)*128 + swg);
                uint32_t be[2] = {bq[0], bq[2]};
                uint32_t bo[2] = {bq[1], bq[3]};
                mma_f16(sf[2*p],   qa, be);
                mma_f16(sf[2*p+1], qa, bo);
            }
        }

        // ---- causal mask (diagonal tiles only) + row max ----
        float rmax0 = -1e30f, rmax1 = -1e30f;
        if (tk >= ntiles - 2) {
            const int k0 = tk * AKV;
            #pragma unroll
            for (int nt = 0; nt < 8; ++nt) {
                int jb = k0 + nt*8 + 2*t4;
                #pragma unroll
                for (int e = 0; e < 4; ++e) {
                    int j = jb + (e & 1);
                    float v = sf[nt][e];
                    int qr = (e < 2) ? qi0 : qi1;
                    v = (j > qr) ? -1e30f : v;
                    sf[nt][e] = v;
                    if (e < 2) rmax0 = fmaxf(rmax0, v);
                    else       rmax1 = fmaxf(rmax1, v);
                }
            }
        } else {
            #pragma unroll
            for (int nt = 0; nt < 8; ++nt) {
                rmax0 = fmaxf(rmax0, fmaxf(sf[nt][0], sf[nt][1]));
                rmax1 = fmaxf(rmax1, fmaxf(sf[nt][2], sf[nt][3]));
            }
        }
        rmax0 = fmaxf(rmax0, __shfl_xor_sync(0xffffffff, rmax0, 1));
        rmax0 = fmaxf(rmax0, __shfl_xor_sync(0xffffffff, rmax0, 2));
        rmax1 = fmaxf(rmax1, __shfl_xor_sync(0xffffffff, rmax1, 1));
        rmax1 = fmaxf(rmax1, __shfl_xor_sync(0xffffffff, rmax1, 2));

        float mn0 = fmaxf(m0, rmax0);
        float mn1 = fmaxf(m1, rmax1);
        float c0 = fexp2(m0 - mn0);
        float c1 = fexp2(m1 - mn1);
        m0 = mn0; m1 = mn1;

        #pragma unroll
        for (int nt = 0; nt < 8; ++nt) {
            oacc[nt][0] *= c0; oacc[nt][1] *= c0;
            oacc[nt][2] *= c1; oacc[nt][3] *= c1;
        }

        // ---- exp -> P directly as PV A-fragments (no smem) ----
        float s0 = 0.f, s1 = 0.f;
        uint32_t pa[4][4];
        #pragma unroll
        for (int s = 0; s < 4; ++s) {
            float e00 = fexp2(sf[2*s  ][0] - mn0), e01 = fexp2(sf[2*s  ][1] - mn0);
            float e02 = fexp2(sf[2*s  ][2] - mn1), e03 = fexp2(sf[2*s  ][3] - mn1);
            float e10 = fexp2(sf[2*s+1][0] - mn0), e11 = fexp2(sf[2*s+1][1] - mn0);
            float e12 = fexp2(sf[2*s+1][2] - mn1), e13 = fexp2(sf[2*s+1][3] - mn1);
            s0 += (e00 + e01) + (e10 + e11);
            s1 += (e02 + e03) + (e12 + e13);
            pa[s][0] = pack_h2(e00, e01);    // (r,   k=16s+2t..+1)
            pa[s][1] = pack_h2(e02, e03);    // (r+8, k lo)
            pa[s][2] = pack_h2(e10, e11);    // (r,   k hi)
            pa[s][3] = pack_h2(e12, e13);    // (r+8, k hi)
        }
        s0 += __shfl_xor_sync(0xffffffff, s0, 1);
        s0 += __shfl_xor_sync(0xffffffff, s0, 2);
        s1 += __shfl_xor_sync(0xffffffff, s1, 1);
        s1 += __shfl_xor_sync(0xffffffff, s1, 2);
        l0 = l0*c0 + s0;
        l1 = l1*c1 + s1;

        // ---- O += P @ V ----
        #pragma unroll
        for (int s = 0; s < 4; ++s) {
            const uint32_t swg = 16u * ((2*s + lg) ^ lr);
            #pragma unroll
            for (int p = 0; p < 4; ++p) {
                uint32_t bq[4];
                LDSM_X4(bq[0],bq[1],bq[2],bq[3], sV + (p*16 + frow)*128 + swg);
                uint32_t be[2] = {bq[0], bq[2]};
                uint32_t bo[2] = {bq[1], bq[3]};
                mma_f16(oacc[2*p],   pa[s], be);
                mma_f16(oacc[2*p+1], pa[s], bo);
            }
        }

        __syncthreads();
        if (tk + 2 < ntiles) copy_kv(tk + 2, tk & 1);
        CP_COMMIT();
    }

    // ---- epilogue: write half C ----
    const float i0 = 1.f / l0;
    const float i1 = 1.f / l1;
    __half* Ob = O + ((size_t)(b*TT))*DM + h*DKH;
    #pragma unroll
    for (int nt = 0; nt < 8; ++nt) {
        int d = nt*8 + 2*t4;
        *(uint32_t*)(Ob + (size_t)qi0*DM + d) = pack_h2(oacc[nt][0]*i0, oacc[nt][1]*i0);
        *(uint32_t*)(Ob + (size_t)qi1*DM + d) = pack_h2(oacc[nt][2]*i1, oacc[nt][3]*i1);
    }
}

// ===========================================================================
extern "C" void kernel_launch(void* const* d_in, const int* in_sizes, int n_in,
                              void* d_out, int out_size)
{
    const float* q  = (const float*)d_in[0];
    const float* k  = (const float*)d_in[1];
    const float* v  = (const float*)d_in[2];
    const float* wq = (const float*)d_in[4];
    const float* bq = (const float*)d_in[5];
    const float* wk = (const float*)d_in[6];
    const float* bk = (const float*)d_in[7];
    const float* wv = (const float*)d_in[8];
    const float* bv = (const float*)d_in[9];
    const float* wo = (const float*)d_in[10];
    const float* bo = (const float*)d_in[11];
    float* out = (float*)d_out;

    __half *gqi, *gki, *gvi, *gq, *gk, *gvt, *gc, *gwt;
    cudaGetSymbolAddress((void**)&gqi, g_QI);
    cudaGetSymbolAddress((void**)&gki, g_KI);
    cudaGetSymbolAddress((void**)&gvi, g_VI);
    cudaGetSymbolAddress((void**)&gq,  g_Q);
    cudaGetSymbolAddress((void**)&gk,  g_K);
    cudaGetSymbolAddress((void**)&gvt, g_VT);
    cudaGetSymbolAddress((void**)&gc,  g_C);
    cudaGetSymbolAddress((void**)&gwt, g_WT);
    __half* wtq = gwt;
    __half* wtk = gwt + (size_t)DM*DM;
    __half* wtv = gwt + (size_t)2*DM*DM;
    __half* wto = gwt + (size_t)3*DM*DM;

    cudaFuncSetAttribute(attn_tc, cudaFuncAttributeMaxDynamicSharedMemorySize, ATTN_SMEM_TC);
    cudaFuncSetAttribute(gemm_qkv, cudaFuncAttributeMaxDynamicSharedMemorySize, GM_SMEM);
    cudaFuncSetAttribute(gemm_out, cudaFuncAttributeMaxDynamicSharedMemorySize, GM_SMEM);

    dim3 tgrid(DM/32, DM/32, 4);
    transpose_h_x4<<<tgrid, 256>>>(wq, wk, wv, wo, wtq, wtk, wtv, wto);

    dim3 pgrid(MTOK*DM/4/256, 1, 3);     // (4096, 1, 3)
    preround_h<<<pgrid, 256>>>(q, k, v, gqi, gki, gvi);

    dim3 qkvgrid(DM/128, MTOK/256, 3);   // (8, 16, 3) = 384 CTAs
    gemm_qkv<<<qkvgrid, 512, GM_SMEM>>>(gqi, gki, gvi, wtq, wtk, wtv,
                                        bq, bk, bv, gq, gk, gvt);

    dim3 agrid(TT/AQ_ROWS, NH, BB);      // (16, 16, 2)
    attn_tc<<<agrid, 256, ATTN_SMEM_TC>>>(gq, gk, gvt, gc);

    dim3 ogrid(DM/128, MTOK/256);        // (8, 16) = 128 CTAs
    gemm_out<<<ogrid, 512, GM_SMEM>>>(gc, wto, bo, out);
}

// round 13
// speedup vs baseline: 8.5143x; 1.0491x over previous
#include <cuda_runtime.h>
#include <cuda_fp16.h>
#include <cstdint>
#include <math.h>

#define BB   2
#define TT   2048
#define DM   1024
#define NH   16
#define DKH  64
#define MTOK (BB*TT)     // 4096

// Scratch (allocation-free), all fp16 operands
__device__ __half g_QI[MTOK*DM];
__device__ __half g_KI[MTOK*DM];
__device__ __half g_VI[MTOK*DM];
__device__ __half g_Q[MTOK*DM];     // Q proj, prescaled 0.125*log2e
__device__ __half g_K[MTOK*DM];
__device__ __half g_VT[DM*MTOK];    // V proj transposed [channel][token]
__device__ __half g_C[MTOK*DM];
__device__ __half g_WT[4][DM*DM];   // weights transposed [n][k]

#define LOG2E 1.4426950408889634f

__device__ __forceinline__ uint32_t smem_u32(const void* p) {
    uint32_t a;
    asm("{ .reg .u64 t; cvta.to.shared.u64 t, %1; cvt.u32.u64 %0, t; }" : "=r"(a) : "l"(p));
    return a;
}
__device__ __forceinline__ float fexp2(float x) {
    float y; asm("ex2.approx.f32 %0, %1;" : "=f"(y) : "f"(x)); return y;
}
__device__ __forceinline__ uint32_t pack_h2(float lo, float hi) {
    uint32_t r;
    asm("cvt.rn.f16x2.f32 %0, %1, %2;" : "=r"(r) : "f"(hi), "f"(lo));
    return r;
}
__device__ __forceinline__ void mma_f16(float* c, const uint32_t* a, const uint32_t* b) {
    asm volatile(
        "mma.sync.aligned.m16n8k16.row.col.f32.f16.f16.f32 "
        "{%0,%1,%2,%3}, {%4,%5,%6,%7}, {%8,%9}, {%0,%1,%2,%3};"
        : "+f"(c[0]), "+f"(c[1]), "+f"(c[2]), "+f"(c[3])
        : "r"(a[0]), "r"(a[1]), "r"(a[2]), "r"(a[3]), "r"(b[0]), "r"(b[1]));
}
#define LDSM_X4(r0,r1,r2,r3,addr) \
    asm volatile("ldmatrix.sync.aligned.m8n8.x4.shared.b16 {%0,%1,%2,%3}, [%4];" \
        : "=r"(r0), "=r"(r1), "=r"(r2), "=r"(r3) : "r"(addr))
#define CP_ASYNC16(dst, src) \
    asm volatile("cp.async.cg.shared.global [%0], [%1], 16;" :: "r"(dst), "l"(src))
#define CP_COMMIT()  asm volatile("cp.async.commit_group;" ::: "memory")
#define CP_WAIT2()   asm volatile("cp.async.wait_group 2;" ::: "memory")
#define CP_WAIT1()   asm volatile("cp.async.wait_group 1;" ::: "memory")

// ===========================================================================
// Weight transpose + fp16 convert: out[n*K+k] = half(in[k*N+n])
// ===========================================================================
__global__ __launch_bounds__(256) void transpose_h_x4(
    const float* __restrict__ w0, const float* __restrict__ w1,
    const float* __restrict__ w2, const float* __restrict__ w3,
    __half* __restrict__ o0, __half* __restrict__ o1,
    __half* __restrict__ o2, __half* __restrict__ o3)
{
    const float* in  = (blockIdx.z == 0) ? w0 : (blockIdx.z == 1) ? w1 :
                       (blockIdx.z == 2) ? w2 : w3;
    __half*      out = (blockIdx.z == 0) ? o0 : (blockIdx.z == 1) ? o1 :
                       (blockIdx.z == 2) ? o2 : o3;
    __shared__ float t[32][33];
    int tx = threadIdx.x & 31;
    int ty = threadIdx.x >> 5;
    int x  = blockIdx.x*32 + tx;
    int y0 = blockIdx.y*32;
    #pragma unroll
    for (int j = ty; j < 32; j += 8) t[j][tx] = in[(size_t)(y0+j)*DM + x];
    __syncthreads();
    int xo  = y0 + tx;
    int yo0 = blockIdx.x*32;
    #pragma unroll
    for (int j = ty; j < 32; j += 8)
        out[(size_t)(yo0+j)*DM + xo] = __float2half_rn(t[tx][j]);
}

// ===========================================================================
// Elementwise fp32 -> fp16 preround for q,k,v inputs
// ===========================================================================
__global__ __launch_bounds__(256) void preround_h(
    const float* __restrict__ q, const float* __restrict__ k,
    const float* __restrict__ v,
    __half* __restrict__ oq, __half* __restrict__ ok, __half* __restrict__ ov)
{
    const float* in = (blockIdx.z == 0) ? q : (blockIdx.z == 1) ? k : v;
    __half*     out = (blockIdx.z == 0) ? oq : (blockIdx.z == 1) ? ok : ov;
    int idx = blockIdx.x*256 + threadIdx.x;
    float4 f = ((const float4*)in)[idx];
    uint2 u;
    u.x = pack_h2(f.x, f.y);
    u.y = pack_h2(f.z, f.w);
    ((uint2*)out)[idx] = u;
}

// ===========================================================================
// fp16 GEMM core: 128(M) x 128(N) CTA tile, 256 threads (8 warps, 4m x 2n),
// K-chunk 64 halves (128B rows), 3-stage cp.async, 2 CTAs/SM.
// Loop order: compute(c) -> barrier -> copy(c+3) into freed stage (NO race).
// mode 0: fp32 out; mode 1: half(x*scl); mode 2: transposed half out
// ===========================================================================
#define NCH      16
#define STG_B    32768                // A 16KB + B 16KB
#define GM_SMEM  (3*STG_B)            // 96 KB -> 2 CTAs/SM

__device__ __forceinline__ void gemm_core(
    const __half* __restrict__ A, const __half* __restrict__ WT,
    const float* __restrict__ bias, void* __restrict__ Cv,
    float scl, int mode, char* dsm)
{
    const uint32_t smb = smem_u32(dsm);

    const int tid  = threadIdx.x;
    const int wid  = tid >> 5;
    const int lane = tid & 31;
    const int wm   = wid >> 1;           // 0..3
    const int wn   = wid & 1;            // 0..1
    const int g    = lane >> 2;
    const int t    = lane & 3;
    const int rowBase = blockIdx.y * 128;
    const int colBase = blockIdx.x * 128;

    const int lr = lane & 7;
    const int lh = (lane >> 3) & 1;
    const int lg = lane >> 4;
    const int rowA0 = wm*32 + lr + 8*lh;
    const int rowB0 = wn*64 + lr + 8*lh;

    float acc[2][8][4];
    #pragma unroll
    for (int i = 0; i < 2; ++i)
        #pragma unroll
        for (int j = 0; j < 8; ++j)
            #pragma unroll
            for (int e = 0; e < 4; ++e) acc[i][j][e] = 0.f;

    auto copy_chunk = [&](int c, int stage) {
        const int k0 = c * 64;
        const uint32_t sb = smb + stage*STG_B;
        #pragma unroll
        for (int i = 0; i < 4; ++i) {        // A: 128 rows x 8 granules
            int idx = tid + i*256;
            int row = idx >> 3;
            int gg  = idx & 7;
            uint32_t dst = sb + row*128 + 16*(gg ^ (row & 7));
            CP_ASYNC16(dst, A + (size_t)(rowBase+row)*DM + k0 + gg*8);
        }
        #pragma unroll
        for (int i = 0; i < 4; ++i) {        // B: 128 rows x 8 granules
            int idx = tid + i*256;
            int row = idx >> 3;
            int gg  = idx & 7;
            uint32_t dst = sb + 16384 + row*128 + 16*(gg ^ (row & 7));
            CP_ASYNC16(dst, WT + (size_t)(colBase+row)*DM + k0 + gg*8);
        }
    };

    auto compute = [&](int stage) {
        const uint32_t sa  = smb + stage*STG_B;
        const uint32_t sbB = sa + 16384;
        #pragma unroll
        for (int ks = 0; ks < 4; ++ks) {
            const uint32_t swg = 16u * ((2*ks + lg) ^ lr);
            uint32_t a0[4], a1[4];
            LDSM_X4(a0[0],a0[1],a0[2],a0[3], sa + (rowA0     )*128 + swg);
            LDSM_X4(a1[0],a1[1],a1[2],a1[3], sa + (rowA0 + 16)*128 + swg);
            #pragma unroll
            for (int p = 0; p < 4; ++p) {
                uint32_t bq[4];
                LDSM_X4(bq[0],bq[1],bq[2],bq[3], sbB + (rowB0 + p*16)*128 + swg);
                uint32_t be[2] = {bq[0], bq[2]};
                uint32_t bo[2] = {bq[1], bq[3]};
                mma_f16(acc[0][2*p],   a0, be);
                mma_f16(acc[1][2*p],   a1, be);
                mma_f16(acc[0][2*p+1], a0, bo);
                mma_f16(acc[1][2*p+1], a1, bo);
            }
        }
    };

    copy_chunk(0, 0); CP_COMMIT();
    copy_chunk(1, 1); CP_COMMIT();
    copy_chunk(2, 2); CP_COMMIT();

    for (int c = 0; c < NCH; ++c) {
        CP_WAIT2();
        __syncthreads();                 // chunk c resident in stage c%3
        compute(c % 3);
        __syncthreads();                 // stage c%3 fully consumed
        if (c + 3 < NCH) copy_chunk(c + 3, c % 3);
        CP_COMMIT();
    }

    #pragma unroll
    for (int mt = 0; mt < 2; ++mt) {
        int r0 = rowBase + wm*32 + mt*16 + g;
        #pragma unroll
        for (int nt = 0; nt < 8; ++nt) {
            int col = colBase + wn*64 + nt*8 + 2*t;
            float b0 = bias[col], b1 = bias[col+1];
            float v00 = acc[mt][nt][0] + b0, v01 = acc[mt][nt][1] + b1;
            float v10 = acc[mt][nt][2] + b0, v11 = acc[mt][nt][3] + b1;
            if (mode == 0) {
                float* C = (float*)Cv;
                *(float2*)(C + (size_t)r0*DM + col)     = make_float2(v00, v01);
                *(float2*)(C + (size_t)(r0+8)*DM + col) = make_float2(v10, v11);
            } else if (mode == 1) {
                __half* C = (__half*)Cv;
                *(uint32_t*)(C + (size_t)r0*DM + col)     = pack_h2(v00*scl, v01*scl);
                *(uint32_t*)(C + (size_t)(r0+8)*DM + col) = pack_h2(v10*scl, v11*scl);
            } else {
                __half* C = (__half*)Cv;
                C[(size_t)col*MTOK + r0]         = __float2half_rn(v00);
                C[(size_t)(col+1)*MTOK + r0]     = __float2half_rn(v01);
                C[(size_t)col*MTOK + r0 + 8]     = __float2half_rn(v10);
                C[(size_t)(col+1)*MTOK + r0 + 8] = __float2half_rn(v11);
            }
        }
    }
}

__global__ __launch_bounds__(256, 2) void gemm_qkv(
    const __half* __restrict__ qi, const __half* __restrict__ ki, const __half* __restrict__ vi,
    const __half* __restrict__ wtq, const __half* __restrict__ wtk, const __half* __restrict__ wtv,
    const float* __restrict__ bq, const float* __restrict__ bk, const float* __restrict__ bv,
    __half* __restrict__ oq, __half* __restrict__ ok, __half* __restrict__ ovt)
{
    extern __shared__ char dsm[];
    const int z = blockIdx.z;
    const __half* A  = (z == 0) ? qi  : (z == 1) ? ki  : vi;
    const __half* WT = (z == 0) ? wtq : (z == 1) ? wtk : wtv;
    const float*  bb = (z == 0) ? bq  : (z == 1) ? bk  : bv;
    __half*       C  = (z == 0) ? oq  : (z == 1) ? ok  : ovt;
    float scl = (z == 0) ? 0.125f * LOG2E : 1.0f;
    int mode  = (z == 2) ? 2 : 1;
    gemm_core(A, WT, bb, C, scl, mode, dsm);
}

__global__ __launch_bounds__(256, 2) void gemm_out(
    const __half* __restrict__ A, const __half* __restrict__ WT,
    const float* __restrict__ bias, float* __restrict__ C)
{
    extern __shared__ char dsm[];
    gemm_core(A, WT, bias, C, 1.0f, 0, dsm);
}

// ===========================================================================
// fp16 tensor-core causal flash attention: 64 q-rows per CTA, 4 warps,
// 4 CTAs/SM. P stays in registers (FA2 fragment identity). KV tile 64 keys.
// smem (40KB): [0,8K) Q; [8K + st*16K) st=0,1: K 8KB + VT 8KB
// ===========================================================================
#define AQ_ROWS 64
#define AKV     64
#define AOFF_KV 8192
#define ATTN_SMEM_TC (AOFF_KV + 2*16384)   // 40 KB

__global__ __launch_bounds__(128, 4) void attn_tc(
    const __half* __restrict__ Q, const __half* __restrict__ K,
    const __half* __restrict__ VT, __half* __restrict__ O)
{
    extern __shared__ char smraw[];
    const uint32_t smb = smem_u32(smraw);

    const int tid  = threadIdx.x;
    const int wid  = tid >> 5;            // 0..3
    const int lane = tid & 31;
    const int g    = lane >> 2;
    const int t4   = lane & 3;
    const int lr   = lane & 7;
    const int lh   = (lane >> 3) & 1;
    const int lg   = lane >> 4;
    const int h    = blockIdx.y;
    const int b    = blockIdx.z;
    const int q0   = (gridDim.x - 1 - blockIdx.x) * AQ_ROWS;  // longest first

    const int qi0 = q0 + wid*16 + g;
    const int qi1 = qi0 + 8;

    const __half* Qb  = Q + ((size_t)(b*TT))*DM + h*DKH;
    const __half* Kb  = K + ((size_t)(b*TT))*DM + h*DKH;
    const __half* VTb = VT + (size_t)(h*DKH)*MTOK + b*TT;

    const int ntiles = q0/AKV + 1;

    auto copy_kv = [&](int tile, int st) {
        const int k0 = tile * AKV;
        const uint32_t base = smb + AOFF_KV + st*16384;
        #pragma unroll
        for (int i = 0; i < 4; ++i) {           // K: 64 rows x 8 granules
            int idx = tid + i*128;
            int row = idx >> 3;
            int gg  = idx & 7;
            uint32_t dst = base + row*128 + 16*(gg ^ (row & 7));
            CP_ASYNC16(dst, Kb + (size_t)(k0+row)*DM + gg*8);
        }
        #pragma unroll
        for (int i = 0; i < 4; ++i) {           // VT: 64 d-rows x 8 granules
            int idx = tid + i*128;
            int row = idx >> 3;
            int gg  = idx & 7;
            uint32_t dst = base + 8192 + row*128 + 16*(gg ^ (row & 7));
            CP_ASYNC16(dst, VTb + (size_t)row*MTOK + k0 + gg*8);
        }
    };

    // ---- prologue: Q staging + first (up to) 2 KV tiles ----
    #pragma unroll
    for (int i = 0; i < 4; ++i) {               // Q: 64 rows x 8 granules
        int idx = tid + i*128;
        int row = idx >> 3;
        int gg  = idx & 7;
        uint32_t dst = smb + row*128 + 16*(gg ^ (row & 7));
        CP_ASYNC16(dst, Qb + (size_t)(q0+row)*DM + gg*8);
    }
    copy_kv(0, 0); CP_COMMIT();
    if (1 < ntiles) copy_kv(1, 1);
    CP_COMMIT();

    float oacc[8][4];
    #pragma unroll
    for (int nt = 0; nt < 8; ++nt)
        #pragma unroll
        for (int e = 0; e < 4; ++e) oacc[nt][e] = 0.f;
    float m0 = -1e30f, m1 = -1e30f, l0 = 0.f, l1 = 0.f;

    const int frow = lr + 8*lh;
    const int qrow = wid*16 + frow;

    for (int tk = 0; tk < ntiles; ++tk) {
        CP_WAIT1();
        __syncthreads();
        const uint32_t sK = smb + AOFF_KV + (tk & 1)*16384;
        const uint32_t sV = sK + 8192;

        // ---- S = Q @ K^T ----
        float sf[8][4];
        #pragma unroll
        for (int nt = 0; nt < 8; ++nt)
            #pragma unroll
            for (int e = 0; e < 4; ++e) sf[nt][e] = 0.f;
        #pragma unroll
        for (int ks = 0; ks < 4; ++ks) {
            const uint32_t swg = 16u * ((2*ks + lg) ^ lr);
            uint32_t qa[4];
            LDSM_X4(qa[0], qa[1], qa[2], qa[3], smb + qrow*128 + swg);
            #pragma unroll
            for (int p = 0; p < 4; ++p) {
                uint32_t bq[4];
                LDSM_X4(bq[0],bq[1],bq[2],bq[3], sK + (p*16 + frow)*128 + swg);
                uint32_t be[2] = {bq[0], bq[2]};
                uint32_t bo[2] = {bq[1], bq[3]};
                mma_f16(sf[2*p],   qa, be);
                mma_f16(sf[2*p+1], qa, bo);
            }
        }

        // ---- causal mask (last tile only) + row max ----
        float rmax0 = -1e30f, rmax1 = -1e30f;
        if (tk == ntiles - 1) {
            const int k0 = tk * AKV;
            #pragma unroll
            for (int nt = 0; nt < 8; ++nt) {
                int jb = k0 + nt*8 + 2*t4;
                #pragma unroll
                for (int e = 0; e < 4; ++e) {
                    int j = jb + (e & 1);
                    float v = sf[nt][e];
                    int qr = (e < 2) ? qi0 : qi1;
                    v = (j > qr) ? -1e30f : v;
                    sf[nt][e] = v;
                    if (e < 2) rmax0 = fmaxf(rmax0, v);
                    else       rmax1 = fmaxf(rmax1, v);
                }
            }
        } else {
            #pragma unroll
            for (int nt = 0; nt < 8; ++nt) {
                rmax0 = fmaxf(rmax0, fmaxf(sf[nt][0], sf[nt][1]));
                rmax1 = fmaxf(rmax1, fmaxf(sf[nt][2], sf[nt][3]));
            }
        }
        rmax0 = fmaxf(rmax0, __shfl_xor_sync(0xffffffff, rmax0, 1));
        rmax0 = fmaxf(rmax0, __shfl_xor_sync(0xffffffff, rmax0, 2));
        rmax1 = fmaxf(rmax1, __shfl_xor_sync(0xffffffff, rmax1, 1));
        rmax1 = fmaxf(rmax1, __shfl_xor_sync(0xffffffff, rmax1, 2));

        float mn0 = fmaxf(m0, rmax0);
        float mn1 = fmaxf(m1, rmax1);
        float c0 = fexp2(m0 - mn0);
        float c1 = fexp2(m1 - mn1);
        m0 = mn0; m1 = mn1;

        #pragma unroll
        for (int nt = 0; nt < 8; ++nt) {
            oacc[nt][0] *= c0; oacc[nt][1] *= c0;
            oacc[nt][2] *= c1; oacc[nt][3] *= c1;
        }

        // ---- exp -> P directly as PV A-fragments ----
        float s0 = 0.f, s1 = 0.f;
        uint32_t pa[4][4];
        #pragma unroll
        for (int s = 0; s < 4; ++s) {
            float e00 = fexp2(sf[2*s  ][0] - mn0), e01 = fexp2(sf[2*s  ][1] - mn0);
            float e02 = fexp2(sf[2*s  ][2] - mn1), e03 = fexp2(sf[2*s  ][3] - mn1);
            float e10 = fexp2(sf[2*s+1][0] - mn0), e11 = fexp2(sf[2*s+1][1] - mn0);
            float e12 = fexp2(sf[2*s+1][2] - mn1), e13 = fexp2(sf[2*s+1][3] - mn1);
            s0 += (e00 + e01) + (e10 + e11);
            s1 += (e02 + e03) + (e12 + e13);
            pa[s][0] = pack_h2(e00, e01);
            pa[s][1] = pack_h2(e02, e03);
            pa[s][2] = pack_h2(e10, e11);
            pa[s][3] = pack_h2(e12, e13);
        }
        s0 += __shfl_xor_sync(0xffffffff, s0, 1);
        s0 += __shfl_xor_sync(0xffffffff, s0, 2);
        s1 += __shfl_xor_sync(0xffffffff, s1, 1);
        s1 += __shfl_xor_sync(0xffffffff, s1, 2);
        l0 = l0*c0 + s0;
        l1 = l1*c1 + s1;

        // ---- O += P @ V ----
        #pragma unroll
        for (int s = 0; s < 4; ++s) {
            const uint32_t swg = 16u * ((2*s + lg) ^ lr);
            #pragma unroll
            for (int p = 0; p < 4; ++p) {
                uint32_t bq[4];
                LDSM_X4(bq[0],bq[1],bq[2],bq[3], sV + (p*16 + frow)*128 + swg);
                uint32_t be[2] = {bq[0], bq[2]};
                uint32_t bo[2] = {bq[1], bq[3]};
                mma_f16(oacc[2*p],   pa[s], be);
                mma_f16(oacc[2*p+1], pa[s], bo);
            }
        }

        __syncthreads();
        if (tk + 2 < ntiles) copy_kv(tk + 2, tk & 1);
        CP_COMMIT();
    }

    // ---- epilogue ----
    const float i0 = 1.f / l0;
    const float i1 = 1.f / l1;
    __half* Ob = O + ((size_t)(b*TT))*DM + h*DKH;
    #pragma unroll
    for (int nt = 0; nt < 8; ++nt) {
        int d = nt*8 + 2*t4;
        *(uint32_t*)(Ob + (size_t)qi0*DM + d) = pack_h2(oacc[nt][0]*i0, oacc[nt][1]*i0);
        *(uint32_t*)(Ob + (size_t)qi1*DM + d) = pack_h2(oacc[nt][2]*i1, oacc[nt][3]*i1);
    }
}

// ===========================================================================
extern "C" void kernel_launch(void* const* d_in, const int* in_sizes, int n_in,
                              void* d_out, int out_size)
{
    const float* q  = (const float*)d_in[0];
    const float* k  = (const float*)d_in[1];
    const float* v  = (const float*)d_in[2];
    const float* wq = (const float*)d_in[4];
    const float* bq = (const float*)d_in[5];
    const float* wk = (const float*)d_in[6];
    const float* bk = (const float*)d_in[7];
    const float* wv = (const float*)d_in[8];
    const float* bv = (const float*)d_in[9];
    const float* wo = (const float*)d_in[10];
    const float* bo = (const float*)d_in[11];
    float* out = (float*)d_out;

    __half *gqi, *gki, *gvi, *gq, *gk, *gvt, *gc, *gwt;
    cudaGetSymbolAddress((void**)&gqi, g_QI);
    cudaGetSymbolAddress((void**)&gki, g_KI);
    cudaGetSymbolAddress((void**)&gvi, g_VI);
    cudaGetSymbolAddress((void**)&gq,  g_Q);
    cudaGetSymbolAddress((void**)&gk,  g_K);
    cudaGetSymbolAddress((void**)&gvt, g_VT);
    cudaGetSymbolAddress((void**)&gc,  g_C);
    cudaGetSymbolAddress((void**)&gwt, g_WT);
    __half* wtq = gwt;
    __half* wtk = gwt + (size_t)DM*DM;
    __half* wtv = gwt + (size_t)2*DM*DM;
    __half* wto = gwt + (size_t)3*DM*DM;

    cudaFuncSetAttribute(attn_tc, cudaFuncAttributeMaxDynamicSharedMemorySize, ATTN_SMEM_TC);
    cudaFuncSetAttribute(gemm_qkv, cudaFuncAttributeMaxDynamicSharedMemorySize, GM_SMEM);
    cudaFuncSetAttribute(gemm_out, cudaFuncAttributeMaxDynamicSharedMemorySize, GM_SMEM);

    dim3 tgrid(DM/32, DM/32, 4);
    transpose_h_x4<<<tgrid, 256>>>(wq, wk, wv, wo, wtq, wtk, wtv, wto);

    dim3 pgrid(MTOK*DM/4/256, 1, 3);
    preround_h<<<pgrid, 256>>>(q, k, v, gqi, gki, gvi);

    dim3 qkvgrid(DM/128, MTOK/128, 3);   // (8, 32, 3) = 768 CTAs, 2/SM
    gemm_qkv<<<qkvgrid, 256, GM_SMEM>>>(gqi, gki, gvi, wtq, wtk, wtv,
                                        bq, bk, bv, gq, gk, gvt);

    dim3 agrid(TT/AQ_ROWS, NH, BB);      // (32, 16, 2) = 1024 CTAs, 4/SM
    attn_tc<<<agrid, 128, ATTN_SMEM_TC>>>(gq, gk, gvt, gc);

    dim3 ogrid(DM/128, MTOK/128);        // (8, 32) = 256 CTAs = 1 full wave
    gemm_out<<<ogrid, 256, GM_SMEM>>>(gc, wto, bo, out);
}